// round 6
// baseline (speedup 1.0000x reference)
#include <cuda_runtime.h>
#include <cuda_bf16.h>

// Problem constants
#define BB 2
#define NN 16384
#define CIN 64
#define SS 4096
#define NSAMP 32

// Output layout (floats): new_xyz | new_features | scores
#define OUT_XYZ_OFF   0
#define OUT_FEAT_OFF  (BB * SS * 3)                       // 24576
#define OUT_SCORE_OFF (OUT_FEAT_OFF + BB * 128 * SS)      // 1073152

// ---------------- scratch (no allocations allowed) ----------------
__device__ float g_featsT[BB * NN * CIN];    // (B,N,C) transposed features, 8 MB
__device__ int   g_ballIdx[BB * SS * NSAMP]; // neighbor indices
__device__ int   g_ballCnt[BB * SS];         // in-ball counts (0 => empty)

typedef unsigned long long u64;

// =================================================================
// Kernel 1: FPS (one 256-thread block per batch)
//  - hot tail points (<=768, padded to 1024) in REGISTERS, scanned
//    every iter via 8 virtual chunks ckey[128..135]
//  - cold points Morton-sorted into <=128 chunks of 128, AABB pruned
//  - per-chunk max via smem atomicMax(u64) (zeroed fresh each rescan)
//  - fused block argmax: every warp reduces all 144 chunk keys
//  - per-point math bit-identical to reference; key
//    (dist_bits<<14)|(16383-idx) => exact first-index tie-break
// =================================================================
#define FPS_T   256
#define FPS_W   8
#define HOTCAP  1024
#define HOT_TGT 768
#define NCELL   2048

// smem layout (bytes):
// cxy f2[16384]=131072 | inv16 u16[16384]=32768 | hot4 f4[1024]=16384
// | hist u32[2048]=8192 | aabb f32[768]=3072 | ckey u64[144]=1152
// | cwin f4[136]=2176   => 194816
#define FPS_SMEM_BYTES (131072 + 32768 + 16384 + 8192 + 3072 + 1152 + 2176)

__device__ __forceinline__ float r2_rn(float x, float y, float z)
{
    return __fadd_rn(__fadd_rn(__fmul_rn(x, x), __fmul_rn(y, y)), __fmul_rn(z, z));
}
__device__ __forceinline__ float dist_rn(float x, float y, float z,
                                         float nx, float ny, float nz)
{
    const float dx = __fadd_rn(x, nx);
    const float dy = __fadd_rn(y, ny);
    const float dz = __fadd_rn(z, nz);
    return __fadd_rn(__fadd_rn(__fmul_rn(dx, dx), __fmul_rn(dy, dy)), __fmul_rn(dz, dz));
}

__device__ __forceinline__ int fps_cell(float x, float y, float z,
                                        float mnx, float mny, float mnz,
                                        float isx, float isy, float isz)
{
    int qx = __float2int_rd((x - mnx) * isx); qx = max(0, min(15, qx));
    int qy = __float2int_rd((y - mny) * isy); qy = max(0, min(15, qy));
    int qz = __float2int_rd((z - mnz) * isz); qz = max(0, min(7,  qz));
    return  (qx & 1)        | ((qy & 1) << 1)        | ((qz & 1) << 2)
         | (((qx >> 1) & 1) << 3) | (((qy >> 1) & 1) << 4) | (((qz >> 1) & 1) << 5)
         | (((qx >> 2) & 1) << 6) | (((qy >> 2) & 1) << 7) | (((qz >> 2) & 1) << 8)
         | (((qx >> 3) & 1) << 9) | (((qy >> 3) & 1) << 10);
}

__global__ __launch_bounds__(FPS_T) void fps_kernel(
    const float* __restrict__ xyz, float* __restrict__ out_newxyz)
{
    extern __shared__ unsigned char raw[];
    float2*         cxy   = (float2*)raw;                      // [16384]
    unsigned short* inv16 = (unsigned short*)(cxy + NN);       // [16384]
    float4*         hot4  = (float4*)(inv16 + NN);             // [1024] (staging + winner lookup)
    unsigned*       hist  = (unsigned*)(hot4 + HOTCAP);        // [2048]
    float*          aabb  = (float*)(hist + NCELL);            // [128*6]
    u64*            ckey  = (u64*)(aabb + 128 * 6);            // [144] 0-127 cold, 128-135 hot, 136-143 pad
    float4*         cwin  = (float4*)(ckey + 144);             // [136]

    __shared__ float    s_wred[FPS_W][6];
    __shared__ unsigned s_wsum[FPS_W], s_wbase[FPS_W];
    __shared__ unsigned s_rh[128];
    __shared__ float    s_r2b, s_thresh;
    __shared__ float    s_grid[6];
    __shared__ unsigned s_hotCnt;

    const int b    = blockIdx.x;
    const int tid  = threadIdx.x;
    const int lane = tid & 31, w = tid >> 5;
    const float* xb = xyz + (size_t)b * NN * 3;

    // ---- pass 0: global AABB ----
    {
        float mnx = 1e30f, mny = 1e30f, mnz = 1e30f;
        float mxx = -1e30f, mxy = -1e30f, mxz = -1e30f;
        for (int i = tid; i < NN; i += FPS_T) {
            const float x = xb[3 * i], y = xb[3 * i + 1], z = xb[3 * i + 2];
            mnx = fminf(mnx, x); mny = fminf(mny, y); mnz = fminf(mnz, z);
            mxx = fmaxf(mxx, x); mxy = fmaxf(mxy, y); mxz = fmaxf(mxz, z);
        }
#pragma unroll
        for (int off = 16; off; off >>= 1) {
            mnx = fminf(mnx, __shfl_xor_sync(0xffffffffu, mnx, off));
            mny = fminf(mny, __shfl_xor_sync(0xffffffffu, mny, off));
            mnz = fminf(mnz, __shfl_xor_sync(0xffffffffu, mnz, off));
            mxx = fmaxf(mxx, __shfl_xor_sync(0xffffffffu, mxx, off));
            mxy = fmaxf(mxy, __shfl_xor_sync(0xffffffffu, mxy, off));
            mxz = fmaxf(mxz, __shfl_xor_sync(0xffffffffu, mxz, off));
        }
        if (lane == 0) {
            s_wred[w][0] = mnx; s_wred[w][1] = mny; s_wred[w][2] = mnz;
            s_wred[w][3] = mxx; s_wred[w][4] = mxy; s_wred[w][5] = mxz;
        }
    }
    for (int i = tid; i < NCELL; i += FPS_T) hist[i] = 0;
    if (tid < 144) ckey[tid] = 0ull;
    if (tid < 128) s_rh[tid] = 0;
    if (tid == 0) s_hotCnt = 0;
    __syncthreads();
    if (tid == 0) {
        float a0 = 1e30f, a1 = 1e30f, a2 = 1e30f, a3 = -1e30f, a4 = -1e30f, a5 = -1e30f;
        for (int i = 0; i < FPS_W; i++) {
            a0 = fminf(a0, s_wred[i][0]); a1 = fminf(a1, s_wred[i][1]); a2 = fminf(a2, s_wred[i][2]);
            a3 = fmaxf(a3, s_wred[i][3]); a4 = fmaxf(a4, s_wred[i][4]); a5 = fmaxf(a5, s_wred[i][5]);
        }
        s_grid[0] = a0; s_grid[1] = a1; s_grid[2] = a2;
        s_grid[3] = 16.f / fmaxf(a3 - a0, 1e-9f);
        s_grid[4] = 16.f / fmaxf(a4 - a1, 1e-9f);
        s_grid[5] = 8.f  / fmaxf(a5 - a2, 1e-9f);
        const float bx = fmaxf(fabsf(a0), fabsf(a3));
        const float by = fmaxf(fabsf(a1), fabsf(a4));
        const float bz = fmaxf(fabsf(a2), fabsf(a5));
        s_r2b = bx * bx + by * by + bz * bz + 1e-6f;
    }
    __syncthreads();

    const float gmnx = s_grid[0], gmny = s_grid[1], gmnz = s_grid[2];
    const float isx = s_grid[3], isy = s_grid[4], isz = s_grid[5];
    const float r2b = s_r2b;

    // ---- pass 1: r2 histogram -> hot threshold (deterministic) ----
    for (int i = tid; i < NN; i += FPS_T) {
        const float r2 = r2_rn(xb[3 * i], xb[3 * i + 1], xb[3 * i + 2]);
        const int bin = min(127, (int)(r2 * (128.f / r2b)));
        atomicAdd(&s_rh[bin], 1u);
    }
    __syncthreads();
    if (tid == 0) {
        unsigned acc = 0;
        float thr = 3e38f;
        for (int q = 127; q >= 0; q--) {
            if (acc + s_rh[q] > HOT_TGT) break;
            acc += s_rh[q];
            thr = (float)q * (r2b / 128.f);
        }
        s_thresh = thr;
    }
    __syncthreads();
    const float thresh = s_thresh;

    // ---- pass 2: Morton histogram over cold ----
    for (int i = tid; i < NN; i += FPS_T) {
        const float x = xb[3 * i], y = xb[3 * i + 1], z = xb[3 * i + 2];
        if (r2_rn(x, y, z) < thresh) {
            const int c = fps_cell(x, y, z, gmnx, gmny, gmnz, isx, isy, isz);
            atomicAdd(&hist[c], 1u);
        }
    }
    __syncthreads();

    // ---- exclusive scan of hist[2048] (8 per thread) ----
    {
        const int t8 = tid * 8;
        unsigned v[8], s = 0;
#pragma unroll
        for (int q = 0; q < 8; q++) { v[q] = hist[t8 + q]; s += v[q]; }
        unsigned inc = s;
#pragma unroll
        for (int off = 1; off < 32; off <<= 1) {
            const unsigned n = __shfl_up_sync(0xffffffffu, inc, off);
            if (lane >= off) inc += n;
        }
        if (lane == 31) s_wsum[w] = inc;
        __syncthreads();
        if (tid < FPS_W) {
            const unsigned ws = s_wsum[tid];
            unsigned winc = ws;
#pragma unroll
            for (int off = 1; off < FPS_W; off <<= 1) {
                const unsigned n = __shfl_up_sync(0x000000ffu, winc, off);
                if ((int)tid >= off) winc += n;
            }
            s_wbase[tid] = winc - ws;
        }
        __syncthreads();
        unsigned run = s_wbase[w] + (inc - s);
#pragma unroll
        for (int q = 0; q < 8; q++) { hist[t8 + q] = run; run += v[q]; }
    }
    __syncthreads();

    // ---- pass 3: scatter hot / cold (inv = 16383 - i) ----
    for (int i = tid; i < NN; i += FPS_T) {
        const float x = xb[3 * i], y = xb[3 * i + 1], z = xb[3 * i + 2];
        if (r2_rn(x, y, z) >= thresh) {
            const unsigned pos = atomicAdd(&s_hotCnt, 1u);
            hot4[pos] = make_float4(x, y, z, __uint_as_float(16383u - (unsigned)i));
        } else {
            const int c = fps_cell(x, y, z, gmnx, gmny, gmnz, isx, isy, isz);
            const unsigned slot = atomicAdd(&hist[c], 1u);
            cxy[slot]   = make_float2(x, y);
            inv16[slot] = (unsigned short)(16383u - (unsigned)i);
        }
    }
    __syncthreads();

    const int hc    = (int)s_hotCnt;
    const int coldN = NN - hc;
    const int nch   = (coldN + 127) >> 7;

    // pads (duplicate points: harmless, identical keys/coords)
    for (int s2 = hc + tid; s2 < HOTCAP; s2 += FPS_T)
        hot4[s2] = (hc > 0) ? hot4[0]
                            : make_float4(xb[0], xb[1], xb[2], __uint_as_float(16383u));
    for (int s2 = coldN + tid; s2 < nch * 128; s2 += FPS_T) {
        cxy[s2]   = cxy[coldN - 1];
        inv16[s2] = inv16[coldN - 1];
    }
    __syncthreads();

    // ---- hot -> registers (4 pts/thread) ----
    float hx[4], hy[4], hz[4], hd[4];
    unsigned hinv[4];
#pragma unroll
    for (int k = 0; k < 4; k++) {
        const float4 h = hot4[tid + FPS_T * k];
        hx[k] = h.x; hy[k] = h.y; hz[k] = h.z;
        hinv[k] = __float_as_uint(h.w);
        hd[k] = 1e10f;
    }

    // ---- owner fill: cold z + dist regs, chunk AABBs ----
    float cz[64], cd[64];
#pragma unroll
    for (int k = 0; k < 64; k++) { cz[k] = 0.f; cd[k] = 1e10f; }

#pragma unroll
    for (int m = 0; m < 16; m++) {
        const int c = w + FPS_W * m;
        if (c < nch) {
            float lmn0 = 1e30f, lmn1 = 1e30f, lmn2 = 1e30f;
            float lmx0 = -1e30f, lmx1 = -1e30f, lmx2 = -1e30f;
#pragma unroll
            for (int k = 0; k < 4; k++) {
                const int slot = c * 128 + lane + 32 * k;
                const float2 xy = cxy[slot];
                const int oi = 16383 - (int)inv16[slot];
                const float z = __ldg(xb + 3 * oi + 2);
                cz[m * 4 + k] = z;
                lmn0 = fminf(lmn0, xy.x); lmn1 = fminf(lmn1, xy.y); lmn2 = fminf(lmn2, z);
                lmx0 = fmaxf(lmx0, xy.x); lmx1 = fmaxf(lmx1, xy.y); lmx2 = fmaxf(lmx2, z);
            }
#pragma unroll
            for (int off = 16; off; off >>= 1) {
                lmn0 = fminf(lmn0, __shfl_xor_sync(0xffffffffu, lmn0, off));
                lmn1 = fminf(lmn1, __shfl_xor_sync(0xffffffffu, lmn1, off));
                lmn2 = fminf(lmn2, __shfl_xor_sync(0xffffffffu, lmn2, off));
                lmx0 = fmaxf(lmx0, __shfl_xor_sync(0xffffffffu, lmx0, off));
                lmx1 = fmaxf(lmx1, __shfl_xor_sync(0xffffffffu, lmx1, off));
                lmx2 = fmaxf(lmx2, __shfl_xor_sync(0xffffffffu, lmx2, off));
            }
            if (lane == 0) {
                aabb[c * 6 + 0] = lmn0; aabb[c * 6 + 1] = lmn1; aabb[c * 6 + 2] = lmn2;
                aabb[c * 6 + 3] = lmx0; aabb[c * 6 + 4] = lmx1; aabb[c * 6 + 5] = lmx2;
                ckey[c] = ((u64)__float_as_uint(1e10f)) << 14;  // force first-iter scan
            }
        }
    }
    __syncthreads();

    float* outx = out_newxyz + (size_t)b * SS * 3;
    float ccx = __ldg(xb + 0), ccy = __ldg(xb + 1), ccz = __ldg(xb + 2);

    // ---- main loop: [output; scan(B); bar; argmax(A); bar] ----
    for (int j = 0; j < SS; j++) {
        if (tid == 0) {
            outx[3 * j + 0] = ccx;
            outx[3 * j + 1] = ccy;
            outx[3 * j + 2] = ccz;
        }
        const float nx = -ccx, ny = -ccy, nz = -ccz;

        // --- phase B: prune ---
        bool act = false;
        if (lane < 16) {
            const int c = w + FPS_W * lane;
            const float* bb2 = aabb + c * 6;
            const float dxm = fmaxf(fmaxf(__fadd_rn(bb2[0], nx), -__fadd_rn(bb2[3], nx)), 0.f);
            const float dym = fmaxf(fmaxf(__fadd_rn(bb2[1], ny), -__fadd_rn(bb2[4], ny)), 0.f);
            const float dzm = fmaxf(fmaxf(__fadd_rn(bb2[2], nz), -__fadd_rn(bb2[5], nz)), 0.f);
            const float dmin2 = __fadd_rn(__fadd_rn(__fmul_rn(dxm, dxm), __fmul_rn(dym, dym)),
                                          __fmul_rn(dzm, dzm));
            const float cm = __uint_as_float((unsigned)(ckey[c] >> 14));
            act = dmin2 < cm;   // ckey==0 for c>=nch => never active
        }
        const unsigned mask = __ballot_sync(0xffffffffu, act);

        // --- hot scan (always) -> virtual chunk 128+w ---
        {
            u64 bk = 0ull; float bx = 0.f, by = 0.f, bz = 0.f;
#pragma unroll
            for (int k = 0; k < 4; k++) {
                const float d = dist_rn(hx[k], hy[k], hz[k], nx, ny, nz);
                const float nd = fminf(hd[k], d);
                hd[k] = nd;
                const u64 key = ((u64)__float_as_uint(nd) << 14) | (u64)hinv[k];
                if (key > bk) { bk = key; bx = hx[k]; by = hy[k]; bz = hz[k]; }
            }
            const int c = 128 + w;
            if (lane == 0) ckey[c] = 0ull;
            __syncwarp();
            atomicMax(&ckey[c], bk);
            __syncwarp();
            const u64 ck = ckey[c];
            const unsigned own = __ballot_sync(0xffffffffu, bk == ck);
            if (lane == (int)(__ffs(own) - 1)) cwin[c] = make_float4(bx, by, bz, 0.f);
        }

        // --- cold scans (static unroll, warp-uniform guards) ---
#pragma unroll
        for (int m = 0; m < 16; m++) {
            if ((mask >> m) & 1u) {
                const int c = w + FPS_W * m;
                u64 bk = 0ull; float bx = 0.f, by = 0.f, bz = 0.f;
#pragma unroll
                for (int k = 0; k < 4; k++) {
                    const int slot = c * 128 + lane + 32 * k;
                    const float2 xy = cxy[slot];
                    const float zz = cz[m * 4 + k];
                    const float d = dist_rn(xy.x, xy.y, zz, nx, ny, nz);
                    const float nd = fminf(cd[m * 4 + k], d);
                    cd[m * 4 + k] = nd;
                    const u64 key = ((u64)__float_as_uint(nd) << 14) | (u64)inv16[slot];
                    if (key > bk) { bk = key; bx = xy.x; by = xy.y; bz = zz; }
                }
                if (lane == 0) ckey[c] = 0ull;
                __syncwarp();
                atomicMax(&ckey[c], bk);
                __syncwarp();
                const u64 ck = ckey[c];
                const unsigned own = __ballot_sync(0xffffffffu, bk == ck);
                if (lane == (int)(__ffs(own) - 1)) cwin[c] = make_float4(bx, by, bz, 0.f);
            }
        }
        __syncthreads();

        // --- phase A: fused block argmax (every warp, redundant) ---
        {
            const u64 v0 = ckey[lane];
            const u64 v1 = ckey[lane + 32];
            const u64 v2 = ckey[lane + 64];
            const u64 v3 = ckey[lane + 96];
            const u64 v4 = (lane < FPS_W) ? ckey[128 + lane] : 0ull;
            u64 a01 = v0 > v1 ? v0 : v1;
            u64 a23 = v2 > v3 ? v2 : v3;
            u64 K = a01 > a23 ? a01 : a23;
            if (v4 > K) K = v4;
#pragma unroll
            for (int off = 16; off; off >>= 1) {
                const u64 o = __shfl_xor_sync(0xffffffffu, K, off);
                if (o > K) K = o;
            }
            int myc = -1;
            if (v0 == K) myc = lane;
            else if (v1 == K) myc = lane + 32;
            else if (v2 == K) myc = lane + 64;
            else if (v3 == K) myc = lane + 96;
            else if (v4 == K && lane < FPS_W) myc = 128 + lane;
            const unsigned has = __ballot_sync(0xffffffffu, myc >= 0);
            const int src = __shfl_sync(0xffffffffu, myc, (int)(__ffs(has) - 1));
            const float4 wv = cwin[src];
            ccx = wv.x; ccy = wv.y; ccz = wv.z;
        }
        __syncthreads();   // WAR: cwin/ckey rewritten next iter
    }
}

// =================================================================
// Kernel 2: transpose features (B,C,N) -> (B,N,C)
// =================================================================
__global__ void transpose_kernel(const float* __restrict__ f)
{
    __shared__ float tile[32][33];
    const int b  = blockIdx.z;
    const int n0 = blockIdx.x * 32;
    const int c0 = blockIdx.y * 32;
    const int tx = threadIdx.x, ty = threadIdx.y;
    tile[ty][tx] = f[((size_t)b * CIN + (c0 + ty)) * NN + n0 + tx];
    __syncthreads();
    g_featsT[((size_t)b * NN + (n0 + ty)) * CIN + c0 + tx] = tile[tx][ty];
}

// =================================================================
// Kernel 3: ball query (one warp per group), first-32-ascending
// =================================================================
__global__ void ballq_kernel(const float* __restrict__ xyz,
                             const float* __restrict__ newxyz)
{
    const int g    = blockIdx.x * 8 + (threadIdx.x >> 5);
    const int lane = threadIdx.x & 31;
    const int b    = g >> 12;
    const float* xb = xyz + (size_t)b * NN * 3;

    const float cx = newxyz[g * 3 + 0];
    const float cy = newxyz[g * 3 + 1];
    const float cz = newxyz[g * 3 + 2];

    int* out = g_ballIdx + g * NSAMP;
    int cnt = 0;

    for (int base = 0; base < NN && cnt < NSAMP; base += 32) {
        const int i = base + lane;
        const float dx = xb[3 * i + 0] - cx;
        const float dy = xb[3 * i + 1] - cy;
        const float dz = xb[3 * i + 2] - cz;
        const float d2 = __fadd_rn(__fadd_rn(__fmul_rn(dx, dx), __fmul_rn(dy, dy)),
                                   __fmul_rn(dz, dz));
        const bool inb = d2 < 0.25f;
        const unsigned m = __ballot_sync(0xffffffffu, inb);
        const int pos = cnt + __popc(m & ((1u << lane) - 1u));
        if (inb && pos < NSAMP) out[pos] = i;
        cnt += __popc(m);
    }
    __syncwarp();
    if (cnt == 0) {
        out[lane] = 0;
    } else if (cnt < NSAMP) {
        const int first = out[0];
        if (lane >= cnt) out[lane] = first;
    }
    if (lane == 0) g_ballCnt[g] = cnt;
}

// =================================================================
// Kernel 4: fused gather + 3-layer MLP + maxpool + agg + score
// =================================================================
#define W1_STR 65
#define W2_STR 65
#define W3_STR 129
#define SM_INT_F   (67 * 36)
#define SM_W1_F    4356
#define SM_W2_F    (64 * W2_STR)
#define SM_W3_F    (64 * W3_STR)
#define SM_H_F     (64 * 36)
#define MLP_SMEM_FLOATS (SM_INT_F + SM_W1_F + SM_W2_F + SM_W3_F + 2 * SM_H_F + 256 + 256 + 128 + 128 + 32)

__global__ __launch_bounds__(256, 2) void group_mlp_kernel(
    const float* __restrict__ xyz,
    const float* __restrict__ newxyz,
    const float* __restrict__ w1, const float* __restrict__ b1,
    const float* __restrict__ w2, const float* __restrict__ b2,
    const float* __restrict__ w3, const float* __restrict__ b3,
    const float* __restrict__ wa, const float* __restrict__ ba,
    const float* __restrict__ wc, const float* __restrict__ bc,
    float* __restrict__ d_out)
{
    extern __shared__ float sm[];
    float* inT     = sm;
    float* w1s     = inT + SM_INT_F;
    float* w2s     = w1s + SM_W1_F;
    float* w3s     = w2s + SM_W2_F;
    float* h1T     = w3s + SM_W3_F;
    float* h2T     = h1T + SM_H_F;
    float* bss     = h2T + SM_H_F;
    float* poolbuf = bss + 256;
    float* pooled  = poolbuf + 256;
    float* aggv    = pooled + 128;
    int*   idxs    = (int*)(aggv + 128);

    const int g = blockIdx.x;
    const int b = g >> 12;
    const int s = g & 4095;
    const int tid = threadIdx.x;

    if (tid < 32)  idxs[tid] = g_ballIdx[g * NSAMP + tid];
    if (tid < 64)       bss[tid] = b1[tid];
    else if (tid < 128) bss[tid] = b2[tid - 64];
    if (tid < 128) bss[128 + tid] = b3[tid];

    for (int e = tid; e < 64 * 67; e += 256) {
        const int oc = e / 67, i = e % 67;
        w1s[i * W1_STR + oc] = w1[e];
    }
    for (int e = tid; e < 64 * 64; e += 256) {
        const int oc = e >> 6, i = e & 63;
        w2s[i * W2_STR + oc] = w2[e];
    }
    for (int e = tid; e < 128 * 64; e += 256) {
        const int oc = e >> 6, i = e & 63;
        w3s[i * W3_STR + oc] = w3[e];
    }
    __syncthreads();

    const float* xb = xyz + (size_t)b * NN * 3;
    const float cx = newxyz[g * 3 + 0];
    const float cy = newxyz[g * 3 + 1];
    const float cz = newxyz[g * 3 + 2];
    for (int e = tid; e < 32 * 67; e += 256) {
        const int nb = e & 31;
        const int i  = e >> 5;
        const int pi = idxs[nb];
        float v;
        if (i == 0)      v = xb[pi * 3 + 0] - cx;
        else if (i == 1) v = xb[pi * 3 + 1] - cy;
        else if (i == 2) v = xb[pi * 3 + 2] - cz;
        else             v = g_featsT[((size_t)b * NN + pi) * CIN + (i - 3)];
        inT[i * 36 + nb] = v;
    }
    __syncthreads();

    {
        const int oc = tid & 63, ng = tid >> 6;
        float acc[8];
        const float bv = bss[oc];
#pragma unroll
        for (int n = 0; n < 8; n++) acc[n] = bv;
        for (int i = 0; i < 67; i++) {
            const float w = w1s[i * W1_STR + oc];
            const float4* xp = (const float4*)(inT + i * 36 + ng * 8);
            const float4 x0 = xp[0], x1 = xp[1];
            acc[0] += w * x0.x; acc[1] += w * x0.y; acc[2] += w * x0.z; acc[3] += w * x0.w;
            acc[4] += w * x1.x; acc[5] += w * x1.y; acc[6] += w * x1.z; acc[7] += w * x1.w;
        }
        float* hp = h1T + oc * 36 + ng * 8;
#pragma unroll
        for (int n = 0; n < 8; n++) hp[n] = fmaxf(acc[n], 0.f);
    }
    __syncthreads();

    {
        const int oc = tid & 63, ng = tid >> 6;
        float acc[8];
        const float bv = bss[64 + oc];
#pragma unroll
        for (int n = 0; n < 8; n++) acc[n] = bv;
        for (int i = 0; i < 64; i++) {
            const float w = w2s[i * W2_STR + oc];
            const float4* xp = (const float4*)(h1T + i * 36 + ng * 8);
            const float4 x0 = xp[0], x1 = xp[1];
            acc[0] += w * x0.x; acc[1] += w * x0.y; acc[2] += w * x0.z; acc[3] += w * x0.w;
            acc[4] += w * x1.x; acc[5] += w * x1.y; acc[6] += w * x1.z; acc[7] += w * x1.w;
        }
        float* hp = h2T + oc * 36 + ng * 8;
#pragma unroll
        for (int n = 0; n < 8; n++) hp[n] = fmaxf(acc[n], 0.f);
    }
    __syncthreads();

    {
        const int oc = tid & 127, ng = tid >> 7;
        float acc[16];
        const float bv = bss[128 + oc];
#pragma unroll
        for (int n = 0; n < 16; n++) acc[n] = bv;
        for (int i = 0; i < 64; i++) {
            const float w = w3s[i * W3_STR + oc];
            const float4* xp = (const float4*)(h2T + i * 36 + ng * 16);
            const float4 x0 = xp[0], x1 = xp[1], x2 = xp[2], x3 = xp[3];
            acc[0]  += w * x0.x; acc[1]  += w * x0.y; acc[2]  += w * x0.z; acc[3]  += w * x0.w;
            acc[4]  += w * x1.x; acc[5]  += w * x1.y; acc[6]  += w * x1.z; acc[7]  += w * x1.w;
            acc[8]  += w * x2.x; acc[9]  += w * x2.y; acc[10] += w * x2.z; acc[11] += w * x2.w;
            acc[12] += w * x3.x; acc[13] += w * x3.y; acc[14] += w * x3.z; acc[15] += w * x3.w;
        }
        float m = acc[0];
#pragma unroll
        for (int n = 1; n < 16; n++) m = fmaxf(m, acc[n]);
        m = fmaxf(m, 0.f);
        poolbuf[oc * 2 + ng] = m;
    }
    __syncthreads();

    const int cnt = g_ballCnt[g];
    if (tid < 128) {
        const float m = fmaxf(poolbuf[tid * 2], poolbuf[tid * 2 + 1]);
        pooled[tid] = (cnt > 0) ? m : 0.f;
    }
    __syncthreads();

    if (tid < 128) {
        const int o = tid;
        float acc = ba[o];
        const float4* w4 = (const float4*)(wa + o * 128);
#pragma unroll 8
        for (int i = 0; i < 32; i++) {
            const float4 wv = __ldg(w4 + i);
            acc += pooled[4 * i + 0] * wv.x;
            acc += pooled[4 * i + 1] * wv.y;
            acc += pooled[4 * i + 2] * wv.z;
            acc += pooled[4 * i + 3] * wv.w;
        }
        const float a = fmaxf(acc, 0.f);
        aggv[o] = a;
        d_out[OUT_FEAT_OFF + ((size_t)(b * 128 + o)) * SS + s] = a;
    }
    __syncthreads();

    if (tid < 32) {
        float p = 0.f;
#pragma unroll
        for (int k = 0; k < 4; k++) {
            const int i = k * 32 + tid;
            p += aggv[i] * wc[i];
        }
#pragma unroll
        for (int off = 16; off; off >>= 1)
            p += __shfl_down_sync(0xffffffffu, p, off);
        if (tid == 0)
            d_out[OUT_SCORE_OFF + b * SS + s] = p + bc[0];
    }
}

// =================================================================
// launch
// =================================================================
extern "C" void kernel_launch(void* const* d_in, const int* in_sizes, int n_in,
                              void* d_out, int out_size)
{
    const float* xyz      = (const float*)d_in[0];
    const float* features = (const float*)d_in[1];
    const float* w1 = (const float*)d_in[2];
    const float* b1 = (const float*)d_in[3];
    const float* w2 = (const float*)d_in[4];
    const float* b2 = (const float*)d_in[5];
    const float* w3 = (const float*)d_in[6];
    const float* b3 = (const float*)d_in[7];
    const float* wa = (const float*)d_in[8];
    const float* ba = (const float*)d_in[9];
    const float* wc = (const float*)d_in[10];
    const float* bc = (const float*)d_in[11];
    float* out = (float*)d_out;

    static bool attr_set = false;
    if (!attr_set) {
        cudaFuncSetAttribute(fps_kernel, cudaFuncAttributeMaxDynamicSharedMemorySize,
                             FPS_SMEM_BYTES);
        cudaFuncSetAttribute(group_mlp_kernel, cudaFuncAttributeMaxDynamicSharedMemorySize,
                             MLP_SMEM_FLOATS * (int)sizeof(float));
        attr_set = true;
    }

    // 1) transpose features to (B,N,C)
    transpose_kernel<<<dim3(NN / 32, CIN / 32, BB), dim3(32, 32)>>>(features);

    // 2) FPS -> writes new_xyz into d_out[0:24576)
    fps_kernel<<<BB, FPS_T, FPS_SMEM_BYTES>>>(xyz, out + OUT_XYZ_OFF);

    // 3) ball query
    ballq_kernel<<<(BB * SS) / 8, 256>>>(xyz, out + OUT_XYZ_OFF);

    // 4) fused gather + MLP + pool + agg + score
    group_mlp_kernel<<<BB * SS, 256, MLP_SMEM_FLOATS * sizeof(float)>>>(
        xyz, out + OUT_XYZ_OFF,
        w1, b1, w2, b2, w3, b3, wa, ba, wc, bc, out);
}

// round 7
// speedup vs baseline: 1.6989x; 1.6989x over previous
#include <cuda_runtime.h>
#include <cuda_bf16.h>

// Problem constants
#define BB 2
#define NN 16384
#define CIN 64
#define SS 4096
#define NSAMP 32

// Output layout (floats): new_xyz | new_features | scores
#define OUT_XYZ_OFF   0
#define OUT_FEAT_OFF  (BB * SS * 3)                       // 24576
#define OUT_SCORE_OFF (OUT_FEAT_OFF + BB * 128 * SS)      // 1073152

// ---------------- scratch (no allocations allowed) ----------------
__device__ float g_featsT[BB * NN * CIN];    // (B,N,C) transposed features, 8 MB
__device__ int   g_ballIdx[BB * SS * NSAMP]; // neighbor indices
__device__ int   g_ballCnt[BB * SS];         // in-ball counts (0 => empty)

typedef unsigned long long u64;

// =================================================================
// Kernel 1: FPS (one 256-thread block per batch)
//  - hot tail points (<=768, padded to 1024) in registers; 8 virtual
//    chunks ckey[128..135], scanned every iter
//  - cold points Morton-sorted into <=128 chunks of 128, AABB pruned
//  - DIRTY-SKIP: per-chunk u64 reduce runs only if some dist changed
//    (ballot of per-lane flags); otherwise cached ckey/cwin are exact
//  - flat block argmax: every warp redundantly reduces ckey[0..159]
//  - per-point math bit-identical to reference; key
//    (dist_bits<<14)|(16383-idx) => exact first-index tie-break
// =================================================================
#define FPS_T   256
#define FPS_W   8
#define HOTCAP  1024
#define HOT_TGT 768
#define NCELL   2048

// smem (bytes): cxy f2[16384]=131072 | inv16 u16[16384]=32768
// | hot4 f4[1024]=16384 | hist u32[2048]=8192 | aabb f32[128*8]=4096
// | ckey u64[160]=1280 | cwin f4[136]=2176  => 195968
#define FPS_SMEM_BYTES (131072 + 32768 + 16384 + 8192 + 4096 + 1280 + 2176)

__device__ __forceinline__ float r2_rn(float x, float y, float z)
{
    return __fadd_rn(__fadd_rn(__fmul_rn(x, x), __fmul_rn(y, y)), __fmul_rn(z, z));
}
__device__ __forceinline__ float dist_rn(float x, float y, float z,
                                         float nx, float ny, float nz)
{
    const float dx = __fadd_rn(x, nx);
    const float dy = __fadd_rn(y, ny);
    const float dz = __fadd_rn(z, nz);
    return __fadd_rn(__fadd_rn(__fmul_rn(dx, dx), __fmul_rn(dy, dy)), __fmul_rn(dz, dz));
}

__device__ __forceinline__ int fps_cell(float x, float y, float z,
                                        float mnx, float mny, float mnz,
                                        float isx, float isy, float isz)
{
    int qx = __float2int_rd((x - mnx) * isx); qx = max(0, min(15, qx));
    int qy = __float2int_rd((y - mny) * isy); qy = max(0, min(15, qy));
    int qz = __float2int_rd((z - mnz) * isz); qz = max(0, min(7,  qz));
    return  (qx & 1)        | ((qy & 1) << 1)        | ((qz & 1) << 2)
         | (((qx >> 1) & 1) << 3) | (((qy >> 1) & 1) << 4) | (((qz >> 1) & 1) << 5)
         | (((qx >> 2) & 1) << 6) | (((qy >> 2) & 1) << 7) | (((qz >> 2) & 1) << 8)
         | (((qx >> 3) & 1) << 9) | (((qy >> 3) & 1) << 10);
}

__global__ __launch_bounds__(FPS_T) void fps_kernel(
    const float* __restrict__ xyz, float* __restrict__ out_newxyz)
{
    extern __shared__ unsigned char raw[];
    float2*         cxy   = (float2*)raw;                      // [16384]
    unsigned short* inv16 = (unsigned short*)(cxy + NN);       // [16384]
    float4*         hot4  = (float4*)(inv16 + NN);             // [1024]
    unsigned*       hist  = (unsigned*)(hot4 + HOTCAP);        // [2048]
    float*          aabb  = (float*)(hist + NCELL);            // [128*8] (mn.xyz,pad, mx.xyz,pad)
    u64*            ckey  = (u64*)(aabb + 128 * 8);            // [160]: 0-127 cold, 128-135 hot, rest pad=0
    float4*         cwin  = (float4*)(ckey + 160);             // [136]

    __shared__ float    s_wred[FPS_W][6];
    __shared__ unsigned s_wsum[FPS_W], s_wbase[FPS_W];
    __shared__ unsigned s_rh[128];
    __shared__ float    s_r2b, s_thresh;
    __shared__ float    s_grid[6];
    __shared__ unsigned s_hotCnt;

    const int b    = blockIdx.x;
    const int tid  = threadIdx.x;
    const int lane = tid & 31, w = tid >> 5;
    const float* xb = xyz + (size_t)b * NN * 3;

    // ---- pass 0: global AABB ----
    {
        float mnx = 1e30f, mny = 1e30f, mnz = 1e30f;
        float mxx = -1e30f, mxy = -1e30f, mxz = -1e30f;
        for (int i = tid; i < NN; i += FPS_T) {
            const float x = xb[3 * i], y = xb[3 * i + 1], z = xb[3 * i + 2];
            mnx = fminf(mnx, x); mny = fminf(mny, y); mnz = fminf(mnz, z);
            mxx = fmaxf(mxx, x); mxy = fmaxf(mxy, y); mxz = fmaxf(mxz, z);
        }
#pragma unroll
        for (int off = 16; off; off >>= 1) {
            mnx = fminf(mnx, __shfl_xor_sync(0xffffffffu, mnx, off));
            mny = fminf(mny, __shfl_xor_sync(0xffffffffu, mny, off));
            mnz = fminf(mnz, __shfl_xor_sync(0xffffffffu, mnz, off));
            mxx = fmaxf(mxx, __shfl_xor_sync(0xffffffffu, mxx, off));
            mxy = fmaxf(mxy, __shfl_xor_sync(0xffffffffu, mxy, off));
            mxz = fmaxf(mxz, __shfl_xor_sync(0xffffffffu, mxz, off));
        }
        if (lane == 0) {
            s_wred[w][0] = mnx; s_wred[w][1] = mny; s_wred[w][2] = mnz;
            s_wred[w][3] = mxx; s_wred[w][4] = mxy; s_wred[w][5] = mxz;
        }
    }
    for (int i = tid; i < NCELL; i += FPS_T) hist[i] = 0;
    if (tid < 160) ckey[tid] = 0ull;
    if (tid < 128) s_rh[tid] = 0;
    if (tid == 0) s_hotCnt = 0;
    __syncthreads();
    if (tid == 0) {
        float a0 = 1e30f, a1 = 1e30f, a2 = 1e30f, a3 = -1e30f, a4 = -1e30f, a5 = -1e30f;
        for (int i = 0; i < FPS_W; i++) {
            a0 = fminf(a0, s_wred[i][0]); a1 = fminf(a1, s_wred[i][1]); a2 = fminf(a2, s_wred[i][2]);
            a3 = fmaxf(a3, s_wred[i][3]); a4 = fmaxf(a4, s_wred[i][4]); a5 = fmaxf(a5, s_wred[i][5]);
        }
        s_grid[0] = a0; s_grid[1] = a1; s_grid[2] = a2;
        s_grid[3] = 16.f / fmaxf(a3 - a0, 1e-9f);
        s_grid[4] = 16.f / fmaxf(a4 - a1, 1e-9f);
        s_grid[5] = 8.f  / fmaxf(a5 - a2, 1e-9f);
        const float bx = fmaxf(fabsf(a0), fabsf(a3));
        const float by = fmaxf(fabsf(a1), fabsf(a4));
        const float bz = fmaxf(fabsf(a2), fabsf(a5));
        s_r2b = bx * bx + by * by + bz * bz + 1e-6f;
    }
    __syncthreads();

    const float gmnx = s_grid[0], gmny = s_grid[1], gmnz = s_grid[2];
    const float isx = s_grid[3], isy = s_grid[4], isz = s_grid[5];
    const float r2b = s_r2b;

    // ---- pass 1: r2 histogram -> deterministic hot threshold ----
    for (int i = tid; i < NN; i += FPS_T) {
        const float r2 = r2_rn(xb[3 * i], xb[3 * i + 1], xb[3 * i + 2]);
        const int bin = min(127, (int)(r2 * (128.f / r2b)));
        atomicAdd(&s_rh[bin], 1u);
    }
    __syncthreads();
    if (tid == 0) {
        unsigned acc = 0;
        float thr = 3e38f;
        for (int q = 127; q >= 0; q--) {
            if (acc + s_rh[q] > HOT_TGT) break;
            acc += s_rh[q];
            thr = (float)q * (r2b / 128.f);
        }
        s_thresh = thr;
    }
    __syncthreads();
    const float thresh = s_thresh;

    // ---- pass 2: Morton histogram over cold ----
    for (int i = tid; i < NN; i += FPS_T) {
        const float x = xb[3 * i], y = xb[3 * i + 1], z = xb[3 * i + 2];
        if (r2_rn(x, y, z) < thresh) {
            const int c = fps_cell(x, y, z, gmnx, gmny, gmnz, isx, isy, isz);
            atomicAdd(&hist[c], 1u);
        }
    }
    __syncthreads();

    // ---- exclusive scan of hist[2048] ----
    {
        const int t8 = tid * 8;
        unsigned v[8], s = 0;
#pragma unroll
        for (int q = 0; q < 8; q++) { v[q] = hist[t8 + q]; s += v[q]; }
        unsigned inc = s;
#pragma unroll
        for (int off = 1; off < 32; off <<= 1) {
            const unsigned n = __shfl_up_sync(0xffffffffu, inc, off);
            if (lane >= off) inc += n;
        }
        if (lane == 31) s_wsum[w] = inc;
        __syncthreads();
        if (tid < FPS_W) {
            const unsigned ws = s_wsum[tid];
            unsigned winc = ws;
#pragma unroll
            for (int off = 1; off < FPS_W; off <<= 1) {
                const unsigned n = __shfl_up_sync(0x000000ffu, winc, off);
                if ((int)tid >= off) winc += n;
            }
            s_wbase[tid] = winc - ws;
        }
        __syncthreads();
        unsigned run = s_wbase[w] + (inc - s);
#pragma unroll
        for (int q = 0; q < 8; q++) { hist[t8 + q] = run; run += v[q]; }
    }
    __syncthreads();

    // ---- pass 3: scatter hot / cold (inv = 16383 - i) ----
    for (int i = tid; i < NN; i += FPS_T) {
        const float x = xb[3 * i], y = xb[3 * i + 1], z = xb[3 * i + 2];
        if (r2_rn(x, y, z) >= thresh) {
            const unsigned pos = atomicAdd(&s_hotCnt, 1u);
            hot4[pos] = make_float4(x, y, z, __uint_as_float(16383u - (unsigned)i));
        } else {
            const int c = fps_cell(x, y, z, gmnx, gmny, gmnz, isx, isy, isz);
            const unsigned slot = atomicAdd(&hist[c], 1u);
            cxy[slot]   = make_float2(x, y);
            inv16[slot] = (unsigned short)(16383u - (unsigned)i);
        }
    }
    __syncthreads();

    const int hc    = (int)s_hotCnt;
    const int coldN = NN - hc;
    const int nch   = (coldN + 127) >> 7;

    // pads (duplicates: identical keys/coords, harmless)
    for (int s2 = hc + tid; s2 < HOTCAP; s2 += FPS_T)
        hot4[s2] = (hc > 0) ? hot4[0]
                            : make_float4(xb[0], xb[1], xb[2], __uint_as_float(16383u));
    for (int s2 = coldN + tid; s2 < nch * 128; s2 += FPS_T) {
        cxy[s2]   = cxy[coldN - 1];
        inv16[s2] = inv16[coldN - 1];
    }
    __syncthreads();

    // ---- hot -> registers (4 pts/thread) ----
    float hx[4], hy[4], hz[4], hd[4];
    unsigned hinv[4];
#pragma unroll
    for (int k = 0; k < 4; k++) {
        const float4 h = hot4[tid + FPS_T * k];
        hx[k] = h.x; hy[k] = h.y; hz[k] = h.z;
        hinv[k] = __float_as_uint(h.w);
        hd[k] = 1e10f;
    }

    // ---- owner fill: cold z + dist regs, chunk AABBs (stride 8) ----
    float cz[64], cd[64];
#pragma unroll
    for (int k = 0; k < 64; k++) { cz[k] = 0.f; cd[k] = 1e10f; }

#pragma unroll
    for (int m = 0; m < 16; m++) {
        const int c = w + FPS_W * m;
        if (c < nch) {
            float lmn0 = 1e30f, lmn1 = 1e30f, lmn2 = 1e30f;
            float lmx0 = -1e30f, lmx1 = -1e30f, lmx2 = -1e30f;
#pragma unroll
            for (int k = 0; k < 4; k++) {
                const int slot = c * 128 + lane + 32 * k;
                const float2 xy = cxy[slot];
                const int oi = 16383 - (int)inv16[slot];
                const float z = __ldg(xb + 3 * oi + 2);
                cz[m * 4 + k] = z;
                lmn0 = fminf(lmn0, xy.x); lmn1 = fminf(lmn1, xy.y); lmn2 = fminf(lmn2, z);
                lmx0 = fmaxf(lmx0, xy.x); lmx1 = fmaxf(lmx1, xy.y); lmx2 = fmaxf(lmx2, z);
            }
#pragma unroll
            for (int off = 16; off; off >>= 1) {
                lmn0 = fminf(lmn0, __shfl_xor_sync(0xffffffffu, lmn0, off));
                lmn1 = fminf(lmn1, __shfl_xor_sync(0xffffffffu, lmn1, off));
                lmn2 = fminf(lmn2, __shfl_xor_sync(0xffffffffu, lmn2, off));
                lmx0 = fmaxf(lmx0, __shfl_xor_sync(0xffffffffu, lmx0, off));
                lmx1 = fmaxf(lmx1, __shfl_xor_sync(0xffffffffu, lmx1, off));
                lmx2 = fmaxf(lmx2, __shfl_xor_sync(0xffffffffu, lmx2, off));
            }
            if (lane == 0) {
                aabb[c * 8 + 0] = lmn0; aabb[c * 8 + 1] = lmn1; aabb[c * 8 + 2] = lmn2;
                aabb[c * 8 + 4] = lmx0; aabb[c * 8 + 5] = lmx1; aabb[c * 8 + 6] = lmx2;
                ckey[c] = ((u64)__float_as_uint(1e10f)) << 14;  // force first scan
            }
        }
    }
    __syncthreads();

    float* outx = out_newxyz + (size_t)b * SS * 3;
    float ccx = __ldg(xb + 0), ccy = __ldg(xb + 1), ccz = __ldg(xb + 2);

    // ---- main loop ----
    for (int j = 0; j < SS; j++) {
        if (tid == 0) {
            outx[3 * j + 0] = ccx;
            outx[3 * j + 1] = ccy;
            outx[3 * j + 2] = ccz;
        }
        const float nx = -ccx, ny = -ccy, nz = -ccz;

        // --- hot scan (always); reduce only if some dist changed ---
        {
            u64 bk = 0ull; float bx = 0.f, by = 0.f, bz = 0.f;
            bool chg = false;
#pragma unroll
            for (int k = 0; k < 4; k++) {
                const float d = dist_rn(hx[k], hy[k], hz[k], nx, ny, nz);
                const float old = hd[k];
                const float nd = fminf(old, d);
                chg |= (nd < old);
                hd[k] = nd;
                const u64 key = ((u64)__float_as_uint(nd) << 14) | (u64)hinv[k];
                if (key > bk) { bk = key; bx = hx[k]; by = hy[k]; bz = hz[k]; }
            }
            if (__ballot_sync(0xffffffffu, chg)) {
                u64 mk = bk;
#pragma unroll
                for (int off = 16; off; off >>= 1) {
                    const u64 ok = __shfl_xor_sync(0xffffffffu, mk, off);
                    if (ok > mk) mk = ok;
                }
                const unsigned own = __ballot_sync(0xffffffffu, bk == mk);
                if (lane == (int)(__ffs(own) - 1)) {
                    ckey[128 + w] = mk;
                    cwin[128 + w] = make_float4(bx, by, bz, 0.f);
                }
            }
        }

        // --- prune: lanes 0..15 test this warp's 16 chunks ---
        bool act = false;
        if (lane < 16) {
            const int c = w + FPS_W * lane;
            const float4 bmn = *(const float4*)(aabb + c * 8);
            const float4 bmx = *(const float4*)(aabb + c * 8 + 4);
            const float dxm = fmaxf(fmaxf(__fadd_rn(bmn.x, nx), -__fadd_rn(bmx.x, nx)), 0.f);
            const float dym = fmaxf(fmaxf(__fadd_rn(bmn.y, ny), -__fadd_rn(bmx.y, ny)), 0.f);
            const float dzm = fmaxf(fmaxf(__fadd_rn(bmn.z, nz), -__fadd_rn(bmx.z, nz)), 0.f);
            const float dmin2 = __fadd_rn(__fadd_rn(__fmul_rn(dxm, dxm), __fmul_rn(dym, dym)),
                                          __fmul_rn(dzm, dzm));
            const float cm = __uint_as_float((unsigned)(ckey[c] >> 14));
            act = dmin2 < cm;   // ckey==0 for c>=nch => never active
        }
        const unsigned mask = __ballot_sync(0xffffffffu, act);

        // --- cold scans; reduce only if some dist changed ---
#pragma unroll
        for (int m = 0; m < 16; m++) {
            if ((mask >> m) & 1u) {   // warp-uniform
                const int c = w + FPS_W * m;
                u64 bk = 0ull; float bx = 0.f, by = 0.f, bz = 0.f;
                bool chg = false;
#pragma unroll
                for (int k = 0; k < 4; k++) {
                    const int slot = c * 128 + lane + 32 * k;
                    const float2 xy = cxy[slot];
                    const float zz = cz[m * 4 + k];
                    const float d = dist_rn(xy.x, xy.y, zz, nx, ny, nz);
                    const float old = cd[m * 4 + k];
                    const float nd = fminf(old, d);
                    chg |= (nd < old);
                    cd[m * 4 + k] = nd;
                    const u64 key = ((u64)__float_as_uint(nd) << 14) | (u64)inv16[slot];
                    if (key > bk) { bk = key; bx = xy.x; by = xy.y; bz = zz; }
                }
                if (__ballot_sync(0xffffffffu, chg)) {
                    u64 mk = bk;
#pragma unroll
                    for (int off = 16; off; off >>= 1) {
                        const u64 ok = __shfl_xor_sync(0xffffffffu, mk, off);
                        if (ok > mk) mk = ok;
                    }
                    const unsigned own = __ballot_sync(0xffffffffu, bk == mk);
                    if (lane == (int)(__ffs(own) - 1)) {
                        ckey[c] = mk;
                        cwin[c] = make_float4(bx, by, bz, 0.f);
                    }
                }
            }
        }
        __syncthreads();

        // --- flat block argmax (every warp, redundant, no stage-2) ---
        {
            const u64 v0 = ckey[lane];
            const u64 v1 = ckey[lane + 32];
            const u64 v2 = ckey[lane + 64];
            const u64 v3 = ckey[lane + 96];
            const u64 v4 = ckey[lane + 128];   // 128..159 (pads = 0)
            u64 a01 = v0 > v1 ? v0 : v1;
            u64 a23 = v2 > v3 ? v2 : v3;
            u64 K = a01 > a23 ? a01 : a23;
            if (v4 > K) K = v4;
#pragma unroll
            for (int off = 16; off; off >>= 1) {
                const u64 o = __shfl_xor_sync(0xffffffffu, K, off);
                if (o > K) K = o;
            }
            int myc = -1;
            if (v0 == K) myc = lane;
            else if (v1 == K) myc = lane + 32;
            else if (v2 == K) myc = lane + 64;
            else if (v3 == K) myc = lane + 96;
            else if (v4 == K) myc = lane + 128;
            const unsigned has = __ballot_sync(0xffffffffu, myc >= 0);
            const int src = __shfl_sync(0xffffffffu, myc, (int)(__ffs(has) - 1));
            const float4 wv = cwin[src];
            ccx = wv.x; ccy = wv.y; ccz = wv.z;
        }
        __syncthreads();   // WAR: ckey/cwin rewritten next iteration
    }
}

// =================================================================
// Kernel 2: transpose features (B,C,N) -> (B,N,C)
// =================================================================
__global__ void transpose_kernel(const float* __restrict__ f)
{
    __shared__ float tile[32][33];
    const int b  = blockIdx.z;
    const int n0 = blockIdx.x * 32;
    const int c0 = blockIdx.y * 32;
    const int tx = threadIdx.x, ty = threadIdx.y;
    tile[ty][tx] = f[((size_t)b * CIN + (c0 + ty)) * NN + n0 + tx];
    __syncthreads();
    g_featsT[((size_t)b * NN + (n0 + ty)) * CIN + c0 + tx] = tile[tx][ty];
}

// =================================================================
// Kernel 3: ball query (one warp per group), first-32-ascending
// =================================================================
__global__ void ballq_kernel(const float* __restrict__ xyz,
                             const float* __restrict__ newxyz)
{
    const int g    = blockIdx.x * 8 + (threadIdx.x >> 5);
    const int lane = threadIdx.x & 31;
    const int b    = g >> 12;
    const float* xb = xyz + (size_t)b * NN * 3;

    const float cx = newxyz[g * 3 + 0];
    const float cy = newxyz[g * 3 + 1];
    const float cz = newxyz[g * 3 + 2];

    int* out = g_ballIdx + g * NSAMP;
    int cnt = 0;

    for (int base = 0; base < NN && cnt < NSAMP; base += 32) {
        const int i = base + lane;
        const float dx = xb[3 * i + 0] - cx;
        const float dy = xb[3 * i + 1] - cy;
        const float dz = xb[3 * i + 2] - cz;
        const float d2 = __fadd_rn(__fadd_rn(__fmul_rn(dx, dx), __fmul_rn(dy, dy)),
                                   __fmul_rn(dz, dz));
        const bool inb = d2 < 0.25f;
        const unsigned m = __ballot_sync(0xffffffffu, inb);
        const int pos = cnt + __popc(m & ((1u << lane) - 1u));
        if (inb && pos < NSAMP) out[pos] = i;
        cnt += __popc(m);
    }
    __syncwarp();
    if (cnt == 0) {
        out[lane] = 0;
    } else if (cnt < NSAMP) {
        const int first = out[0];
        if (lane >= cnt) out[lane] = first;
    }
    if (lane == 0) g_ballCnt[g] = cnt;
}

// =================================================================
// Kernel 4: fused gather + 3-layer MLP + maxpool + agg + score
// =================================================================
#define W1_STR 65
#define W2_STR 65
#define W3_STR 129
#define SM_INT_F   (67 * 36)
#define SM_W1_F    4356
#define SM_W2_F    (64 * W2_STR)
#define SM_W3_F    (64 * W3_STR)
#define SM_H_F     (64 * 36)
#define MLP_SMEM_FLOATS (SM_INT_F + SM_W1_F + SM_W2_F + SM_W3_F + 2 * SM_H_F + 256 + 256 + 128 + 128 + 32)

__global__ __launch_bounds__(256, 2) void group_mlp_kernel(
    const float* __restrict__ xyz,
    const float* __restrict__ newxyz,
    const float* __restrict__ w1, const float* __restrict__ b1,
    const float* __restrict__ w2, const float* __restrict__ b2,
    const float* __restrict__ w3, const float* __restrict__ b3,
    const float* __restrict__ wa, const float* __restrict__ ba,
    const float* __restrict__ wc, const float* __restrict__ bc,
    float* __restrict__ d_out)
{
    extern __shared__ float sm[];
    float* inT     = sm;
    float* w1s     = inT + SM_INT_F;
    float* w2s     = w1s + SM_W1_F;
    float* w3s     = w2s + SM_W2_F;
    float* h1T     = w3s + SM_W3_F;
    float* h2T     = h1T + SM_H_F;
    float* bss     = h2T + SM_H_F;
    float* poolbuf = bss + 256;
    float* pooled  = poolbuf + 256;
    float* aggv    = pooled + 128;
    int*   idxs    = (int*)(aggv + 128);

    const int g = blockIdx.x;
    const int b = g >> 12;
    const int s = g & 4095;
    const int tid = threadIdx.x;

    if (tid < 32)  idxs[tid] = g_ballIdx[g * NSAMP + tid];
    if (tid < 64)       bss[tid] = b1[tid];
    else if (tid < 128) bss[tid] = b2[tid - 64];
    if (tid < 128) bss[128 + tid] = b3[tid];

    for (int e = tid; e < 64 * 67; e += 256) {
        const int oc = e / 67, i = e % 67;
        w1s[i * W1_STR + oc] = w1[e];
    }
    for (int e = tid; e < 64 * 64; e += 256) {
        const int oc = e >> 6, i = e & 63;
        w2s[i * W2_STR + oc] = w2[e];
    }
    for (int e = tid; e < 128 * 64; e += 256) {
        const int oc = e >> 6, i = e & 63;
        w3s[i * W3_STR + oc] = w3[e];
    }
    __syncthreads();

    const float* xb = xyz + (size_t)b * NN * 3;
    const float cx = newxyz[g * 3 + 0];
    const float cy = newxyz[g * 3 + 1];
    const float cz = newxyz[g * 3 + 2];
    for (int e = tid; e < 32 * 67; e += 256) {
        const int nb = e & 31;
        const int i  = e >> 5;
        const int pi = idxs[nb];
        float v;
        if (i == 0)      v = xb[pi * 3 + 0] - cx;
        else if (i == 1) v = xb[pi * 3 + 1] - cy;
        else if (i == 2) v = xb[pi * 3 + 2] - cz;
        else             v = g_featsT[((size_t)b * NN + pi) * CIN + (i - 3)];
        inT[i * 36 + nb] = v;
    }
    __syncthreads();

    {
        const int oc = tid & 63, ng = tid >> 6;
        float acc[8];
        const float bv = bss[oc];
#pragma unroll
        for (int n = 0; n < 8; n++) acc[n] = bv;
        for (int i = 0; i < 67; i++) {
            const float w = w1s[i * W1_STR + oc];
            const float4* xp = (const float4*)(inT + i * 36 + ng * 8);
            const float4 x0 = xp[0], x1 = xp[1];
            acc[0] += w * x0.x; acc[1] += w * x0.y; acc[2] += w * x0.z; acc[3] += w * x0.w;
            acc[4] += w * x1.x; acc[5] += w * x1.y; acc[6] += w * x1.z; acc[7] += w * x1.w;
        }
        float* hp = h1T + oc * 36 + ng * 8;
#pragma unroll
        for (int n = 0; n < 8; n++) hp[n] = fmaxf(acc[n], 0.f);
    }
    __syncthreads();

    {
        const int oc = tid & 63, ng = tid >> 6;
        float acc[8];
        const float bv = bss[64 + oc];
#pragma unroll
        for (int n = 0; n < 8; n++) acc[n] = bv;
        for (int i = 0; i < 64; i++) {
            const float w = w2s[i * W2_STR + oc];
            const float4* xp = (const float4*)(h1T + i * 36 + ng * 8);
            const float4 x0 = xp[0], x1 = xp[1];
            acc[0] += w * x0.x; acc[1] += w * x0.y; acc[2] += w * x0.z; acc[3] += w * x0.w;
            acc[4] += w * x1.x; acc[5] += w * x1.y; acc[6] += w * x1.z; acc[7] += w * x1.w;
        }
        float* hp = h2T + oc * 36 + ng * 8;
#pragma unroll
        for (int n = 0; n < 8; n++) hp[n] = fmaxf(acc[n], 0.f);
    }
    __syncthreads();

    {
        const int oc = tid & 127, ng = tid >> 7;
        float acc[16];
        const float bv = bss[128 + oc];
#pragma unroll
        for (int n = 0; n < 16; n++) acc[n] = bv;
        for (int i = 0; i < 64; i++) {
            const float w = w3s[i * W3_STR + oc];
            const float4* xp = (const float4*)(h2T + i * 36 + ng * 16);
            const float4 x0 = xp[0], x1 = xp[1], x2 = xp[2], x3 = xp[3];
            acc[0]  += w * x0.x; acc[1]  += w * x0.y; acc[2]  += w * x0.z; acc[3]  += w * x0.w;
            acc[4]  += w * x1.x; acc[5]  += w * x1.y; acc[6]  += w * x1.z; acc[7]  += w * x1.w;
            acc[8]  += w * x2.x; acc[9]  += w * x2.y; acc[10] += w * x2.z; acc[11] += w * x2.w;
            acc[12] += w * x3.x; acc[13] += w * x3.y; acc[14] += w * x3.z; acc[15] += w * x3.w;
        }
        float m = acc[0];
#pragma unroll
        for (int n = 1; n < 16; n++) m = fmaxf(m, acc[n]);
        m = fmaxf(m, 0.f);
        poolbuf[oc * 2 + ng] = m;
    }
    __syncthreads();

    const int cnt = g_ballCnt[g];
    if (tid < 128) {
        const float m = fmaxf(poolbuf[tid * 2], poolbuf[tid * 2 + 1]);
        pooled[tid] = (cnt > 0) ? m : 0.f;
    }
    __syncthreads();

    if (tid < 128) {
        const int o = tid;
        float acc = ba[o];
        const float4* w4 = (const float4*)(wa + o * 128);
#pragma unroll 8
        for (int i = 0; i < 32; i++) {
            const float4 wv = __ldg(w4 + i);
            acc += pooled[4 * i + 0] * wv.x;
            acc += pooled[4 * i + 1] * wv.y;
            acc += pooled[4 * i + 2] * wv.z;
            acc += pooled[4 * i + 3] * wv.w;
        }
        const float a = fmaxf(acc, 0.f);
        aggv[o] = a;
        d_out[OUT_FEAT_OFF + ((size_t)(b * 128 + o)) * SS + s] = a;
    }
    __syncthreads();

    if (tid < 32) {
        float p = 0.f;
#pragma unroll
        for (int k = 0; k < 4; k++) {
            const int i = k * 32 + tid;
            p += aggv[i] * wc[i];
        }
#pragma unroll
        for (int off = 16; off; off >>= 1)
            p += __shfl_down_sync(0xffffffffu, p, off);
        if (tid == 0)
            d_out[OUT_SCORE_OFF + b * SS + s] = p + bc[0];
    }
}

// =================================================================
// launch
// =================================================================
extern "C" void kernel_launch(void* const* d_in, const int* in_sizes, int n_in,
                              void* d_out, int out_size)
{
    const float* xyz      = (const float*)d_in[0];
    const float* features = (const float*)d_in[1];
    const float* w1 = (const float*)d_in[2];
    const float* b1 = (const float*)d_in[3];
    const float* w2 = (const float*)d_in[4];
    const float* b2 = (const float*)d_in[5];
    const float* w3 = (const float*)d_in[6];
    const float* b3 = (const float*)d_in[7];
    const float* wa = (const float*)d_in[8];
    const float* ba = (const float*)d_in[9];
    const float* wc = (const float*)d_in[10];
    const float* bc = (const float*)d_in[11];
    float* out = (float*)d_out;

    static bool attr_set = false;
    if (!attr_set) {
        cudaFuncSetAttribute(fps_kernel, cudaFuncAttributeMaxDynamicSharedMemorySize,
                             FPS_SMEM_BYTES);
        cudaFuncSetAttribute(group_mlp_kernel, cudaFuncAttributeMaxDynamicSharedMemorySize,
                             MLP_SMEM_FLOATS * (int)sizeof(float));
        attr_set = true;
    }

    // 1) transpose features to (B,N,C)
    transpose_kernel<<<dim3(NN / 32, CIN / 32, BB), dim3(32, 32)>>>(features);

    // 2) FPS -> writes new_xyz into d_out[0:24576)
    fps_kernel<<<BB, FPS_T, FPS_SMEM_BYTES>>>(xyz, out + OUT_XYZ_OFF);

    // 3) ball query
    ballq_kernel<<<(BB * SS) / 8, 256>>>(xyz, out + OUT_XYZ_OFF);

    // 4) fused gather + MLP + pool + agg + score
    group_mlp_kernel<<<BB * SS, 256, MLP_SMEM_FLOATS * sizeof(float)>>>(
        xyz, out + OUT_XYZ_OFF,
        w1, b1, w2, b2, w3, b3, wa, ba, wc, bc, out);
}

// round 9
// speedup vs baseline: 1.9074x; 1.1227x over previous
#include <cuda_runtime.h>
#include <cuda_bf16.h>

// Problem constants
#define BB 2
#define NN 16384
#define CIN 64
#define SS 4096
#define NSAMP 32

// Output layout (floats): new_xyz | new_features | scores
#define OUT_XYZ_OFF   0
#define OUT_FEAT_OFF  (BB * SS * 3)                       // 24576
#define OUT_SCORE_OFF (OUT_FEAT_OFF + BB * 128 * SS)      // 1073152

// ---------------- scratch (no allocations allowed) ----------------
__device__ float g_featsT[BB * NN * CIN];    // (B,N,C) transposed features, 8 MB
__device__ int   g_ballIdx[BB * SS * NSAMP]; // neighbor indices
__device__ int   g_ballCnt[BB * SS];         // in-ball counts (0 => empty)

typedef unsigned long long u64;

// =================================================================
// Kernel 1: FPS (one 256-thread block per batch)
//  - hot tail points (<=768, padded to 1024) in registers; 8 virtual
//    chunks ckey[128..135], scanned every iter
//  - cold points Morton-sorted into <=128 chunks of 128, AABB pruned
//  - DIRTY-SKIP: per-chunk reduce only if some dist changed
//  - warp argmax reduces via __reduce_max_sync (REDUX):
//    max dist-bits first, then max inv among dist-winners => exact
//    (dist<<14)|inv winner with first-index tie-break
// =================================================================
#define FPS_T   256
#define FPS_W   8
#define HOTCAP  1024
#define HOT_TGT 768
#define NCELL   2048

#define FPS_SMEM_BYTES (131072 + 32768 + 16384 + 8192 + 4096 + 1280 + 2176)

__device__ __forceinline__ float r2_rn(float x, float y, float z)
{
    return __fadd_rn(__fadd_rn(__fmul_rn(x, x), __fmul_rn(y, y)), __fmul_rn(z, z));
}
__device__ __forceinline__ float dist_rn(float x, float y, float z,
                                         float nx, float ny, float nz)
{
    const float dx = __fadd_rn(x, nx);
    const float dy = __fadd_rn(y, ny);
    const float dz = __fadd_rn(z, nz);
    return __fadd_rn(__fadd_rn(__fmul_rn(dx, dx), __fmul_rn(dy, dy)), __fmul_rn(dz, dz));
}

__device__ __forceinline__ int fps_cell(float x, float y, float z,
                                        float mnx, float mny, float mnz,
                                        float isx, float isy, float isz)
{
    int qx = __float2int_rd((x - mnx) * isx); qx = max(0, min(15, qx));
    int qy = __float2int_rd((y - mny) * isy); qy = max(0, min(15, qy));
    int qz = __float2int_rd((z - mnz) * isz); qz = max(0, min(7,  qz));
    return  (qx & 1)        | ((qy & 1) << 1)        | ((qz & 1) << 2)
         | (((qx >> 1) & 1) << 3) | (((qy >> 1) & 1) << 4) | (((qz >> 1) & 1) << 5)
         | (((qx >> 2) & 1) << 6) | (((qy >> 2) & 1) << 7) | (((qz >> 2) & 1) << 8)
         | (((qx >> 3) & 1) << 9) | (((qy >> 3) & 1) << 10);
}

__global__ __launch_bounds__(FPS_T) void fps_kernel(
    const float* __restrict__ xyz, float* __restrict__ out_newxyz)
{
    extern __shared__ unsigned char raw[];
    float2*         cxy   = (float2*)raw;                      // [16384]
    unsigned short* inv16 = (unsigned short*)(cxy + NN);       // [16384]
    float4*         hot4  = (float4*)(inv16 + NN);             // [1024]
    unsigned*       hist  = (unsigned*)(hot4 + HOTCAP);        // [2048]
    float*          aabb  = (float*)(hist + NCELL);            // [128*8]
    u64*            ckey  = (u64*)(aabb + 128 * 8);            // [160]
    float4*         cwin  = (float4*)(ckey + 160);             // [136]

    __shared__ float    s_wred[FPS_W][6];
    __shared__ unsigned s_wsum[FPS_W], s_wbase[FPS_W];
    __shared__ unsigned s_rh[128];
    __shared__ float    s_r2b, s_thresh;
    __shared__ float    s_grid[6];
    __shared__ unsigned s_hotCnt;

    const int b    = blockIdx.x;
    const int tid  = threadIdx.x;
    const int lane = tid & 31, w = tid >> 5;
    const float* xb = xyz + (size_t)b * NN * 3;

    // ---- pass 0: global AABB ----
    {
        float mnx = 1e30f, mny = 1e30f, mnz = 1e30f;
        float mxx = -1e30f, mxy = -1e30f, mxz = -1e30f;
        for (int i = tid; i < NN; i += FPS_T) {
            const float x = xb[3 * i], y = xb[3 * i + 1], z = xb[3 * i + 2];
            mnx = fminf(mnx, x); mny = fminf(mny, y); mnz = fminf(mnz, z);
            mxx = fmaxf(mxx, x); mxy = fmaxf(mxy, y); mxz = fmaxf(mxz, z);
        }
#pragma unroll
        for (int off = 16; off; off >>= 1) {
            mnx = fminf(mnx, __shfl_xor_sync(0xffffffffu, mnx, off));
            mny = fminf(mny, __shfl_xor_sync(0xffffffffu, mny, off));
            mnz = fminf(mnz, __shfl_xor_sync(0xffffffffu, mnz, off));
            mxx = fmaxf(mxx, __shfl_xor_sync(0xffffffffu, mxx, off));
            mxy = fmaxf(mxy, __shfl_xor_sync(0xffffffffu, mxy, off));
            mxz = fmaxf(mxz, __shfl_xor_sync(0xffffffffu, mxz, off));
        }
        if (lane == 0) {
            s_wred[w][0] = mnx; s_wred[w][1] = mny; s_wred[w][2] = mnz;
            s_wred[w][3] = mxx; s_wred[w][4] = mxy; s_wred[w][5] = mxz;
        }
    }
    for (int i = tid; i < NCELL; i += FPS_T) hist[i] = 0;
    if (tid < 160) ckey[tid] = 0ull;
    if (tid < 128) s_rh[tid] = 0;
    if (tid == 0) s_hotCnt = 0;
    __syncthreads();
    if (tid == 0) {
        float a0 = 1e30f, a1 = 1e30f, a2 = 1e30f, a3 = -1e30f, a4 = -1e30f, a5 = -1e30f;
        for (int i = 0; i < FPS_W; i++) {
            a0 = fminf(a0, s_wred[i][0]); a1 = fminf(a1, s_wred[i][1]); a2 = fminf(a2, s_wred[i][2]);
            a3 = fmaxf(a3, s_wred[i][3]); a4 = fmaxf(a4, s_wred[i][4]); a5 = fmaxf(a5, s_wred[i][5]);
        }
        s_grid[0] = a0; s_grid[1] = a1; s_grid[2] = a2;
        s_grid[3] = 16.f / fmaxf(a3 - a0, 1e-9f);
        s_grid[4] = 16.f / fmaxf(a4 - a1, 1e-9f);
        s_grid[5] = 8.f  / fmaxf(a5 - a2, 1e-9f);
        const float bx = fmaxf(fabsf(a0), fabsf(a3));
        const float by = fmaxf(fabsf(a1), fabsf(a4));
        const float bz = fmaxf(fabsf(a2), fabsf(a5));
        s_r2b = bx * bx + by * by + bz * bz + 1e-6f;
    }
    __syncthreads();

    const float gmnx = s_grid[0], gmny = s_grid[1], gmnz = s_grid[2];
    const float isx = s_grid[3], isy = s_grid[4], isz = s_grid[5];
    const float r2b = s_r2b;

    // ---- pass 1: r2 histogram -> deterministic hot threshold ----
    for (int i = tid; i < NN; i += FPS_T) {
        const float r2 = r2_rn(xb[3 * i], xb[3 * i + 1], xb[3 * i + 2]);
        const int bin = min(127, (int)(r2 * (128.f / r2b)));
        atomicAdd(&s_rh[bin], 1u);
    }
    __syncthreads();
    if (tid == 0) {
        unsigned acc = 0;
        float thr = 3e38f;
        for (int q = 127; q >= 0; q--) {
            if (acc + s_rh[q] > HOT_TGT) break;
            acc += s_rh[q];
            thr = (float)q * (r2b / 128.f);
        }
        s_thresh = thr;
    }
    __syncthreads();
    const float thresh = s_thresh;

    // ---- pass 2: Morton histogram over cold ----
    for (int i = tid; i < NN; i += FPS_T) {
        const float x = xb[3 * i], y = xb[3 * i + 1], z = xb[3 * i + 2];
        if (r2_rn(x, y, z) < thresh) {
            const int c = fps_cell(x, y, z, gmnx, gmny, gmnz, isx, isy, isz);
            atomicAdd(&hist[c], 1u);
        }
    }
    __syncthreads();

    // ---- exclusive scan of hist[2048] ----
    {
        const int t8 = tid * 8;
        unsigned v[8], s = 0;
#pragma unroll
        for (int q = 0; q < 8; q++) { v[q] = hist[t8 + q]; s += v[q]; }
        unsigned inc = s;
#pragma unroll
        for (int off = 1; off < 32; off <<= 1) {
            const unsigned n = __shfl_up_sync(0xffffffffu, inc, off);
            if (lane >= off) inc += n;
        }
        if (lane == 31) s_wsum[w] = inc;
        __syncthreads();
        if (tid < FPS_W) {
            const unsigned ws = s_wsum[tid];
            unsigned winc = ws;
#pragma unroll
            for (int off = 1; off < FPS_W; off <<= 1) {
                const unsigned n = __shfl_up_sync(0x000000ffu, winc, off);
                if ((int)tid >= off) winc += n;
            }
            s_wbase[tid] = winc - ws;
        }
        __syncthreads();
        unsigned run = s_wbase[w] + (inc - s);
#pragma unroll
        for (int q = 0; q < 8; q++) { hist[t8 + q] = run; run += v[q]; }
    }
    __syncthreads();

    // ---- pass 3: scatter hot / cold (inv = 16383 - i) ----
    for (int i = tid; i < NN; i += FPS_T) {
        const float x = xb[3 * i], y = xb[3 * i + 1], z = xb[3 * i + 2];
        if (r2_rn(x, y, z) >= thresh) {
            const unsigned pos = atomicAdd(&s_hotCnt, 1u);
            hot4[pos] = make_float4(x, y, z, __uint_as_float(16383u - (unsigned)i));
        } else {
            const int c = fps_cell(x, y, z, gmnx, gmny, gmnz, isx, isy, isz);
            const unsigned slot = atomicAdd(&hist[c], 1u);
            cxy[slot]   = make_float2(x, y);
            inv16[slot] = (unsigned short)(16383u - (unsigned)i);
        }
    }
    __syncthreads();

    const int hc    = (int)s_hotCnt;
    const int coldN = NN - hc;
    const int nch   = (coldN + 127) >> 7;

    // pads (duplicates: identical keys/coords, harmless)
    for (int s2 = hc + tid; s2 < HOTCAP; s2 += FPS_T)
        hot4[s2] = (hc > 0) ? hot4[0]
                            : make_float4(xb[0], xb[1], xb[2], __uint_as_float(16383u));
    for (int s2 = coldN + tid; s2 < nch * 128; s2 += FPS_T) {
        cxy[s2]   = cxy[coldN - 1];
        inv16[s2] = inv16[coldN - 1];
    }
    __syncthreads();

    // ---- hot -> registers (4 pts/thread) ----
    float hx[4], hy[4], hz[4], hd[4];
    unsigned hinv[4];
#pragma unroll
    for (int k = 0; k < 4; k++) {
        const float4 h = hot4[tid + FPS_T * k];
        hx[k] = h.x; hy[k] = h.y; hz[k] = h.z;
        hinv[k] = __float_as_uint(h.w);
        hd[k] = 1e10f;
    }

    // ---- owner fill: cold z + dist regs, chunk AABBs (stride 8) ----
    float cz[64], cd[64];
#pragma unroll
    for (int k = 0; k < 64; k++) { cz[k] = 0.f; cd[k] = 1e10f; }

#pragma unroll
    for (int m = 0; m < 16; m++) {
        const int c = w + FPS_W * m;
        if (c < nch) {
            float lmn0 = 1e30f, lmn1 = 1e30f, lmn2 = 1e30f;
            float lmx0 = -1e30f, lmx1 = -1e30f, lmx2 = -1e30f;
#pragma unroll
            for (int k = 0; k < 4; k++) {
                const int slot = c * 128 + lane + 32 * k;
                const float2 xy = cxy[slot];
                const int oi = 16383 - (int)inv16[slot];
                const float z = __ldg(xb + 3 * oi + 2);
                cz[m * 4 + k] = z;
                lmn0 = fminf(lmn0, xy.x); lmn1 = fminf(lmn1, xy.y); lmn2 = fminf(lmn2, z);
                lmx0 = fmaxf(lmx0, xy.x); lmx1 = fmaxf(lmx1, xy.y); lmx2 = fmaxf(lmx2, z);
            }
#pragma unroll
            for (int off = 16; off; off >>= 1) {
                lmn0 = fminf(lmn0, __shfl_xor_sync(0xffffffffu, lmn0, off));
                lmn1 = fminf(lmn1, __shfl_xor_sync(0xffffffffu, lmn1, off));
                lmn2 = fminf(lmn2, __shfl_xor_sync(0xffffffffu, lmn2, off));
                lmx0 = fmaxf(lmx0, __shfl_xor_sync(0xffffffffu, lmx0, off));
                lmx1 = fmaxf(lmx1, __shfl_xor_sync(0xffffffffu, lmx1, off));
                lmx2 = fmaxf(lmx2, __shfl_xor_sync(0xffffffffu, lmx2, off));
            }
            if (lane == 0) {
                aabb[c * 8 + 0] = lmn0; aabb[c * 8 + 1] = lmn1; aabb[c * 8 + 2] = lmn2;
                aabb[c * 8 + 4] = lmx0; aabb[c * 8 + 5] = lmx1; aabb[c * 8 + 6] = lmx2;
                ckey[c] = ((u64)__float_as_uint(1e10f)) << 14;  // force first scan
            }
        }
    }
    __syncthreads();

    float* outx = out_newxyz + (size_t)b * SS * 3;
    float ccx = __ldg(xb + 0), ccy = __ldg(xb + 1), ccz = __ldg(xb + 2);

    // ---- main loop ----
    for (int j = 0; j < SS; j++) {
        if (tid == 0) {
            outx[3 * j + 0] = ccx;
            outx[3 * j + 1] = ccy;
            outx[3 * j + 2] = ccz;
        }
        const float nx = -ccx, ny = -ccy, nz = -ccz;

        // --- hot scan (always); REDUX reduce only if dist changed ---
        {
            u64 bk = 0ull; float bx = 0.f, by = 0.f, bz = 0.f;
            bool chg = false;
#pragma unroll
            for (int k = 0; k < 4; k++) {
                const float d = dist_rn(hx[k], hy[k], hz[k], nx, ny, nz);
                const float old = hd[k];
                const float nd = fminf(old, d);
                chg |= (nd < old);
                hd[k] = nd;
                const u64 key = ((u64)__float_as_uint(nd) << 14) | (u64)hinv[k];
                if (key > bk) { bk = key; bx = hx[k]; by = hy[k]; bz = hz[k]; }
            }
            if (__ballot_sync(0xffffffffu, chg)) {
                const unsigned d32 = (unsigned)(bk >> 14);
                const unsigned K32 = __reduce_max_sync(0xffffffffu, d32);
                const unsigned myinv = (unsigned)(bk & 0x3FFFull);
                const unsigned I = __reduce_max_sync(0xffffffffu, (d32 == K32) ? myinv : 0u);
                const bool isw = (d32 == K32) && (myinv == I);
                const unsigned own = __ballot_sync(0xffffffffu, isw);
                if (lane == (int)(__ffs(own) - 1)) {
                    ckey[128 + w] = ((u64)K32 << 14) | (u64)I;
                    cwin[128 + w] = make_float4(bx, by, bz, 0.f);
                }
            }
        }

        // --- prune: lanes 0..15 test this warp's 16 chunks ---
        bool act = false;
        if (lane < 16) {
            const int c = w + FPS_W * lane;
            const float4 bmn = *(const float4*)(aabb + c * 8);
            const float4 bmx = *(const float4*)(aabb + c * 8 + 4);
            const float dxm = fmaxf(fmaxf(__fadd_rn(bmn.x, nx), -__fadd_rn(bmx.x, nx)), 0.f);
            const float dym = fmaxf(fmaxf(__fadd_rn(bmn.y, ny), -__fadd_rn(bmx.y, ny)), 0.f);
            const float dzm = fmaxf(fmaxf(__fadd_rn(bmn.z, nz), -__fadd_rn(bmx.z, nz)), 0.f);
            const float dmin2 = __fadd_rn(__fadd_rn(__fmul_rn(dxm, dxm), __fmul_rn(dym, dym)),
                                          __fmul_rn(dzm, dzm));
            const float cm = __uint_as_float((unsigned)(ckey[c] >> 14));
            act = dmin2 < cm;   // ckey==0 for c>=nch => never active
        }
        const unsigned mask = __ballot_sync(0xffffffffu, act);

        // --- cold scans; REDUX reduce only if some dist changed ---
#pragma unroll
        for (int m = 0; m < 16; m++) {
            if ((mask >> m) & 1u) {   // warp-uniform
                const int c = w + FPS_W * m;
                u64 bk = 0ull; float bx = 0.f, by = 0.f, bz = 0.f;
                bool chg = false;
#pragma unroll
                for (int k = 0; k < 4; k++) {
                    const int slot = c * 128 + lane + 32 * k;
                    const float2 xy = cxy[slot];
                    const float zz = cz[m * 4 + k];
                    const float d = dist_rn(xy.x, xy.y, zz, nx, ny, nz);
                    const float old = cd[m * 4 + k];
                    const float nd = fminf(old, d);
                    chg |= (nd < old);
                    cd[m * 4 + k] = nd;
                    const u64 key = ((u64)__float_as_uint(nd) << 14) | (u64)inv16[slot];
                    if (key > bk) { bk = key; bx = xy.x; by = xy.y; bz = zz; }
                }
                if (__ballot_sync(0xffffffffu, chg)) {
                    const unsigned d32 = (unsigned)(bk >> 14);
                    const unsigned K32 = __reduce_max_sync(0xffffffffu, d32);
                    const unsigned myinv = (unsigned)(bk & 0x3FFFull);
                    const unsigned I = __reduce_max_sync(0xffffffffu, (d32 == K32) ? myinv : 0u);
                    const bool isw = (d32 == K32) && (myinv == I);
                    const unsigned own = __ballot_sync(0xffffffffu, isw);
                    if (lane == (int)(__ffs(own) - 1)) {
                        ckey[c] = ((u64)K32 << 14) | (u64)I;
                        cwin[c] = make_float4(bx, by, bz, 0.f);
                    }
                }
            }
        }
        __syncthreads();

        // --- flat block argmax via REDUX (every warp, redundant) ---
        {
            const u64 v0 = ckey[lane];
            const u64 v1 = ckey[lane + 32];
            const u64 v2 = ckey[lane + 64];
            const u64 v3 = ckey[lane + 96];
            const u64 v4 = ckey[lane + 128];   // pads = 0
            u64 a01 = v0 > v1 ? v0 : v1;
            u64 a23 = v2 > v3 ? v2 : v3;
            u64 mk = a01 > a23 ? a01 : a23;
            if (v4 > mk) mk = v4;
            const unsigned d32 = (unsigned)(mk >> 14);
            const unsigned K32 = __reduce_max_sync(0xffffffffu, d32);
            const unsigned I = __reduce_max_sync(0xffffffffu,
                (d32 == K32) ? (unsigned)(mk & 0x3FFFull) : 0u);
            const u64 W = ((u64)K32 << 14) | (u64)I;
            int myc = -1;
            if (v0 == W) myc = lane;
            else if (v1 == W) myc = lane + 32;
            else if (v2 == W) myc = lane + 64;
            else if (v3 == W) myc = lane + 96;
            else if (v4 == W) myc = lane + 128;
            const unsigned has = __ballot_sync(0xffffffffu, myc >= 0);
            const int src = __shfl_sync(0xffffffffu, myc, (int)(__ffs(has) - 1));
            const float4 wv = cwin[src];
            ccx = wv.x; ccy = wv.y; ccz = wv.z;
        }
        __syncthreads();   // WAR: ckey/cwin rewritten next iteration
    }
}

// =================================================================
// Kernel 2: transpose features (B,C,N) -> (B,N,C)
// =================================================================
__global__ void transpose_kernel(const float* __restrict__ f)
{
    __shared__ float tile[32][33];
    const int b  = blockIdx.z;
    const int n0 = blockIdx.x * 32;
    const int c0 = blockIdx.y * 32;
    const int tx = threadIdx.x, ty = threadIdx.y;
    tile[ty][tx] = f[((size_t)b * CIN + (c0 + ty)) * NN + n0 + tx];
    __syncthreads();
    g_featsT[((size_t)b * NN + (n0 + ty)) * CIN + c0 + tx] = tile[tx][ty];
}

// =================================================================
// Kernel 3: ball query (one warp per group), first-32-ascending
// =================================================================
__global__ void ballq_kernel(const float* __restrict__ xyz,
                             const float* __restrict__ newxyz)
{
    const int g    = blockIdx.x * 8 + (threadIdx.x >> 5);
    const int lane = threadIdx.x & 31;
    const int b    = g >> 12;
    const float* xb = xyz + (size_t)b * NN * 3;

    const float cx = newxyz[g * 3 + 0];
    const float cy = newxyz[g * 3 + 1];
    const float cz = newxyz[g * 3 + 2];

    int* out = g_ballIdx + g * NSAMP;
    int cnt = 0;

    for (int base = 0; base < NN && cnt < NSAMP; base += 32) {
        const int i = base + lane;
        const float dx = xb[3 * i + 0] - cx;
        const float dy = xb[3 * i + 1] - cy;
        const float dz = xb[3 * i + 2] - cz;
        const float d2 = __fadd_rn(__fadd_rn(__fmul_rn(dx, dx), __fmul_rn(dy, dy)),
                                   __fmul_rn(dz, dz));
        const bool inb = d2 < 0.25f;
        const unsigned m = __ballot_sync(0xffffffffu, inb);
        const int pos = cnt + __popc(m & ((1u << lane) - 1u));
        if (inb && pos < NSAMP) out[pos] = i;
        cnt += __popc(m);
    }
    __syncwarp();
    if (cnt == 0) {
        out[lane] = 0;
    } else if (cnt < NSAMP) {
        const int first = out[0];
        if (lane >= cnt) out[lane] = first;
    }
    if (lane == 0) g_ballCnt[g] = cnt;
}

// =================================================================
// Kernel 4: fused gather + MLP + pool + agg + score, 4 GROUPS/BLOCK.
// Register-tiled layers (8oc x 4nb, 8oc x 8nb) over nb=128 (4 groups
// x 32 neighbors). Per-output accumulation order i=0..K-1 unchanged.
// =================================================================
#define MLP_G     4
#define W1_STRV   72
#define W2_STRV   72
#define W3_STRV   136
#define NBS       132
#define W1F       (67 * W1_STRV)    // 4824
#define W2F       (64 * W2_STRV)    // 4608
#define W3F       (64 * W3_STRV)    // 8704
#define ACTA_F    (67 * NBS)        // 8844
#define ACTB_F    (64 * NBS)        // 8448
// tail: bss 384 | poolbuf 2048 | pooled 512 | aggv 512 | c3 16 | idxs 128 | scnt+pad 8
#define MLP2_SMEM_FLOATS (W1F + W2F + W3F + ACTA_F + ACTB_F + 384 + 2048 + 512 + 512 + 16 + 128 + 8)

__global__ __launch_bounds__(256, 1) void group_mlp_kernel(
    const float* __restrict__ xyz,
    const float* __restrict__ newxyz,
    const float* __restrict__ w1, const float* __restrict__ b1,
    const float* __restrict__ w2, const float* __restrict__ b2,
    const float* __restrict__ w3, const float* __restrict__ b3,
    const float* __restrict__ wa, const float* __restrict__ ba,
    const float* __restrict__ wc, const float* __restrict__ bc,
    float* __restrict__ d_out)
{
    extern __shared__ float sm[];
    float* w1s     = sm;                    // [67][72]
    float* w2s     = w1s + W1F;             // [64][72]
    float* w3s     = w2s + W2F;             // [64][136]
    float* actA    = w3s + W3F;             // [67][132] inT; later h2 [64][132]
    float* actB    = actA + ACTA_F;         // [64][132] h1
    float* bss     = actB + ACTB_F;         // b1[64] b2[64] b3[128] (+pad) = 384
    float* poolbuf = bss + 384;             // [128][16]
    float* pooled  = poolbuf + 2048;        // [4][128]
    float* aggv    = pooled + 512;          // [4][128]
    float* c3      = aggv + 512;            // [4][3] (+pad) = 16
    int*   idxs    = (int*)(c3 + 16);       // [128]
    int*   scnt    = idxs + 128;            // [4] (+pad) = 8

    const int blk = blockIdx.x;
    const int g0  = blk * MLP_G;
    const int b   = g0 >> 12;               // same batch for all 4 (4096 % 4 == 0)
    const int tid = threadIdx.x;

    // ---- stage: indices, counts, centers, biases, weights ----
    if (tid < 128) idxs[tid] = g_ballIdx[(g0 + (tid >> 5)) * NSAMP + (tid & 31)];
    if (tid >= 128 && tid < 132) scnt[tid - 128] = g_ballCnt[g0 + (tid - 128)];
    if (tid >= 132 && tid < 144) {
        const int q = (tid - 132) / 3, k = (tid - 132) % 3;
        c3[q * 3 + k] = newxyz[(g0 + q) * 3 + k];
    }
    if (tid < 64)       bss[tid] = b1[tid];
    else if (tid < 128) bss[tid] = b2[tid - 64];
    if (tid < 128) bss[128 + tid] = b3[tid];

    for (int e = tid; e < 64 * 67; e += 256) {
        const int oc = e / 67, i = e % 67;
        w1s[i * W1_STRV + oc] = w1[e];
    }
    for (int e = tid; e < 64 * 64; e += 256) {
        const int oc = e >> 6, i = e & 63;
        w2s[i * W2_STRV + oc] = w2[e];
    }
    for (int e = tid; e < 128 * 64; e += 256) {
        const int oc = e >> 6, i = e & 63;
        w3s[i * W3_STRV + oc] = w3[e];
    }
    __syncthreads();

    // ---- gather: actA[i][nbg] ; nbg = q*32 + nb ----
    const float* xb = xyz + (size_t)b * NN * 3;
    for (int e = tid; e < 67 * 128; e += 256) {
        const int nbg = e & 127;
        const int i   = e >> 7;
        const int q   = nbg >> 5;
        const int pi  = idxs[nbg];
        float v;
        if (i < 3) v = xb[pi * 3 + i] - c3[q * 3 + i];
        else       v = g_featsT[((size_t)b * NN + pi) * CIN + (i - 3)];
        actA[i * NBS + nbg] = v;
    }
    __syncthreads();

    // ---- layer 1: 67 -> 64 over nb=128 ; tile 8oc x 4nb ----
    {
        const int otile = tid & 7, ntile = tid >> 3;
        const int oc0 = otile * 8, nb0 = ntile * 4;
        float acc[8][4];
        const float4 bv0 = *(const float4*)(bss + oc0);
        const float4 bv1 = *(const float4*)(bss + oc0 + 4);
        const float bv[8] = {bv0.x, bv0.y, bv0.z, bv0.w, bv1.x, bv1.y, bv1.z, bv1.w};
#pragma unroll
        for (int jj = 0; jj < 8; jj++)
#pragma unroll
            for (int n = 0; n < 4; n++) acc[jj][n] = bv[jj];
        for (int i = 0; i < 67; i++) {
            const float4 wA = *(const float4*)(w1s + i * W1_STRV + oc0);
            const float4 wB = *(const float4*)(w1s + i * W1_STRV + oc0 + 4);
            const float4 xv = *(const float4*)(actA + i * NBS + nb0);
            const float wr[8] = {wA.x, wA.y, wA.z, wA.w, wB.x, wB.y, wB.z, wB.w};
            const float xr[4] = {xv.x, xv.y, xv.z, xv.w};
#pragma unroll
            for (int jj = 0; jj < 8; jj++)
#pragma unroll
                for (int n = 0; n < 4; n++) acc[jj][n] += wr[jj] * xr[n];
        }
#pragma unroll
        for (int jj = 0; jj < 8; jj++) {
            float4 o;
            o.x = fmaxf(acc[jj][0], 0.f); o.y = fmaxf(acc[jj][1], 0.f);
            o.z = fmaxf(acc[jj][2], 0.f); o.w = fmaxf(acc[jj][3], 0.f);
            *(float4*)(actB + (oc0 + jj) * NBS + nb0) = o;
        }
    }
    __syncthreads();

    // ---- layer 2: 64 -> 64 ; tile 8oc x 4nb ; reads actB, writes actA ----
    {
        const int otile = tid & 7, ntile = tid >> 3;
        const int oc0 = otile * 8, nb0 = ntile * 4;
        float acc[8][4];
        const float4 bv0 = *(const float4*)(bss + 64 + oc0);
        const float4 bv1 = *(const float4*)(bss + 64 + oc0 + 4);
        const float bv[8] = {bv0.x, bv0.y, bv0.z, bv0.w, bv1.x, bv1.y, bv1.z, bv1.w};
#pragma unroll
        for (int jj = 0; jj < 8; jj++)
#pragma unroll
            for (int n = 0; n < 4; n++) acc[jj][n] = bv[jj];
        for (int i = 0; i < 64; i++) {
            const float4 wA = *(const float4*)(w2s + i * W2_STRV + oc0);
            const float4 wB = *(const float4*)(w2s + i * W2_STRV + oc0 + 4);
            const float4 xv = *(const float4*)(actB + i * NBS + nb0);
            const float wr[8] = {wA.x, wA.y, wA.z, wA.w, wB.x, wB.y, wB.z, wB.w};
            const float xr[4] = {xv.x, xv.y, xv.z, xv.w};
#pragma unroll
            for (int jj = 0; jj < 8; jj++)
#pragma unroll
                for (int n = 0; n < 4; n++) acc[jj][n] += wr[jj] * xr[n];
        }
        __syncthreads();   // all layer-2 reads done before h2 overwrites actA
#pragma unroll
        for (int jj = 0; jj < 8; jj++) {
            float4 o;
            o.x = fmaxf(acc[jj][0], 0.f); o.y = fmaxf(acc[jj][1], 0.f);
            o.z = fmaxf(acc[jj][2], 0.f); o.w = fmaxf(acc[jj][3], 0.f);
            *(float4*)(actA + (oc0 + jj) * NBS + nb0) = o;   // h2 into actA
        }
    }
    __syncthreads();

    // ---- layer 3: 64 -> 128 ; tile 8oc x 8nb ; fused relu+local max ----
    {
        const int otile = tid & 15, ntile = tid >> 4;
        const int oc0 = otile * 8, nb0 = ntile * 8;
        float acc[8][8];
        const float4 bv0 = *(const float4*)(bss + 128 + oc0);
        const float4 bv1 = *(const float4*)(bss + 128 + oc0 + 4);
        const float bv[8] = {bv0.x, bv0.y, bv0.z, bv0.w, bv1.x, bv1.y, bv1.z, bv1.w};
#pragma unroll
        for (int jj = 0; jj < 8; jj++)
#pragma unroll
            for (int n = 0; n < 8; n++) acc[jj][n] = bv[jj];
        for (int i = 0; i < 64; i++) {
            const float4 wA = *(const float4*)(w3s + i * W3_STRV + oc0);
            const float4 wB = *(const float4*)(w3s + i * W3_STRV + oc0 + 4);
            const float4 x0 = *(const float4*)(actA + i * NBS + nb0);
            const float4 x1 = *(const float4*)(actA + i * NBS + nb0 + 4);
            const float wr[8] = {wA.x, wA.y, wA.z, wA.w, wB.x, wB.y, wB.z, wB.w};
            const float xr[8] = {x0.x, x0.y, x0.z, x0.w, x1.x, x1.y, x1.z, x1.w};
#pragma unroll
            for (int jj = 0; jj < 8; jj++)
#pragma unroll
                for (int n = 0; n < 8; n++) acc[jj][n] += wr[jj] * xr[n];
        }
        const int grp = nb0 >> 5;
        const int ntl = (nb0 & 31) >> 3;
#pragma unroll
        for (int jj = 0; jj < 8; jj++) {
            float m = acc[jj][0];
#pragma unroll
            for (int n = 1; n < 8; n++) m = fmaxf(m, acc[jj][n]);
            m = fmaxf(m, 0.f);
            poolbuf[(oc0 + jj) * 16 + grp * 4 + ntl] = m;
        }
    }
    __syncthreads();

    // ---- pool combine (512 = 4g x 128oc), mask empty balls ----
#pragma unroll
    for (int r = 0; r < 2; r++) {
        const int idx = tid + 256 * r;
        const int oc = idx & 127, q = idx >> 7;
        const float4 pv = *(const float4*)(poolbuf + oc * 16 + q * 4);
        const float m = fmaxf(fmaxf(pv.x, pv.y), fmaxf(pv.z, pv.w));
        pooled[q * 128 + oc] = (scnt[q] > 0) ? m : 0.f;
    }
    __syncthreads();

    // ---- aggregation MLP: 4g x (128 -> 128), 2 outputs/thread ----
#pragma unroll
    for (int r = 0; r < 2; r++) {
        const int idx = tid + 256 * r;
        const int o = idx & 127, q = idx >> 7;
        float acc = ba[o];
        const float4* w4 = (const float4*)(wa + o * 128);
        const float* pv = pooled + q * 128;
#pragma unroll 8
        for (int i = 0; i < 32; i++) {
            const float4 wv = __ldg(w4 + i);
            acc += pv[4 * i + 0] * wv.x;
            acc += pv[4 * i + 1] * wv.y;
            acc += pv[4 * i + 2] * wv.z;
            acc += pv[4 * i + 3] * wv.w;
        }
        const float a = fmaxf(acc, 0.f);
        aggv[q * 128 + o] = a;
        const int gg = g0 + q;
        d_out[OUT_FEAT_OFF + ((size_t)(b * 128 + o)) * SS + (gg & 4095)] = a;
    }
    __syncthreads();

    // ---- scores: warp q handles group q ----
    {
        const int wq = tid >> 5, lane = tid & 31;
        if (wq < MLP_G) {
            float p = 0.f;
#pragma unroll
            for (int k = 0; k < 4; k++) {
                const int i = k * 32 + lane;
                p += aggv[wq * 128 + i] * wc[i];
            }
#pragma unroll
            for (int off = 16; off; off >>= 1)
                p += __shfl_down_sync(0xffffffffu, p, off);
            if (lane == 0) {
                const int gg = g0 + wq;
                d_out[OUT_SCORE_OFF + b * SS + (gg & 4095)] = p + bc[0];
            }
        }
    }
}

// =================================================================
// launch
// =================================================================
extern "C" void kernel_launch(void* const* d_in, const int* in_sizes, int n_in,
                              void* d_out, int out_size)
{
    const float* xyz      = (const float*)d_in[0];
    const float* features = (const float*)d_in[1];
    const float* w1 = (const float*)d_in[2];
    const float* b1 = (const float*)d_in[3];
    const float* w2 = (const float*)d_in[4];
    const float* b2 = (const float*)d_in[5];
    const float* w3 = (const float*)d_in[6];
    const float* b3 = (const float*)d_in[7];
    const float* wa = (const float*)d_in[8];
    const float* ba = (const float*)d_in[9];
    const float* wc = (const float*)d_in[10];
    const float* bc = (const float*)d_in[11];
    float* out = (float*)d_out;

    static bool attr_set = false;
    if (!attr_set) {
        cudaFuncSetAttribute(fps_kernel, cudaFuncAttributeMaxDynamicSharedMemorySize,
                             FPS_SMEM_BYTES);
        cudaFuncSetAttribute(group_mlp_kernel, cudaFuncAttributeMaxDynamicSharedMemorySize,
                             MLP2_SMEM_FLOATS * (int)sizeof(float));
        attr_set = true;
    }

    // 1) transpose features to (B,N,C)
    transpose_kernel<<<dim3(NN / 32, CIN / 32, BB), dim3(32, 32)>>>(features);

    // 2) FPS -> writes new_xyz into d_out[0:24576)
    fps_kernel<<<BB, FPS_T, FPS_SMEM_BYTES>>>(xyz, out + OUT_XYZ_OFF);

    // 3) ball query
    ballq_kernel<<<(BB * SS) / 8, 256>>>(xyz, out + OUT_XYZ_OFF);

    // 4) fused gather + MLP + pool + agg + score (4 groups/block)
    group_mlp_kernel<<<(BB * SS) / MLP_G, 256, MLP2_SMEM_FLOATS * sizeof(float)>>>(
        xyz, out + OUT_XYZ_OFF,
        w1, b1, w2, b2, w3, b3, wa, ba, wc, bc, out);
}

// round 10
// speedup vs baseline: 1.9436x; 1.0190x over previous
#include <cuda_runtime.h>
#include <cuda_bf16.h>

// Problem constants
#define BB 2
#define NN 16384
#define CIN 64
#define SS 4096
#define NSAMP 32

// Output layout (floats): new_xyz | new_features | scores
#define OUT_XYZ_OFF   0
#define OUT_FEAT_OFF  (BB * SS * 3)                       // 24576
#define OUT_SCORE_OFF (OUT_FEAT_OFF + BB * 128 * SS)      // 1073152

// ---------------- scratch (no allocations allowed) ----------------
__device__ float g_featsT[BB * NN * CIN];    // (B,N,C) transposed features, 8 MB
__device__ int   g_ballIdx[BB * SS * NSAMP]; // neighbor indices
__device__ int   g_ballCnt[BB * SS];         // in-ball counts (0 => empty)

typedef unsigned long long u64;

// =================================================================
// Kernel 1: FPS (one 256-thread block per batch)
//  - hot tail points (<=768, padded to 1024) in registers as 8
//    virtual chunks (ckey[128..135]) WITH their own AABB + cm prune
//    (hot points are picked early by FPS; afterwards the hot scan
//    is provably a no-op and is skipped)
//  - cold points Morton-sorted into <=128 chunks of 128, AABB pruned
//  - DIRTY-SKIP: per-chunk reduce only if some dist changed
//  - warp argmax reduces via __reduce_max_sync (REDUX):
//    max dist-bits first, then max inv among dist-winners => exact
//    (dist<<14)|inv winner with first-index tie-break
// =================================================================
#define FPS_T   256
#define FPS_W   8
#define HOTCAP  1024
#define HOT_TGT 768
#define NCELL   2048

// smem: cxy 131072 | inv16 32768 | hot4 16384 | hist 8192
//     | aabb f32[136*8]=4352 | ckey u64[160]=1280 | cwin f4[136]=2176
#define FPS_SMEM_BYTES (131072 + 32768 + 16384 + 8192 + 4352 + 1280 + 2176)

__device__ __forceinline__ float r2_rn(float x, float y, float z)
{
    return __fadd_rn(__fadd_rn(__fmul_rn(x, x), __fmul_rn(y, y)), __fmul_rn(z, z));
}
__device__ __forceinline__ float dist_rn(float x, float y, float z,
                                         float nx, float ny, float nz)
{
    const float dx = __fadd_rn(x, nx);
    const float dy = __fadd_rn(y, ny);
    const float dz = __fadd_rn(z, nz);
    return __fadd_rn(__fadd_rn(__fmul_rn(dx, dx), __fmul_rn(dy, dy)), __fmul_rn(dz, dz));
}

__device__ __forceinline__ int fps_cell(float x, float y, float z,
                                        float mnx, float mny, float mnz,
                                        float isx, float isy, float isz)
{
    int qx = __float2int_rd((x - mnx) * isx); qx = max(0, min(15, qx));
    int qy = __float2int_rd((y - mny) * isy); qy = max(0, min(15, qy));
    int qz = __float2int_rd((z - mnz) * isz); qz = max(0, min(7,  qz));
    return  (qx & 1)        | ((qy & 1) << 1)        | ((qz & 1) << 2)
         | (((qx >> 1) & 1) << 3) | (((qy >> 1) & 1) << 4) | (((qz >> 1) & 1) << 5)
         | (((qx >> 2) & 1) << 6) | (((qy >> 2) & 1) << 7) | (((qz >> 2) & 1) << 8)
         | (((qx >> 3) & 1) << 9) | (((qy >> 3) & 1) << 10);
}

__global__ __launch_bounds__(FPS_T) void fps_kernel(
    const float* __restrict__ xyz, float* __restrict__ out_newxyz)
{
    extern __shared__ unsigned char raw[];
    float2*         cxy   = (float2*)raw;                      // [16384]
    unsigned short* inv16 = (unsigned short*)(cxy + NN);       // [16384]
    float4*         hot4  = (float4*)(inv16 + NN);             // [1024]
    unsigned*       hist  = (unsigned*)(hot4 + HOTCAP);        // [2048]
    float*          aabb  = (float*)(hist + NCELL);            // [136*8]
    u64*            ckey  = (u64*)(aabb + 136 * 8);            // [160]
    float4*         cwin  = (float4*)(ckey + 160);             // [136]

    __shared__ float    s_wred[FPS_W][6];
    __shared__ unsigned s_wsum[FPS_W], s_wbase[FPS_W];
    __shared__ unsigned s_rh[128];
    __shared__ float    s_r2b, s_thresh;
    __shared__ float    s_grid[6];
    __shared__ unsigned s_hotCnt;

    const int b    = blockIdx.x;
    const int tid  = threadIdx.x;
    const int lane = tid & 31, w = tid >> 5;
    const float* xb = xyz + (size_t)b * NN * 3;

    // ---- pass 0: global AABB ----
    {
        float mnx = 1e30f, mny = 1e30f, mnz = 1e30f;
        float mxx = -1e30f, mxy = -1e30f, mxz = -1e30f;
        for (int i = tid; i < NN; i += FPS_T) {
            const float x = xb[3 * i], y = xb[3 * i + 1], z = xb[3 * i + 2];
            mnx = fminf(mnx, x); mny = fminf(mny, y); mnz = fminf(mnz, z);
            mxx = fmaxf(mxx, x); mxy = fmaxf(mxy, y); mxz = fmaxf(mxz, z);
        }
#pragma unroll
        for (int off = 16; off; off >>= 1) {
            mnx = fminf(mnx, __shfl_xor_sync(0xffffffffu, mnx, off));
            mny = fminf(mny, __shfl_xor_sync(0xffffffffu, mny, off));
            mnz = fminf(mnz, __shfl_xor_sync(0xffffffffu, mnz, off));
            mxx = fmaxf(mxx, __shfl_xor_sync(0xffffffffu, mxx, off));
            mxy = fmaxf(mxy, __shfl_xor_sync(0xffffffffu, mxy, off));
            mxz = fmaxf(mxz, __shfl_xor_sync(0xffffffffu, mxz, off));
        }
        if (lane == 0) {
            s_wred[w][0] = mnx; s_wred[w][1] = mny; s_wred[w][2] = mnz;
            s_wred[w][3] = mxx; s_wred[w][4] = mxy; s_wred[w][5] = mxz;
        }
    }
    for (int i = tid; i < NCELL; i += FPS_T) hist[i] = 0;
    if (tid < 160) ckey[tid] = 0ull;
    if (tid < 128) s_rh[tid] = 0;
    if (tid == 0) s_hotCnt = 0;
    __syncthreads();
    if (tid == 0) {
        float a0 = 1e30f, a1 = 1e30f, a2 = 1e30f, a3 = -1e30f, a4 = -1e30f, a5 = -1e30f;
        for (int i = 0; i < FPS_W; i++) {
            a0 = fminf(a0, s_wred[i][0]); a1 = fminf(a1, s_wred[i][1]); a2 = fminf(a2, s_wred[i][2]);
            a3 = fmaxf(a3, s_wred[i][3]); a4 = fmaxf(a4, s_wred[i][4]); a5 = fmaxf(a5, s_wred[i][5]);
        }
        s_grid[0] = a0; s_grid[1] = a1; s_grid[2] = a2;
        s_grid[3] = 16.f / fmaxf(a3 - a0, 1e-9f);
        s_grid[4] = 16.f / fmaxf(a4 - a1, 1e-9f);
        s_grid[5] = 8.f  / fmaxf(a5 - a2, 1e-9f);
        const float bx = fmaxf(fabsf(a0), fabsf(a3));
        const float by = fmaxf(fabsf(a1), fabsf(a4));
        const float bz = fmaxf(fabsf(a2), fabsf(a5));
        s_r2b = bx * bx + by * by + bz * bz + 1e-6f;
    }
    __syncthreads();

    const float gmnx = s_grid[0], gmny = s_grid[1], gmnz = s_grid[2];
    const float isx = s_grid[3], isy = s_grid[4], isz = s_grid[5];
    const float r2b = s_r2b;

    // ---- pass 1: r2 histogram -> deterministic hot threshold ----
    for (int i = tid; i < NN; i += FPS_T) {
        const float r2 = r2_rn(xb[3 * i], xb[3 * i + 1], xb[3 * i + 2]);
        const int bin = min(127, (int)(r2 * (128.f / r2b)));
        atomicAdd(&s_rh[bin], 1u);
    }
    __syncthreads();
    if (tid == 0) {
        unsigned acc = 0;
        float thr = 3e38f;
        for (int q = 127; q >= 0; q--) {
            if (acc + s_rh[q] > HOT_TGT) break;
            acc += s_rh[q];
            thr = (float)q * (r2b / 128.f);
        }
        s_thresh = thr;
    }
    __syncthreads();
    const float thresh = s_thresh;

    // ---- pass 2: Morton histogram over cold ----
    for (int i = tid; i < NN; i += FPS_T) {
        const float x = xb[3 * i], y = xb[3 * i + 1], z = xb[3 * i + 2];
        if (r2_rn(x, y, z) < thresh) {
            const int c = fps_cell(x, y, z, gmnx, gmny, gmnz, isx, isy, isz);
            atomicAdd(&hist[c], 1u);
        }
    }
    __syncthreads();

    // ---- exclusive scan of hist[2048] ----
    {
        const int t8 = tid * 8;
        unsigned v[8], s = 0;
#pragma unroll
        for (int q = 0; q < 8; q++) { v[q] = hist[t8 + q]; s += v[q]; }
        unsigned inc = s;
#pragma unroll
        for (int off = 1; off < 32; off <<= 1) {
            const unsigned n = __shfl_up_sync(0xffffffffu, inc, off);
            if (lane >= off) inc += n;
        }
        if (lane == 31) s_wsum[w] = inc;
        __syncthreads();
        if (tid < FPS_W) {
            const unsigned ws = s_wsum[tid];
            unsigned winc = ws;
#pragma unroll
            for (int off = 1; off < FPS_W; off <<= 1) {
                const unsigned n = __shfl_up_sync(0x000000ffu, winc, off);
                if ((int)tid >= off) winc += n;
            }
            s_wbase[tid] = winc - ws;
        }
        __syncthreads();
        unsigned run = s_wbase[w] + (inc - s);
#pragma unroll
        for (int q = 0; q < 8; q++) { hist[t8 + q] = run; run += v[q]; }
    }
    __syncthreads();

    // ---- pass 3: scatter hot / cold (inv = 16383 - i) ----
    for (int i = tid; i < NN; i += FPS_T) {
        const float x = xb[3 * i], y = xb[3 * i + 1], z = xb[3 * i + 2];
        if (r2_rn(x, y, z) >= thresh) {
            const unsigned pos = atomicAdd(&s_hotCnt, 1u);
            hot4[pos] = make_float4(x, y, z, __uint_as_float(16383u - (unsigned)i));
        } else {
            const int c = fps_cell(x, y, z, gmnx, gmny, gmnz, isx, isy, isz);
            const unsigned slot = atomicAdd(&hist[c], 1u);
            cxy[slot]   = make_float2(x, y);
            inv16[slot] = (unsigned short)(16383u - (unsigned)i);
        }
    }
    __syncthreads();

    const int hc    = (int)s_hotCnt;
    const int coldN = NN - hc;
    const int nch   = (coldN + 127) >> 7;

    // pads (duplicates: identical keys/coords, harmless)
    for (int s2 = hc + tid; s2 < HOTCAP; s2 += FPS_T)
        hot4[s2] = (hc > 0) ? hot4[0]
                            : make_float4(xb[0], xb[1], xb[2], __uint_as_float(16383u));
    for (int s2 = coldN + tid; s2 < nch * 128; s2 += FPS_T) {
        cxy[s2]   = cxy[coldN - 1];
        inv16[s2] = inv16[coldN - 1];
    }
    __syncthreads();

    // ---- hot -> registers (4 pts/thread) + hot AABB per warp ----
    float hx[4], hy[4], hz[4], hd[4];
    unsigned hinv[4];
    {
        float hmn0 = 1e30f, hmn1 = 1e30f, hmn2 = 1e30f;
        float hmx0 = -1e30f, hmx1 = -1e30f, hmx2 = -1e30f;
#pragma unroll
        for (int k = 0; k < 4; k++) {
            const float4 h = hot4[tid + FPS_T * k];
            hx[k] = h.x; hy[k] = h.y; hz[k] = h.z;
            hinv[k] = __float_as_uint(h.w);
            hd[k] = 1e10f;
            hmn0 = fminf(hmn0, h.x); hmn1 = fminf(hmn1, h.y); hmn2 = fminf(hmn2, h.z);
            hmx0 = fmaxf(hmx0, h.x); hmx1 = fmaxf(hmx1, h.y); hmx2 = fmaxf(hmx2, h.z);
        }
#pragma unroll
        for (int off = 16; off; off >>= 1) {
            hmn0 = fminf(hmn0, __shfl_xor_sync(0xffffffffu, hmn0, off));
            hmn1 = fminf(hmn1, __shfl_xor_sync(0xffffffffu, hmn1, off));
            hmn2 = fminf(hmn2, __shfl_xor_sync(0xffffffffu, hmn2, off));
            hmx0 = fmaxf(hmx0, __shfl_xor_sync(0xffffffffu, hmx0, off));
            hmx1 = fmaxf(hmx1, __shfl_xor_sync(0xffffffffu, hmx1, off));
            hmx2 = fmaxf(hmx2, __shfl_xor_sync(0xffffffffu, hmx2, off));
        }
        if (lane == 0) {
            const int c = 128 + w;
            aabb[c * 8 + 0] = hmn0; aabb[c * 8 + 1] = hmn1; aabb[c * 8 + 2] = hmn2;
            aabb[c * 8 + 4] = hmx0; aabb[c * 8 + 5] = hmx1; aabb[c * 8 + 6] = hmx2;
            ckey[c] = ((u64)__float_as_uint(1e10f)) << 14;  // force first scan
        }
    }

    // ---- owner fill: cold z + dist regs, chunk AABBs (stride 8) ----
    float cz[64], cd[64];
#pragma unroll
    for (int k = 0; k < 64; k++) { cz[k] = 0.f; cd[k] = 1e10f; }

#pragma unroll
    for (int m = 0; m < 16; m++) {
        const int c = w + FPS_W * m;
        if (c < nch) {
            float lmn0 = 1e30f, lmn1 = 1e30f, lmn2 = 1e30f;
            float lmx0 = -1e30f, lmx1 = -1e30f, lmx2 = -1e30f;
#pragma unroll
            for (int k = 0; k < 4; k++) {
                const int slot = c * 128 + lane + 32 * k;
                const float2 xy = cxy[slot];
                const int oi = 16383 - (int)inv16[slot];
                const float z = __ldg(xb + 3 * oi + 2);
                cz[m * 4 + k] = z;
                lmn0 = fminf(lmn0, xy.x); lmn1 = fminf(lmn1, xy.y); lmn2 = fminf(lmn2, z);
                lmx0 = fmaxf(lmx0, xy.x); lmx1 = fmaxf(lmx1, xy.y); lmx2 = fmaxf(lmx2, z);
            }
#pragma unroll
            for (int off = 16; off; off >>= 1) {
                lmn0 = fminf(lmn0, __shfl_xor_sync(0xffffffffu, lmn0, off));
                lmn1 = fminf(lmn1, __shfl_xor_sync(0xffffffffu, lmn1, off));
                lmn2 = fminf(lmn2, __shfl_xor_sync(0xffffffffu, lmn2, off));
                lmx0 = fmaxf(lmx0, __shfl_xor_sync(0xffffffffu, lmx0, off));
                lmx1 = fmaxf(lmx1, __shfl_xor_sync(0xffffffffu, lmx1, off));
                lmx2 = fmaxf(lmx2, __shfl_xor_sync(0xffffffffu, lmx2, off));
            }
            if (lane == 0) {
                aabb[c * 8 + 0] = lmn0; aabb[c * 8 + 1] = lmn1; aabb[c * 8 + 2] = lmn2;
                aabb[c * 8 + 4] = lmx0; aabb[c * 8 + 5] = lmx1; aabb[c * 8 + 6] = lmx2;
                ckey[c] = ((u64)__float_as_uint(1e10f)) << 14;  // force first scan
            }
        }
    }
    __syncthreads();

    float* outx = out_newxyz + (size_t)b * SS * 3;
    float ccx = __ldg(xb + 0), ccy = __ldg(xb + 1), ccz = __ldg(xb + 2);

    // ---- main loop ----
    for (int j = 0; j < SS; j++) {
        if (tid == 0) {
            outx[3 * j + 0] = ccx;
            outx[3 * j + 1] = ccy;
            outx[3 * j + 2] = ccz;
        }
        const float nx = -ccx, ny = -ccy, nz = -ccz;

        // --- prune: lanes 0..15 cold chunks; lane 16 hot chunk ---
        bool act = false;
        if (lane < 17) {
            const int c = (lane < 16) ? (w + FPS_W * lane) : (128 + w);
            const float4 bmn = *(const float4*)(aabb + c * 8);
            const float4 bmx = *(const float4*)(aabb + c * 8 + 4);
            const float dxm = fmaxf(fmaxf(__fadd_rn(bmn.x, nx), -__fadd_rn(bmx.x, nx)), 0.f);
            const float dym = fmaxf(fmaxf(__fadd_rn(bmn.y, ny), -__fadd_rn(bmx.y, ny)), 0.f);
            const float dzm = fmaxf(fmaxf(__fadd_rn(bmn.z, nz), -__fadd_rn(bmx.z, nz)), 0.f);
            const float dmin2 = __fadd_rn(__fadd_rn(__fmul_rn(dxm, dxm), __fmul_rn(dym, dym)),
                                          __fmul_rn(dzm, dzm));
            const float cm = __uint_as_float((unsigned)(ckey[c] >> 14));
            act = dmin2 < cm;   // ckey==0 for c>=nch => never active
        }
        const unsigned mask = __ballot_sync(0xffffffffu, act);

        // --- hot scan (only when hot chunk active) ---
        if ((mask >> 16) & 1u) {
            u64 bk = 0ull; float bx = 0.f, by = 0.f, bz = 0.f;
            bool chg = false;
#pragma unroll
            for (int k = 0; k < 4; k++) {
                const float d = dist_rn(hx[k], hy[k], hz[k], nx, ny, nz);
                const float old = hd[k];
                const float nd = fminf(old, d);
                chg |= (nd < old);
                hd[k] = nd;
                const u64 key = ((u64)__float_as_uint(nd) << 14) | (u64)hinv[k];
                if (key > bk) { bk = key; bx = hx[k]; by = hy[k]; bz = hz[k]; }
            }
            if (__ballot_sync(0xffffffffu, chg)) {
                const unsigned d32 = (unsigned)(bk >> 14);
                const unsigned K32 = __reduce_max_sync(0xffffffffu, d32);
                const unsigned myinv = (unsigned)(bk & 0x3FFFull);
                const unsigned I = __reduce_max_sync(0xffffffffu, (d32 == K32) ? myinv : 0u);
                const bool isw = (d32 == K32) && (myinv == I);
                const unsigned own = __ballot_sync(0xffffffffu, isw);
                if (lane == (int)(__ffs(own) - 1)) {
                    ckey[128 + w] = ((u64)K32 << 14) | (u64)I;
                    cwin[128 + w] = make_float4(bx, by, bz, 0.f);
                }
            }
        }

        // --- cold scans; REDUX reduce only if some dist changed ---
#pragma unroll
        for (int m = 0; m < 16; m++) {
            if ((mask >> m) & 1u) {   // warp-uniform
                const int c = w + FPS_W * m;
                u64 bk = 0ull; float bx = 0.f, by = 0.f, bz = 0.f;
                bool chg = false;
#pragma unroll
                for (int k = 0; k < 4; k++) {
                    const int slot = c * 128 + lane + 32 * k;
                    const float2 xy = cxy[slot];
                    const float zz = cz[m * 4 + k];
                    const float d = dist_rn(xy.x, xy.y, zz, nx, ny, nz);
                    const float old = cd[m * 4 + k];
                    const float nd = fminf(old, d);
                    chg |= (nd < old);
                    cd[m * 4 + k] = nd;
                    const u64 key = ((u64)__float_as_uint(nd) << 14) | (u64)inv16[slot];
                    if (key > bk) { bk = key; bx = xy.x; by = xy.y; bz = zz; }
                }
                if (__ballot_sync(0xffffffffu, chg)) {
                    const unsigned d32 = (unsigned)(bk >> 14);
                    const unsigned K32 = __reduce_max_sync(0xffffffffu, d32);
                    const unsigned myinv = (unsigned)(bk & 0x3FFFull);
                    const unsigned I = __reduce_max_sync(0xffffffffu, (d32 == K32) ? myinv : 0u);
                    const bool isw = (d32 == K32) && (myinv == I);
                    const unsigned own = __ballot_sync(0xffffffffu, isw);
                    if (lane == (int)(__ffs(own) - 1)) {
                        ckey[c] = ((u64)K32 << 14) | (u64)I;
                        cwin[c] = make_float4(bx, by, bz, 0.f);
                    }
                }
            }
        }
        __syncthreads();

        // --- flat block argmax via REDUX (every warp, redundant) ---
        {
            const u64 v0 = ckey[lane];
            const u64 v1 = ckey[lane + 32];
            const u64 v2 = ckey[lane + 64];
            const u64 v3 = ckey[lane + 96];
            const u64 v4 = ckey[lane + 128];   // pads = 0
            u64 a01 = v0 > v1 ? v0 : v1;
            u64 a23 = v2 > v3 ? v2 : v3;
            u64 mk = a01 > a23 ? a01 : a23;
            if (v4 > mk) mk = v4;
            const unsigned d32 = (unsigned)(mk >> 14);
            const unsigned K32 = __reduce_max_sync(0xffffffffu, d32);
            const unsigned I = __reduce_max_sync(0xffffffffu,
                (d32 == K32) ? (unsigned)(mk & 0x3FFFull) : 0u);
            const u64 W = ((u64)K32 << 14) | (u64)I;
            int myc = -1;
            if (v0 == W) myc = lane;
            else if (v1 == W) myc = lane + 32;
            else if (v2 == W) myc = lane + 64;
            else if (v3 == W) myc = lane + 96;
            else if (v4 == W) myc = lane + 128;
            const unsigned has = __ballot_sync(0xffffffffu, myc >= 0);
            const int src = __shfl_sync(0xffffffffu, myc, (int)(__ffs(has) - 1));
            const float4 wv = cwin[src];
            ccx = wv.x; ccy = wv.y; ccz = wv.z;
        }
        __syncthreads();   // WAR: ckey/cwin rewritten next iteration
    }
}

// =================================================================
// Kernel 2: transpose features (B,C,N) -> (B,N,C)
// =================================================================
__global__ void transpose_kernel(const float* __restrict__ f)
{
    __shared__ float tile[32][33];
    const int b  = blockIdx.z;
    const int n0 = blockIdx.x * 32;
    const int c0 = blockIdx.y * 32;
    const int tx = threadIdx.x, ty = threadIdx.y;
    tile[ty][tx] = f[((size_t)b * CIN + (c0 + ty)) * NN + n0 + tx];
    __syncthreads();
    g_featsT[((size_t)b * NN + (n0 + ty)) * CIN + c0 + tx] = tile[tx][ty];
}

// =================================================================
// Kernel 3: ball query (one warp per group), first-32-ascending
// =================================================================
__global__ void ballq_kernel(const float* __restrict__ xyz,
                             const float* __restrict__ newxyz)
{
    const int g    = blockIdx.x * 8 + (threadIdx.x >> 5);
    const int lane = threadIdx.x & 31;
    const int b    = g >> 12;
    const float* xb = xyz + (size_t)b * NN * 3;

    const float cx = newxyz[g * 3 + 0];
    const float cy = newxyz[g * 3 + 1];
    const float cz = newxyz[g * 3 + 2];

    int* out = g_ballIdx + g * NSAMP;
    int cnt = 0;

    for (int base = 0; base < NN && cnt < NSAMP; base += 32) {
        const int i = base + lane;
        const float dx = xb[3 * i + 0] - cx;
        const float dy = xb[3 * i + 1] - cy;
        const float dz = xb[3 * i + 2] - cz;
        const float d2 = __fadd_rn(__fadd_rn(__fmul_rn(dx, dx), __fmul_rn(dy, dy)),
                                   __fmul_rn(dz, dz));
        const bool inb = d2 < 0.25f;
        const unsigned m = __ballot_sync(0xffffffffu, inb);
        const int pos = cnt + __popc(m & ((1u << lane) - 1u));
        if (inb && pos < NSAMP) out[pos] = i;
        cnt += __popc(m);
    }
    __syncwarp();
    if (cnt == 0) {
        out[lane] = 0;
    } else if (cnt < NSAMP) {
        const int first = out[0];
        if (lane >= cnt) out[lane] = first;
    }
    if (lane == 0) g_ballCnt[g] = cnt;
}

// =================================================================
// Kernel 4: fused gather + MLP + pool + agg + score, 4 GROUPS/BLOCK.
// =================================================================
#define MLP_G     4
#define W1_STRV   72
#define W2_STRV   72
#define W3_STRV   136
#define NBS       132
#define W1F       (67 * W1_STRV)
#define W2F       (64 * W2_STRV)
#define W3F       (64 * W3_STRV)
#define ACTA_F    (67 * NBS)
#define ACTB_F    (64 * NBS)
#define MLP2_SMEM_FLOATS (W1F + W2F + W3F + ACTA_F + ACTB_F + 384 + 2048 + 512 + 512 + 16 + 128 + 8)

__global__ __launch_bounds__(256, 1) void group_mlp_kernel(
    const float* __restrict__ xyz,
    const float* __restrict__ newxyz,
    const float* __restrict__ w1, const float* __restrict__ b1,
    const float* __restrict__ w2, const float* __restrict__ b2,
    const float* __restrict__ w3, const float* __restrict__ b3,
    const float* __restrict__ wa, const float* __restrict__ ba,
    const float* __restrict__ wc, const float* __restrict__ bc,
    float* __restrict__ d_out)
{
    extern __shared__ float sm[];
    float* w1s     = sm;
    float* w2s     = w1s + W1F;
    float* w3s     = w2s + W2F;
    float* actA    = w3s + W3F;
    float* actB    = actA + ACTA_F;
    float* bss     = actB + ACTB_F;
    float* poolbuf = bss + 384;
    float* pooled  = poolbuf + 2048;
    float* aggv    = pooled + 512;
    float* c3      = aggv + 512;
    int*   idxs    = (int*)(c3 + 16);
    int*   scnt    = idxs + 128;

    const int blk = blockIdx.x;
    const int g0  = blk * MLP_G;
    const int b   = g0 >> 12;
    const int tid = threadIdx.x;

    if (tid < 128) idxs[tid] = g_ballIdx[(g0 + (tid >> 5)) * NSAMP + (tid & 31)];
    if (tid >= 128 && tid < 132) scnt[tid - 128] = g_ballCnt[g0 + (tid - 128)];
    if (tid >= 132 && tid < 144) {
        const int q = (tid - 132) / 3, k = (tid - 132) % 3;
        c3[q * 3 + k] = newxyz[(g0 + q) * 3 + k];
    }
    if (tid < 64)       bss[tid] = b1[tid];
    else if (tid < 128) bss[tid] = b2[tid - 64];
    if (tid < 128) bss[128 + tid] = b3[tid];

    for (int e = tid; e < 64 * 67; e += 256) {
        const int oc = e / 67, i = e % 67;
        w1s[i * W1_STRV + oc] = w1[e];
    }
    for (int e = tid; e < 64 * 64; e += 256) {
        const int oc = e >> 6, i = e & 63;
        w2s[i * W2_STRV + oc] = w2[e];
    }
    for (int e = tid; e < 128 * 64; e += 256) {
        const int oc = e >> 6, i = e & 63;
        w3s[i * W3_STRV + oc] = w3[e];
    }
    __syncthreads();

    const float* xb = xyz + (size_t)b * NN * 3;
    for (int e = tid; e < 67 * 128; e += 256) {
        const int nbg = e & 127;
        const int i   = e >> 7;
        const int q   = nbg >> 5;
        const int pi  = idxs[nbg];
        float v;
        if (i < 3) v = xb[pi * 3 + i] - c3[q * 3 + i];
        else       v = g_featsT[((size_t)b * NN + pi) * CIN + (i - 3)];
        actA[i * NBS + nbg] = v;
    }
    __syncthreads();

    {
        const int otile = tid & 7, ntile = tid >> 3;
        const int oc0 = otile * 8, nb0 = ntile * 4;
        float acc[8][4];
        const float4 bv0 = *(const float4*)(bss + oc0);
        const float4 bv1 = *(const float4*)(bss + oc0 + 4);
        const float bv[8] = {bv0.x, bv0.y, bv0.z, bv0.w, bv1.x, bv1.y, bv1.z, bv1.w};
#pragma unroll
        for (int jj = 0; jj < 8; jj++)
#pragma unroll
            for (int n = 0; n < 4; n++) acc[jj][n] = bv[jj];
        for (int i = 0; i < 67; i++) {
            const float4 wA = *(const float4*)(w1s + i * W1_STRV + oc0);
            const float4 wB = *(const float4*)(w1s + i * W1_STRV + oc0 + 4);
            const float4 xv = *(const float4*)(actA + i * NBS + nb0);
            const float wr[8] = {wA.x, wA.y, wA.z, wA.w, wB.x, wB.y, wB.z, wB.w};
            const float xr[4] = {xv.x, xv.y, xv.z, xv.w};
#pragma unroll
            for (int jj = 0; jj < 8; jj++)
#pragma unroll
                for (int n = 0; n < 4; n++) acc[jj][n] += wr[jj] * xr[n];
        }
#pragma unroll
        for (int jj = 0; jj < 8; jj++) {
            float4 o;
            o.x = fmaxf(acc[jj][0], 0.f); o.y = fmaxf(acc[jj][1], 0.f);
            o.z = fmaxf(acc[jj][2], 0.f); o.w = fmaxf(acc[jj][3], 0.f);
            *(float4*)(actB + (oc0 + jj) * NBS + nb0) = o;
        }
    }
    __syncthreads();

    {
        const int otile = tid & 7, ntile = tid >> 3;
        const int oc0 = otile * 8, nb0 = ntile * 4;
        float acc[8][4];
        const float4 bv0 = *(const float4*)(bss + 64 + oc0);
        const float4 bv1 = *(const float4*)(bss + 64 + oc0 + 4);
        const float bv[8] = {bv0.x, bv0.y, bv0.z, bv0.w, bv1.x, bv1.y, bv1.z, bv1.w};
#pragma unroll
        for (int jj = 0; jj < 8; jj++)
#pragma unroll
            for (int n = 0; n < 4; n++) acc[jj][n] = bv[jj];
        for (int i = 0; i < 64; i++) {
            const float4 wA = *(const float4*)(w2s + i * W2_STRV + oc0);
            const float4 wB = *(const float4*)(w2s + i * W2_STRV + oc0 + 4);
            const float4 xv = *(const float4*)(actB + i * NBS + nb0);
            const float wr[8] = {wA.x, wA.y, wA.z, wA.w, wB.x, wB.y, wB.z, wB.w};
            const float xr[4] = {xv.x, xv.y, xv.z, xv.w};
#pragma unroll
            for (int jj = 0; jj < 8; jj++)
#pragma unroll
                for (int n = 0; n < 4; n++) acc[jj][n] += wr[jj] * xr[n];
        }
        __syncthreads();
#pragma unroll
        for (int jj = 0; jj < 8; jj++) {
            float4 o;
            o.x = fmaxf(acc[jj][0], 0.f); o.y = fmaxf(acc[jj][1], 0.f);
            o.z = fmaxf(acc[jj][2], 0.f); o.w = fmaxf(acc[jj][3], 0.f);
            *(float4*)(actA + (oc0 + jj) * NBS + nb0) = o;
        }
    }
    __syncthreads();

    {
        const int otile = tid & 15, ntile = tid >> 4;
        const int oc0 = otile * 8, nb0 = ntile * 8;
        float acc[8][8];
        const float4 bv0 = *(const float4*)(bss + 128 + oc0);
        const float4 bv1 = *(const float4*)(bss + 128 + oc0 + 4);
        const float bv[8] = {bv0.x, bv0.y, bv0.z, bv0.w, bv1.x, bv1.y, bv1.z, bv1.w};
#pragma unroll
        for (int jj = 0; jj < 8; jj++)
#pragma unroll
            for (int n = 0; n < 8; n++) acc[jj][n] = bv[jj];
        for (int i = 0; i < 64; i++) {
            const float4 wA = *(const float4*)(w3s + i * W3_STRV + oc0);
            const float4 wB = *(const float4*)(w3s + i * W3_STRV + oc0 + 4);
            const float4 x0 = *(const float4*)(actA + i * NBS + nb0);
            const float4 x1 = *(const float4*)(actA + i * NBS + nb0 + 4);
            const float wr[8] = {wA.x, wA.y, wA.z, wA.w, wB.x, wB.y, wB.z, wB.w};
            const float xr[8] = {x0.x, x0.y, x0.z, x0.w, x1.x, x1.y, x1.z, x1.w};
#pragma unroll
            for (int jj = 0; jj < 8; jj++)
#pragma unroll
                for (int n = 0; n < 8; n++) acc[jj][n] += wr[jj] * xr[n];
        }
        const int grp = nb0 >> 5;
        const int ntl = (nb0 & 31) >> 3;
#pragma unroll
        for (int jj = 0; jj < 8; jj++) {
            float m = acc[jj][0];
#pragma unroll
            for (int n = 1; n < 8; n++) m = fmaxf(m, acc[jj][n]);
            m = fmaxf(m, 0.f);
            poolbuf[(oc0 + jj) * 16 + grp * 4 + ntl] = m;
        }
    }
    __syncthreads();

#pragma unroll
    for (int r = 0; r < 2; r++) {
        const int idx = tid + 256 * r;
        const int oc = idx & 127, q = idx >> 7;
        const float4 pv = *(const float4*)(poolbuf + oc * 16 + q * 4);
        const float m = fmaxf(fmaxf(pv.x, pv.y), fmaxf(pv.z, pv.w));
        pooled[q * 128 + oc] = (scnt[q] > 0) ? m : 0.f;
    }
    __syncthreads();

#pragma unroll
    for (int r = 0; r < 2; r++) {
        const int idx = tid + 256 * r;
        const int o = idx & 127, q = idx >> 7;
        float acc = ba[o];
        const float4* w4 = (const float4*)(wa + o * 128);
        const float* pv = pooled + q * 128;
#pragma unroll 8
        for (int i = 0; i < 32; i++) {
            const float4 wv = __ldg(w4 + i);
            acc += pv[4 * i + 0] * wv.x;
            acc += pv[4 * i + 1] * wv.y;
            acc += pv[4 * i + 2] * wv.z;
            acc += pv[4 * i + 3] * wv.w;
        }
        const float a = fmaxf(acc, 0.f);
        aggv[q * 128 + o] = a;
        const int gg = g0 + q;
        d_out[OUT_FEAT_OFF + ((size_t)(b * 128 + o)) * SS + (gg & 4095)] = a;
    }
    __syncthreads();

    {
        const int wq = tid >> 5, lane = tid & 31;
        if (wq < MLP_G) {
            float p = 0.f;
#pragma unroll
            for (int k = 0; k < 4; k++) {
                const int i = k * 32 + lane;
                p += aggv[wq * 128 + i] * wc[i];
            }
#pragma unroll
            for (int off = 16; off; off >>= 1)
                p += __shfl_down_sync(0xffffffffu, p, off);
            if (lane == 0) {
                const int gg = g0 + wq;
                d_out[OUT_SCORE_OFF + b * SS + (gg & 4095)] = p + bc[0];
            }
        }
    }
}

// =================================================================
// launch
// =================================================================
extern "C" void kernel_launch(void* const* d_in, const int* in_sizes, int n_in,
                              void* d_out, int out_size)
{
    const float* xyz      = (const float*)d_in[0];
    const float* features = (const float*)d_in[1];
    const float* w1 = (const float*)d_in[2];
    const float* b1 = (const float*)d_in[3];
    const float* w2 = (const float*)d_in[4];
    const float* b2 = (const float*)d_in[5];
    const float* w3 = (const float*)d_in[6];
    const float* b3 = (const float*)d_in[7];
    const float* wa = (const float*)d_in[8];
    const float* ba = (const float*)d_in[9];
    const float* wc = (const float*)d_in[10];
    const float* bc = (const float*)d_in[11];
    float* out = (float*)d_out;

    static bool attr_set = false;
    if (!attr_set) {
        cudaFuncSetAttribute(fps_kernel, cudaFuncAttributeMaxDynamicSharedMemorySize,
                             FPS_SMEM_BYTES);
        cudaFuncSetAttribute(group_mlp_kernel, cudaFuncAttributeMaxDynamicSharedMemorySize,
                             MLP2_SMEM_FLOATS * (int)sizeof(float));
        attr_set = true;
    }

    // 1) transpose features to (B,N,C)
    transpose_kernel<<<dim3(NN / 32, CIN / 32, BB), dim3(32, 32)>>>(features);

    // 2) FPS -> writes new_xyz into d_out[0:24576)
    fps_kernel<<<BB, FPS_T, FPS_SMEM_BYTES>>>(xyz, out + OUT_XYZ_OFF);

    // 3) ball query
    ballq_kernel<<<(BB * SS) / 8, 256>>>(xyz, out + OUT_XYZ_OFF);

    // 4) fused gather + MLP + pool + agg + score (4 groups/block)
    group_mlp_kernel<<<(BB * SS) / MLP_G, 256, MLP2_SMEM_FLOATS * sizeof(float)>>>(
        xyz, out + OUT_XYZ_OFF,
        w1, b1, w2, b2, w3, b3, wa, ba, wc, bc, out);
}

// round 11
// speedup vs baseline: 2.0343x; 1.0467x over previous
#include <cuda_runtime.h>
#include <cuda_bf16.h>

// Problem constants
#define BB 2
#define NN 16384
#define CIN 64
#define SS 4096
#define NSAMP 32

// Output layout (floats): new_xyz | new_features | scores
#define OUT_XYZ_OFF   0
#define OUT_FEAT_OFF  (BB * SS * 3)                       // 24576
#define OUT_SCORE_OFF (OUT_FEAT_OFF + BB * 128 * SS)      // 1073152

// ---------------- scratch (no allocations allowed) ----------------
__device__ float g_featsT[BB * NN * CIN];    // (B,N,C) transposed features, 8 MB
__device__ int   g_ballIdx[BB * SS * NSAMP]; // neighbor indices
__device__ int   g_ballCnt[BB * SS];         // in-ball counts (0 => empty)

typedef unsigned long long u64;

// =================================================================
// Kernel 1: FPS (one 512-thread block per batch; 16 warps)
//  - hot tail points (<=768, padded to 1024): 2/thread in regs,
//    16 virtual chunks ckey[128..143] with AABB prune
//  - cold: Morton chunks of 128 (<=128 chunks); warp owns 8 chunks
//  - DIRTY-SKIP reduces; REDUX argmax (dist first, then inv) =>
//    exact (dist<<14)|inv winner, first-index tie-break
// =================================================================
#define FPS_T   512
#define FPS_W   16
#define HOTCAP  1024
#define HOT_TGT 768
#define NCELL   2048

// smem: cxy 131072 | inv16 32768 | hot4 16384 | hist 8192
//     | aabb f32[144*8]=4608 | ckey u64[192]=1536 | cwin f4[144]=2304
#define FPS_SMEM_BYTES (131072 + 32768 + 16384 + 8192 + 4608 + 1536 + 2304)

__device__ __forceinline__ float r2_rn(float x, float y, float z)
{
    return __fadd_rn(__fadd_rn(__fmul_rn(x, x), __fmul_rn(y, y)), __fmul_rn(z, z));
}
__device__ __forceinline__ float dist_rn(float x, float y, float z,
                                         float nx, float ny, float nz)
{
    const float dx = __fadd_rn(x, nx);
    const float dy = __fadd_rn(y, ny);
    const float dz = __fadd_rn(z, nz);
    return __fadd_rn(__fadd_rn(__fmul_rn(dx, dx), __fmul_rn(dy, dy)), __fmul_rn(dz, dz));
}

__device__ __forceinline__ int fps_cell(float x, float y, float z,
                                        float mnx, float mny, float mnz,
                                        float isx, float isy, float isz)
{
    int qx = __float2int_rd((x - mnx) * isx); qx = max(0, min(15, qx));
    int qy = __float2int_rd((y - mny) * isy); qy = max(0, min(15, qy));
    int qz = __float2int_rd((z - mnz) * isz); qz = max(0, min(7,  qz));
    return  (qx & 1)        | ((qy & 1) << 1)        | ((qz & 1) << 2)
         | (((qx >> 1) & 1) << 3) | (((qy >> 1) & 1) << 4) | (((qz >> 1) & 1) << 5)
         | (((qx >> 2) & 1) << 6) | (((qy >> 2) & 1) << 7) | (((qz >> 2) & 1) << 8)
         | (((qx >> 3) & 1) << 9) | (((qy >> 3) & 1) << 10);
}

__global__ __launch_bounds__(FPS_T) void fps_kernel(
    const float* __restrict__ xyz, float* __restrict__ out_newxyz)
{
    extern __shared__ unsigned char raw[];
    float2*         cxy   = (float2*)raw;                      // [16384]
    unsigned short* inv16 = (unsigned short*)(cxy + NN);       // [16384]
    float4*         hot4  = (float4*)(inv16 + NN);             // [1024]
    unsigned*       hist  = (unsigned*)(hot4 + HOTCAP);        // [2048]
    float*          aabb  = (float*)(hist + NCELL);            // [144*8]
    u64*            ckey  = (u64*)(aabb + 144 * 8);            // [192]
    float4*         cwin  = (float4*)(ckey + 192);             // [144]

    __shared__ float    s_wred[FPS_W][6];
    __shared__ unsigned s_wsum[FPS_W], s_wbase[FPS_W];
    __shared__ unsigned s_rh[128];
    __shared__ float    s_r2b, s_thresh;
    __shared__ float    s_grid[6];
    __shared__ unsigned s_hotCnt;

    const int b    = blockIdx.x;
    const int tid  = threadIdx.x;
    const int lane = tid & 31, w = tid >> 5;
    const float* xb = xyz + (size_t)b * NN * 3;

    // ---- pass 0: global AABB ----
    {
        float mnx = 1e30f, mny = 1e30f, mnz = 1e30f;
        float mxx = -1e30f, mxy = -1e30f, mxz = -1e30f;
        for (int i = tid; i < NN; i += FPS_T) {
            const float x = xb[3 * i], y = xb[3 * i + 1], z = xb[3 * i + 2];
            mnx = fminf(mnx, x); mny = fminf(mny, y); mnz = fminf(mnz, z);
            mxx = fmaxf(mxx, x); mxy = fmaxf(mxy, y); mxz = fmaxf(mxz, z);
        }
#pragma unroll
        for (int off = 16; off; off >>= 1) {
            mnx = fminf(mnx, __shfl_xor_sync(0xffffffffu, mnx, off));
            mny = fminf(mny, __shfl_xor_sync(0xffffffffu, mny, off));
            mnz = fminf(mnz, __shfl_xor_sync(0xffffffffu, mnz, off));
            mxx = fmaxf(mxx, __shfl_xor_sync(0xffffffffu, mxx, off));
            mxy = fmaxf(mxy, __shfl_xor_sync(0xffffffffu, mxy, off));
            mxz = fmaxf(mxz, __shfl_xor_sync(0xffffffffu, mxz, off));
        }
        if (lane == 0) {
            s_wred[w][0] = mnx; s_wred[w][1] = mny; s_wred[w][2] = mnz;
            s_wred[w][3] = mxx; s_wred[w][4] = mxy; s_wred[w][5] = mxz;
        }
    }
    for (int i = tid; i < NCELL; i += FPS_T) hist[i] = 0;
    if (tid < 192) ckey[tid] = 0ull;
    if (tid < 128) s_rh[tid] = 0;
    if (tid == 0) s_hotCnt = 0;
    __syncthreads();
    if (tid == 0) {
        float a0 = 1e30f, a1 = 1e30f, a2 = 1e30f, a3 = -1e30f, a4 = -1e30f, a5 = -1e30f;
        for (int i = 0; i < FPS_W; i++) {
            a0 = fminf(a0, s_wred[i][0]); a1 = fminf(a1, s_wred[i][1]); a2 = fminf(a2, s_wred[i][2]);
            a3 = fmaxf(a3, s_wred[i][3]); a4 = fmaxf(a4, s_wred[i][4]); a5 = fmaxf(a5, s_wred[i][5]);
        }
        s_grid[0] = a0; s_grid[1] = a1; s_grid[2] = a2;
        s_grid[3] = 16.f / fmaxf(a3 - a0, 1e-9f);
        s_grid[4] = 16.f / fmaxf(a4 - a1, 1e-9f);
        s_grid[5] = 8.f  / fmaxf(a5 - a2, 1e-9f);
        const float bx = fmaxf(fabsf(a0), fabsf(a3));
        const float by = fmaxf(fabsf(a1), fabsf(a4));
        const float bz = fmaxf(fabsf(a2), fabsf(a5));
        s_r2b = bx * bx + by * by + bz * bz + 1e-6f;
    }
    __syncthreads();

    const float gmnx = s_grid[0], gmny = s_grid[1], gmnz = s_grid[2];
    const float isx = s_grid[3], isy = s_grid[4], isz = s_grid[5];
    const float r2b = s_r2b;

    // ---- pass 1: r2 histogram -> deterministic hot threshold ----
    for (int i = tid; i < NN; i += FPS_T) {
        const float r2 = r2_rn(xb[3 * i], xb[3 * i + 1], xb[3 * i + 2]);
        const int bin = min(127, (int)(r2 * (128.f / r2b)));
        atomicAdd(&s_rh[bin], 1u);
    }
    __syncthreads();
    if (tid == 0) {
        unsigned acc = 0;
        float thr = 3e38f;
        for (int q = 127; q >= 0; q--) {
            if (acc + s_rh[q] > HOT_TGT) break;
            acc += s_rh[q];
            thr = (float)q * (r2b / 128.f);
        }
        s_thresh = thr;
    }
    __syncthreads();
    const float thresh = s_thresh;

    // ---- pass 2: Morton histogram over cold ----
    for (int i = tid; i < NN; i += FPS_T) {
        const float x = xb[3 * i], y = xb[3 * i + 1], z = xb[3 * i + 2];
        if (r2_rn(x, y, z) < thresh) {
            const int c = fps_cell(x, y, z, gmnx, gmny, gmnz, isx, isy, isz);
            atomicAdd(&hist[c], 1u);
        }
    }
    __syncthreads();

    // ---- exclusive scan of hist[2048] (4 per thread, 512 threads) ----
    {
        const int t4 = tid * 4;
        unsigned v[4], s = 0;
#pragma unroll
        for (int q = 0; q < 4; q++) { v[q] = hist[t4 + q]; s += v[q]; }
        unsigned inc = s;
#pragma unroll
        for (int off = 1; off < 32; off <<= 1) {
            const unsigned n = __shfl_up_sync(0xffffffffu, inc, off);
            if (lane >= off) inc += n;
        }
        if (lane == 31) s_wsum[w] = inc;
        __syncthreads();
        if (tid < FPS_W) {
            const unsigned ws = s_wsum[tid];
            unsigned winc = ws;
#pragma unroll
            for (int off = 1; off < FPS_W; off <<= 1) {
                const unsigned n = __shfl_up_sync(0x0000ffffu, winc, off);
                if ((int)tid >= off) winc += n;
            }
            s_wbase[tid] = winc - ws;
        }
        __syncthreads();
        unsigned run = s_wbase[w] + (inc - s);
#pragma unroll
        for (int q = 0; q < 4; q++) { hist[t4 + q] = run; run += v[q]; }
    }
    __syncthreads();

    // ---- pass 3: scatter hot / cold (inv = 16383 - i) ----
    for (int i = tid; i < NN; i += FPS_T) {
        const float x = xb[3 * i], y = xb[3 * i + 1], z = xb[3 * i + 2];
        if (r2_rn(x, y, z) >= thresh) {
            const unsigned pos = atomicAdd(&s_hotCnt, 1u);
            hot4[pos] = make_float4(x, y, z, __uint_as_float(16383u - (unsigned)i));
        } else {
            const int c = fps_cell(x, y, z, gmnx, gmny, gmnz, isx, isy, isz);
            const unsigned slot = atomicAdd(&hist[c], 1u);
            cxy[slot]   = make_float2(x, y);
            inv16[slot] = (unsigned short)(16383u - (unsigned)i);
        }
    }
    __syncthreads();

    const int hc    = (int)s_hotCnt;
    const int coldN = NN - hc;
    const int nch   = (coldN + 127) >> 7;

    // pads (duplicates: identical keys/coords, harmless)
    for (int s2 = hc + tid; s2 < HOTCAP; s2 += FPS_T)
        hot4[s2] = (hc > 0) ? hot4[0]
                            : make_float4(xb[0], xb[1], xb[2], __uint_as_float(16383u));
    for (int s2 = coldN + tid; s2 < nch * 128; s2 += FPS_T) {
        cxy[s2]   = cxy[coldN - 1];
        inv16[s2] = inv16[coldN - 1];
    }
    __syncthreads();

    // ---- hot -> registers (2 pts/thread) + hot AABB per warp ----
    float hx[2], hy[2], hz[2], hd[2];
    unsigned hinv[2];
    {
        float hmn0 = 1e30f, hmn1 = 1e30f, hmn2 = 1e30f;
        float hmx0 = -1e30f, hmx1 = -1e30f, hmx2 = -1e30f;
#pragma unroll
        for (int k = 0; k < 2; k++) {
            const float4 h = hot4[tid + FPS_T * k];
            hx[k] = h.x; hy[k] = h.y; hz[k] = h.z;
            hinv[k] = __float_as_uint(h.w);
            hd[k] = 1e10f;
            hmn0 = fminf(hmn0, h.x); hmn1 = fminf(hmn1, h.y); hmn2 = fminf(hmn2, h.z);
            hmx0 = fmaxf(hmx0, h.x); hmx1 = fmaxf(hmx1, h.y); hmx2 = fmaxf(hmx2, h.z);
        }
#pragma unroll
        for (int off = 16; off; off >>= 1) {
            hmn0 = fminf(hmn0, __shfl_xor_sync(0xffffffffu, hmn0, off));
            hmn1 = fminf(hmn1, __shfl_xor_sync(0xffffffffu, hmn1, off));
            hmn2 = fminf(hmn2, __shfl_xor_sync(0xffffffffu, hmn2, off));
            hmx0 = fmaxf(hmx0, __shfl_xor_sync(0xffffffffu, hmx0, off));
            hmx1 = fmaxf(hmx1, __shfl_xor_sync(0xffffffffu, hmx1, off));
            hmx2 = fmaxf(hmx2, __shfl_xor_sync(0xffffffffu, hmx2, off));
        }
        if (lane == 0) {
            const int c = 128 + w;
            aabb[c * 8 + 0] = hmn0; aabb[c * 8 + 1] = hmn1; aabb[c * 8 + 2] = hmn2;
            aabb[c * 8 + 4] = hmx0; aabb[c * 8 + 5] = hmx1; aabb[c * 8 + 6] = hmx2;
            ckey[c] = ((u64)__float_as_uint(1e10f)) << 14;  // force first scan
        }
    }

    // ---- owner fill: cold z + dist regs, chunk AABBs (stride 8) ----
    float cz[32], cd[32];
#pragma unroll
    for (int k = 0; k < 32; k++) { cz[k] = 0.f; cd[k] = 1e10f; }

#pragma unroll
    for (int m = 0; m < 8; m++) {
        const int c = w + FPS_W * m;
        if (c < nch) {
            float lmn0 = 1e30f, lmn1 = 1e30f, lmn2 = 1e30f;
            float lmx0 = -1e30f, lmx1 = -1e30f, lmx2 = -1e30f;
#pragma unroll
            for (int k = 0; k < 4; k++) {
                const int slot = c * 128 + lane + 32 * k;
                const float2 xy = cxy[slot];
                const int oi = 16383 - (int)inv16[slot];
                const float z = __ldg(xb + 3 * oi + 2);
                cz[m * 4 + k] = z;
                lmn0 = fminf(lmn0, xy.x); lmn1 = fminf(lmn1, xy.y); lmn2 = fminf(lmn2, z);
                lmx0 = fmaxf(lmx0, xy.x); lmx1 = fmaxf(lmx1, xy.y); lmx2 = fmaxf(lmx2, z);
            }
#pragma unroll
            for (int off = 16; off; off >>= 1) {
                lmn0 = fminf(lmn0, __shfl_xor_sync(0xffffffffu, lmn0, off));
                lmn1 = fminf(lmn1, __shfl_xor_sync(0xffffffffu, lmn1, off));
                lmn2 = fminf(lmn2, __shfl_xor_sync(0xffffffffu, lmn2, off));
                lmx0 = fmaxf(lmx0, __shfl_xor_sync(0xffffffffu, lmx0, off));
                lmx1 = fmaxf(lmx1, __shfl_xor_sync(0xffffffffu, lmx1, off));
                lmx2 = fmaxf(lmx2, __shfl_xor_sync(0xffffffffu, lmx2, off));
            }
            if (lane == 0) {
                aabb[c * 8 + 0] = lmn0; aabb[c * 8 + 1] = lmn1; aabb[c * 8 + 2] = lmn2;
                aabb[c * 8 + 4] = lmx0; aabb[c * 8 + 5] = lmx1; aabb[c * 8 + 6] = lmx2;
                ckey[c] = ((u64)__float_as_uint(1e10f)) << 14;  // force first scan
            }
        }
    }
    __syncthreads();

    float* outx = out_newxyz + (size_t)b * SS * 3;
    float ccx = __ldg(xb + 0), ccy = __ldg(xb + 1), ccz = __ldg(xb + 2);

    // ---- main loop ----
    for (int j = 0; j < SS; j++) {
        if (tid == 0) {
            outx[3 * j + 0] = ccx;
            outx[3 * j + 1] = ccy;
            outx[3 * j + 2] = ccz;
        }
        const float nx = -ccx, ny = -ccy, nz = -ccz;

        // --- prune: lanes 0..7 cold chunks; lane 8 hot chunk ---
        bool act = false;
        if (lane < 9) {
            const int c = (lane < 8) ? (w + FPS_W * lane) : (128 + w);
            const float4 bmn = *(const float4*)(aabb + c * 8);
            const float4 bmx = *(const float4*)(aabb + c * 8 + 4);
            const float dxm = fmaxf(fmaxf(__fadd_rn(bmn.x, nx), -__fadd_rn(bmx.x, nx)), 0.f);
            const float dym = fmaxf(fmaxf(__fadd_rn(bmn.y, ny), -__fadd_rn(bmx.y, ny)), 0.f);
            const float dzm = fmaxf(fmaxf(__fadd_rn(bmn.z, nz), -__fadd_rn(bmx.z, nz)), 0.f);
            const float dmin2 = __fadd_rn(__fadd_rn(__fmul_rn(dxm, dxm), __fmul_rn(dym, dym)),
                                          __fmul_rn(dzm, dzm));
            const float cm = __uint_as_float((unsigned)(ckey[c] >> 14));
            act = dmin2 < cm;   // ckey==0 for c>=nch => never active
        }
        const unsigned mask = __ballot_sync(0xffffffffu, act);

        // --- hot scan (only when hot chunk active) ---
        if ((mask >> 8) & 1u) {
            u64 bk = 0ull; float bx = 0.f, by = 0.f, bz = 0.f;
            bool chg = false;
#pragma unroll
            for (int k = 0; k < 2; k++) {
                const float d = dist_rn(hx[k], hy[k], hz[k], nx, ny, nz);
                const float old = hd[k];
                const float nd = fminf(old, d);
                chg |= (nd < old);
                hd[k] = nd;
                const u64 key = ((u64)__float_as_uint(nd) << 14) | (u64)hinv[k];
                if (key > bk) { bk = key; bx = hx[k]; by = hy[k]; bz = hz[k]; }
            }
            if (__ballot_sync(0xffffffffu, chg)) {
                const unsigned d32 = (unsigned)(bk >> 14);
                const unsigned K32 = __reduce_max_sync(0xffffffffu, d32);
                const unsigned myinv = (unsigned)(bk & 0x3FFFull);
                const unsigned I = __reduce_max_sync(0xffffffffu, (d32 == K32) ? myinv : 0u);
                const bool isw = (d32 == K32) && (myinv == I);
                const unsigned own = __ballot_sync(0xffffffffu, isw);
                if (lane == (int)(__ffs(own) - 1)) {
                    ckey[128 + w] = ((u64)K32 << 14) | (u64)I;
                    cwin[128 + w] = make_float4(bx, by, bz, 0.f);
                }
            }
        }

        // --- cold scans; REDUX reduce only if some dist changed ---
#pragma unroll
        for (int m = 0; m < 8; m++) {
            if ((mask >> m) & 1u) {   // warp-uniform
                const int c = w + FPS_W * m;
                u64 bk = 0ull; float bx = 0.f, by = 0.f, bz = 0.f;
                bool chg = false;
#pragma unroll
                for (int k = 0; k < 4; k++) {
                    const int slot = c * 128 + lane + 32 * k;
                    const float2 xy = cxy[slot];
                    const float zz = cz[m * 4 + k];
                    const float d = dist_rn(xy.x, xy.y, zz, nx, ny, nz);
                    const float old = cd[m * 4 + k];
                    const float nd = fminf(old, d);
                    chg |= (nd < old);
                    cd[m * 4 + k] = nd;
                    const u64 key = ((u64)__float_as_uint(nd) << 14) | (u64)inv16[slot];
                    if (key > bk) { bk = key; bx = xy.x; by = xy.y; bz = zz; }
                }
                if (__ballot_sync(0xffffffffu, chg)) {
                    const unsigned d32 = (unsigned)(bk >> 14);
                    const unsigned K32 = __reduce_max_sync(0xffffffffu, d32);
                    const unsigned myinv = (unsigned)(bk & 0x3FFFull);
                    const unsigned I = __reduce_max_sync(0xffffffffu, (d32 == K32) ? myinv : 0u);
                    const bool isw = (d32 == K32) && (myinv == I);
                    const unsigned own = __ballot_sync(0xffffffffu, isw);
                    if (lane == (int)(__ffs(own) - 1)) {
                        ckey[c] = ((u64)K32 << 14) | (u64)I;
                        cwin[c] = make_float4(bx, by, bz, 0.f);
                    }
                }
            }
        }
        __syncthreads();

        // --- flat block argmax via REDUX (every warp, redundant) ---
        {
            const u64 v0 = ckey[lane];
            const u64 v1 = ckey[lane + 32];
            const u64 v2 = ckey[lane + 64];
            const u64 v3 = ckey[lane + 96];
            const u64 v4 = ckey[lane + 128];
            const u64 v5 = ckey[lane + 160];   // pads = 0
            u64 a01 = v0 > v1 ? v0 : v1;
            u64 a23 = v2 > v3 ? v2 : v3;
            u64 a45 = v4 > v5 ? v4 : v5;
            u64 mk = a01 > a23 ? a01 : a23;
            if (a45 > mk) mk = a45;
            const unsigned d32 = (unsigned)(mk >> 14);
            const unsigned K32 = __reduce_max_sync(0xffffffffu, d32);
            const unsigned I = __reduce_max_sync(0xffffffffu,
                (d32 == K32) ? (unsigned)(mk & 0x3FFFull) : 0u);
            const u64 W = ((u64)K32 << 14) | (u64)I;
            int myc = -1;
            if (v0 == W) myc = lane;
            else if (v1 == W) myc = lane + 32;
            else if (v2 == W) myc = lane + 64;
            else if (v3 == W) myc = lane + 96;
            else if (v4 == W) myc = lane + 128;
            else if (v5 == W) myc = lane + 160;
            const unsigned has = __ballot_sync(0xffffffffu, myc >= 0);
            const int src = __shfl_sync(0xffffffffu, myc, (int)(__ffs(has) - 1));
            const float4 wv = cwin[src];
            ccx = wv.x; ccy = wv.y; ccz = wv.z;
        }
        __syncthreads();   // WAR: ckey/cwin rewritten next iteration
    }
}

// =================================================================
// Kernel 2: transpose features (B,C,N) -> (B,N,C)
// =================================================================
__global__ void transpose_kernel(const float* __restrict__ f)
{
    __shared__ float tile[32][33];
    const int b  = blockIdx.z;
    const int n0 = blockIdx.x * 32;
    const int c0 = blockIdx.y * 32;
    const int tx = threadIdx.x, ty = threadIdx.y;
    tile[ty][tx] = f[((size_t)b * CIN + (c0 + ty)) * NN + n0 + tx];
    __syncthreads();
    g_featsT[((size_t)b * NN + (n0 + ty)) * CIN + c0 + tx] = tile[tx][ty];
}

// =================================================================
// Kernel 3: ball query (one warp per group), first-32-ascending
// =================================================================
__global__ void ballq_kernel(const float* __restrict__ xyz,
                             const float* __restrict__ newxyz)
{
    const int g    = blockIdx.x * 8 + (threadIdx.x >> 5);
    const int lane = threadIdx.x & 31;
    const int b    = g >> 12;
    const float* xb = xyz + (size_t)b * NN * 3;

    const float cx = newxyz[g * 3 + 0];
    const float cy = newxyz[g * 3 + 1];
    const float cz = newxyz[g * 3 + 2];

    int* out = g_ballIdx + g * NSAMP;
    int cnt = 0;

    for (int base = 0; base < NN && cnt < NSAMP; base += 32) {
        const int i = base + lane;
        const float dx = xb[3 * i + 0] - cx;
        const float dy = xb[3 * i + 1] - cy;
        const float dz = xb[3 * i + 2] - cz;
        const float d2 = __fadd_rn(__fadd_rn(__fmul_rn(dx, dx), __fmul_rn(dy, dy)),
                                   __fmul_rn(dz, dz));
        const bool inb = d2 < 0.25f;
        const unsigned m = __ballot_sync(0xffffffffu, inb);
        const int pos = cnt + __popc(m & ((1u << lane) - 1u));
        if (inb && pos < NSAMP) out[pos] = i;
        cnt += __popc(m);
    }
    __syncwarp();
    if (cnt == 0) {
        out[lane] = 0;
    } else if (cnt < NSAMP) {
        const int first = out[0];
        if (lane >= cnt) out[lane] = first;
    }
    if (lane == 0) g_ballCnt[g] = cnt;
}

// =================================================================
// Kernel 4: fused gather + MLP + pool + agg + score, 8 GROUPS/BLOCK,
// 512 threads. Pool/agg buffers alias dead h1 (actB) storage.
// Per-output accumulation order i=0..K-1 unchanged (bit-identical).
// =================================================================
#define MLP_G     8
#define W1_STRV   72
#define W2_STRV   72
#define W3_STRV   136
#define NBG       256          // 8 groups x 32 neighbors
#define NBS       264          // activation row stride
#define W1F       (67 * W1_STRV)    // 4824
#define W2F       (64 * W2_STRV)    // 4608
#define W3F       (64 * W3_STRV)    // 8704
#define ACTA_F    (67 * NBS)        // 17688
#define ACTB_F    (64 * NBS)        // 16896
#define MLP2_SMEM_FLOATS (W1F + W2F + W3F + ACTA_F + ACTB_F)   // 52720 fl = 210880 B

__global__ __launch_bounds__(512, 1) void group_mlp_kernel(
    const float* __restrict__ xyz,
    const float* __restrict__ newxyz,
    const float* __restrict__ w1, const float* __restrict__ b1,
    const float* __restrict__ w2, const float* __restrict__ b2,
    const float* __restrict__ w3, const float* __restrict__ b3,
    const float* __restrict__ wa, const float* __restrict__ ba,
    const float* __restrict__ wc, const float* __restrict__ bc,
    float* __restrict__ d_out)
{
    extern __shared__ float sm[];
    float* w1s     = sm;                    // [67][72]
    float* w2s     = w1s + W1F;             // [64][72]
    float* w3s     = w2s + W2F;             // [64][136]
    float* actA    = w3s + W3F;             // [67][264] inT; later h2 [64][264]
    float* actB    = actA + ACTA_F;         // [64][264] h1; later pool/agg scratch
    // aliases into actB (h1 dead after layer 2):
    float* poolbuf = actB;                  // [128][32]  (4096)
    float* pooled  = actB + 4096;           // [8][128]   (1024)
    float* aggv    = actB + 5120;           // [8][128]   (1024)

    __shared__ float bss[384];              // b1[64] b2[64] b3[128] (+pad)
    __shared__ float c3[32];                // [8][3] centers (+pad)
    __shared__ int   idxs[NBG];             // [8][32]
    __shared__ int   scnt[8];

    const int blk = blockIdx.x;
    const int g0  = blk * MLP_G;
    const int b   = g0 >> 12;               // same batch for all 8 (4096 % 8 == 0)
    const int tid = threadIdx.x;

    // ---- stage: indices, counts, centers, biases, weights ----
    if (tid < NBG) idxs[tid] = g_ballIdx[(g0 + (tid >> 5)) * NSAMP + (tid & 31)];
    if (tid >= 256 && tid < 264) scnt[tid - 256] = g_ballCnt[g0 + (tid - 256)];
    if (tid >= 264 && tid < 288) {
        const int q = (tid - 264) / 3, k = (tid - 264) % 3;
        if (q < 8) c3[q * 3 + k] = newxyz[(g0 + q) * 3 + k];
    }
    if (tid >= 288 && tid < 352)       bss[tid - 288] = b1[tid - 288];
    else if (tid >= 352 && tid < 416)  bss[64 + (tid - 352)] = b2[tid - 352];
    else if (tid >= 416 && tid < 512) {
        const int o = tid - 416;
        bss[128 + o] = b3[o];
    }
    if (tid < 32) bss[128 + 96 + tid] = b3[96 + tid];

    for (int e = tid; e < 64 * 67; e += 512) {
        const int oc = e / 67, i = e % 67;
        w1s[i * W1_STRV + oc] = w1[e];
    }
    for (int e = tid; e < 64 * 64; e += 512) {
        const int oc = e >> 6, i = e & 63;
        w2s[i * W2_STRV + oc] = w2[e];
    }
    for (int e = tid; e < 128 * 64; e += 512) {
        const int oc = e >> 6, i = e & 63;
        w3s[i * W3_STRV + oc] = w3[e];
    }
    __syncthreads();

    // ---- gather: actA[i][nbg] ; nbg = q*32 + nb ----
    const float* xb = xyz + (size_t)b * NN * 3;
    for (int e = tid; e < 67 * NBG; e += 512) {
        const int nbg = e & 255;
        const int i   = e >> 8;
        const int q   = nbg >> 5;
        const int pi  = idxs[nbg];
        float v;
        if (i < 3) v = xb[pi * 3 + i] - c3[q * 3 + i];
        else       v = g_featsT[((size_t)b * NN + pi) * CIN + (i - 3)];
        actA[i * NBS + nbg] = v;
    }
    __syncthreads();

    // ---- layer 1: 67 -> 64 over nb=256 ; tile 8oc x 4nb ----
    {
        const int otile = tid & 7, ntile = tid >> 3;   // 8 x 64
        const int oc0 = otile * 8, nb0 = ntile * 4;
        float acc[8][4];
        const float4 bv0 = *(const float4*)(bss + oc0);
        const float4 bv1 = *(const float4*)(bss + oc0 + 4);
        const float bv[8] = {bv0.x, bv0.y, bv0.z, bv0.w, bv1.x, bv1.y, bv1.z, bv1.w};
#pragma unroll
        for (int jj = 0; jj < 8; jj++)
#pragma unroll
            for (int n = 0; n < 4; n++) acc[jj][n] = bv[jj];
        for (int i = 0; i < 67; i++) {
            const float4 wA = *(const float4*)(w1s + i * W1_STRV + oc0);
            const float4 wB = *(const float4*)(w1s + i * W1_STRV + oc0 + 4);
            const float4 xv = *(const float4*)(actA + i * NBS + nb0);
            const float wr[8] = {wA.x, wA.y, wA.z, wA.w, wB.x, wB.y, wB.z, wB.w};
            const float xr[4] = {xv.x, xv.y, xv.z, xv.w};
#pragma unroll
            for (int jj = 0; jj < 8; jj++)
#pragma unroll
                for (int n = 0; n < 4; n++) acc[jj][n] += wr[jj] * xr[n];
        }
#pragma unroll
        for (int jj = 0; jj < 8; jj++) {
            float4 o;
            o.x = fmaxf(acc[jj][0], 0.f); o.y = fmaxf(acc[jj][1], 0.f);
            o.z = fmaxf(acc[jj][2], 0.f); o.w = fmaxf(acc[jj][3], 0.f);
            *(float4*)(actB + (oc0 + jj) * NBS + nb0) = o;
        }
    }
    __syncthreads();

    // ---- layer 2: 64 -> 64 ; reads actB (h1), writes actA (h2) ----
    {
        const int otile = tid & 7, ntile = tid >> 3;
        const int oc0 = otile * 8, nb0 = ntile * 4;
        float acc[8][4];
        const float4 bv0 = *(const float4*)(bss + 64 + oc0);
        const float4 bv1 = *(const float4*)(bss + 64 + oc0 + 4);
        const float bv[8] = {bv0.x, bv0.y, bv0.z, bv0.w, bv1.x, bv1.y, bv1.z, bv1.w};
#pragma unroll
        for (int jj = 0; jj < 8; jj++)
#pragma unroll
            for (int n = 0; n < 4; n++) acc[jj][n] = bv[jj];
        for (int i = 0; i < 64; i++) {
            const float4 wA = *(const float4*)(w2s + i * W2_STRV + oc0);
            const float4 wB = *(const float4*)(w2s + i * W2_STRV + oc0 + 4);
            const float4 xv = *(const float4*)(actB + i * NBS + nb0);
            const float wr[8] = {wA.x, wA.y, wA.z, wA.w, wB.x, wB.y, wB.z, wB.w};
            const float xr[4] = {xv.x, xv.y, xv.z, xv.w};
#pragma unroll
            for (int jj = 0; jj < 8; jj++)
#pragma unroll
                for (int n = 0; n < 4; n++) acc[jj][n] += wr[jj] * xr[n];
        }
        __syncthreads();   // all layer-2 reads of actB done; actA writes follow
#pragma unroll
        for (int jj = 0; jj < 8; jj++) {
            float4 o;
            o.x = fmaxf(acc[jj][0], 0.f); o.y = fmaxf(acc[jj][1], 0.f);
            o.z = fmaxf(acc[jj][2], 0.f); o.w = fmaxf(acc[jj][3], 0.f);
            *(float4*)(actA + (oc0 + jj) * NBS + nb0) = o;   // h2 into actA
        }
    }
    __syncthreads();

    // ---- layer 3: 64 -> 128 ; tile 8oc x 8nb ; relu+local max ----
    // writes poolbuf which ALIASES actB (h1 dead) - layer3 reads only actA
    {
        const int otile = tid & 15, ntile = tid >> 4;   // 16 x 32
        const int oc0 = otile * 8, nb0 = ntile * 8;
        float acc[8][8];
        const float4 bv0 = *(const float4*)(bss + 128 + oc0);
        const float4 bv1 = *(const float4*)(bss + 128 + oc0 + 4);
        const float bv[8] = {bv0.x, bv0.y, bv0.z, bv0.w, bv1.x, bv1.y, bv1.z, bv1.w};
#pragma unroll
        for (int jj = 0; jj < 8; jj++)
#pragma unroll
            for (int n = 0; n < 8; n++) acc[jj][n] = bv[jj];
        for (int i = 0; i < 64; i++) {
            const float4 wA = *(const float4*)(w3s + i * W3_STRV + oc0);
            const float4 wB = *(const float4*)(w3s + i * W3_STRV + oc0 + 4);
            const float4 x0 = *(const float4*)(actA + i * NBS + nb0);
            const float4 x1 = *(const float4*)(actA + i * NBS + nb0 + 4);
            const float wr[8] = {wA.x, wA.y, wA.z, wA.w, wB.x, wB.y, wB.z, wB.w};
            const float xr[8] = {x0.x, x0.y, x0.z, x0.w, x1.x, x1.y, x1.z, x1.w};
#pragma unroll
            for (int jj = 0; jj < 8; jj++)
#pragma unroll
                for (int n = 0; n < 8; n++) acc[jj][n] += wr[jj] * xr[n];
        }
        const int grp = nb0 >> 5;            // group 0..7
        const int ntl = (nb0 & 31) >> 3;     // 0..3
#pragma unroll
        for (int jj = 0; jj < 8; jj++) {
            float m = acc[jj][0];
#pragma unroll
            for (int n = 1; n < 8; n++) m = fmaxf(m, acc[jj][n]);
            m = fmaxf(m, 0.f);               // max(relu) == relu(max)
            poolbuf[(oc0 + jj) * 32 + grp * 4 + ntl] = m;
        }
    }
    __syncthreads();

    // ---- pool combine (1024 = 8g x 128oc), mask empty balls ----
#pragma unroll
    for (int r = 0; r < 2; r++) {
        const int idx = tid + 512 * r;
        const int oc = idx & 127, q = idx >> 7;
        const float4 pv = *(const float4*)(poolbuf + oc * 32 + q * 4);
        const float m = fmaxf(fmaxf(pv.x, pv.y), fmaxf(pv.z, pv.w));
        pooled[q * 128 + oc] = (scnt[q] > 0) ? m : 0.f;
    }
    __syncthreads();

    // ---- aggregation MLP: 8g x (128 -> 128), 2 outputs/thread ----
#pragma unroll
    for (int r = 0; r < 2; r++) {
        const int idx = tid + 512 * r;
        const int o = idx & 127, q = idx >> 7;
        float acc = ba[o];
        const float4* w4 = (const float4*)(wa + o * 128);
        const float* pv = pooled + q * 128;
#pragma unroll 8
        for (int i = 0; i < 32; i++) {
            const float4 wv = __ldg(w4 + i);
            acc += pv[4 * i + 0] * wv.x;
            acc += pv[4 * i + 1] * wv.y;
            acc += pv[4 * i + 2] * wv.z;
            acc += pv[4 * i + 3] * wv.w;
        }
        const float a = fmaxf(acc, 0.f);
        aggv[q * 128 + o] = a;
        const int gg = g0 + q;
        d_out[OUT_FEAT_OFF + ((size_t)(b * 128 + o)) * SS + (gg & 4095)] = a;
    }
    __syncthreads();

    // ---- scores: warps 0..7 handle groups 0..7 ----
    {
        const int wq = tid >> 5, lane = tid & 31;
        if (wq < MLP_G) {
            float p = 0.f;
#pragma unroll
            for (int k = 0; k < 4; k++) {
                const int i = k * 32 + lane;
                p += aggv[wq * 128 + i] * wc[i];
            }
#pragma unroll
            for (int off = 16; off; off >>= 1)
                p += __shfl_down_sync(0xffffffffu, p, off);
            if (lane == 0) {
                const int gg = g0 + wq;
                d_out[OUT_SCORE_OFF + b * SS + (gg & 4095)] = p + bc[0];
            }
        }
    }
}

// =================================================================
// launch
// =================================================================
extern "C" void kernel_launch(void* const* d_in, const int* in_sizes, int n_in,
                              void* d_out, int out_size)
{
    const float* xyz      = (const float*)d_in[0];
    const float* features = (const float*)d_in[1];
    const float* w1 = (const float*)d_in[2];
    const float* b1 = (const float*)d_in[3];
    const float* w2 = (const float*)d_in[4];
    const float* b2 = (const float*)d_in[5];
    const float* w3 = (const float*)d_in[6];
    const float* b3 = (const float*)d_in[7];
    const float* wa = (const float*)d_in[8];
    const float* ba = (const float*)d_in[9];
    const float* wc = (const float*)d_in[10];
    const float* bc = (const float*)d_in[11];
    float* out = (float*)d_out;

    static bool attr_set = false;
    if (!attr_set) {
        cudaFuncSetAttribute(fps_kernel, cudaFuncAttributeMaxDynamicSharedMemorySize,
                             FPS_SMEM_BYTES);
        cudaFuncSetAttribute(group_mlp_kernel, cudaFuncAttributeMaxDynamicSharedMemorySize,
                             MLP2_SMEM_FLOATS * (int)sizeof(float));
        attr_set = true;
    }

    // 1) transpose features to (B,N,C)
    transpose_kernel<<<dim3(NN / 32, CIN / 32, BB), dim3(32, 32)>>>(features);

    // 2) FPS -> writes new_xyz into d_out[0:24576)
    fps_kernel<<<BB, FPS_T, FPS_SMEM_BYTES>>>(xyz, out + OUT_XYZ_OFF);

    // 3) ball query
    ballq_kernel<<<(BB * SS) / 8, 256>>>(xyz, out + OUT_XYZ_OFF);

    // 4) fused gather + MLP + pool + agg + score (8 groups/block)
    group_mlp_kernel<<<(BB * SS) / MLP_G, 512, MLP2_SMEM_FLOATS * sizeof(float)>>>(
        xyz, out + OUT_XYZ_OFF,
        w1, b1, w2, b2, w3, b3, wa, ba, wc, bc, out);
}

// round 12
// speedup vs baseline: 2.1306x; 1.0474x over previous
#include <cuda_runtime.h>
#include <cuda_bf16.h>

// Problem constants
#define BB 2
#define NN 16384
#define CIN 64
#define SS 4096
#define NSAMP 32

// Output layout (floats): new_xyz | new_features | scores
#define OUT_XYZ_OFF   0
#define OUT_FEAT_OFF  (BB * SS * 3)                       // 24576
#define OUT_SCORE_OFF (OUT_FEAT_OFF + BB * 128 * SS)      // 1073152

// ---------------- scratch (no allocations allowed) ----------------
__device__ float g_featsT[BB * NN * CIN];    // (B,N,C) transposed features, 8 MB
__device__ int   g_ballIdx[BB * SS * NSAMP]; // neighbor indices
__device__ int   g_ballCnt[BB * SS];         // in-ball counts (0 => empty)

typedef unsigned long long u64;

// =================================================================
// Kernel 1: FPS (one 512-thread block per batch; 16 warps)
//  - chunk metadata fully registerized: lane m of warp w holds the
//    AABB + current key of chunk (w + 16m); lane 8 holds the warp's
//    hot chunk. Prune = register math + ballot (no smem).
//  - incremental warp-max: recomputed (2x REDUX) only when one of
//    the warp's chunks had a dirty scan; block argmax reads just 16
//    warp keys. Keys only decrease => staleness conditions exact.
//  - two-pass cold scan: dists first; u64 keys + reduce only when
//    some dist changed.
//  - per-point math bit-identical to reference; key
//    (dist<<14)|(16383-idx) => exact first-index tie-break.
// =================================================================
#define FPS_T   512
#define FPS_W   16
#define HOTCAP  1024
#define HOT_TGT 768
#define NCELL   2048

// smem: cxy 131072 | inv16 32768 | hot4 16384 | hist 8192 | cwin f4[144]=2304
#define FPS_SMEM_BYTES (131072 + 32768 + 16384 + 8192 + 2304)

__device__ __forceinline__ float r2_rn(float x, float y, float z)
{
    return __fadd_rn(__fadd_rn(__fmul_rn(x, x), __fmul_rn(y, y)), __fmul_rn(z, z));
}
__device__ __forceinline__ float dist_rn(float x, float y, float z,
                                         float nx, float ny, float nz)
{
    const float dx = __fadd_rn(x, nx);
    const float dy = __fadd_rn(y, ny);
    const float dz = __fadd_rn(z, nz);
    return __fadd_rn(__fadd_rn(__fmul_rn(dx, dx), __fmul_rn(dy, dy)), __fmul_rn(dz, dz));
}

__device__ __forceinline__ int fps_cell(float x, float y, float z,
                                        float mnx, float mny, float mnz,
                                        float isx, float isy, float isz)
{
    int qx = __float2int_rd((x - mnx) * isx); qx = max(0, min(15, qx));
    int qy = __float2int_rd((y - mny) * isy); qy = max(0, min(15, qy));
    int qz = __float2int_rd((z - mnz) * isz); qz = max(0, min(7,  qz));
    return  (qx & 1)        | ((qy & 1) << 1)        | ((qz & 1) << 2)
         | (((qx >> 1) & 1) << 3) | (((qy >> 1) & 1) << 4) | (((qz >> 1) & 1) << 5)
         | (((qx >> 2) & 1) << 6) | (((qy >> 2) & 1) << 7) | (((qz >> 2) & 1) << 8)
         | (((qx >> 3) & 1) << 9) | (((qy >> 3) & 1) << 10);
}

__global__ __launch_bounds__(FPS_T) void fps_kernel(
    const float* __restrict__ xyz, float* __restrict__ out_newxyz)
{
    extern __shared__ unsigned char raw[];
    float2*         cxy   = (float2*)raw;                      // [16384]
    unsigned short* inv16 = (unsigned short*)(cxy + NN);       // [16384]
    float4*         hot4  = (float4*)(inv16 + NN);             // [1024]
    unsigned*       hist  = (unsigned*)(hot4 + HOTCAP);        // [2048]
    float4*         cwin  = (float4*)(hist + NCELL);           // [144] 0-127 cold, 128-143 hot

    __shared__ u64      s_wm[FPS_W];
    __shared__ float4   s_wwin[FPS_W];
    __shared__ float    s_wred[FPS_W][6];
    __shared__ unsigned s_wsum[FPS_W], s_wbase[FPS_W];
    __shared__ unsigned s_rh[128];
    __shared__ float    s_r2b, s_thresh;
    __shared__ float    s_grid[6];
    __shared__ unsigned s_hotCnt;

    const int b    = blockIdx.x;
    const int tid  = threadIdx.x;
    const int lane = tid & 31, w = tid >> 5;
    const float* xb = xyz + (size_t)b * NN * 3;

    // ---- pass 0: global AABB ----
    {
        float mnx = 1e30f, mny = 1e30f, mnz = 1e30f;
        float mxx = -1e30f, mxy = -1e30f, mxz = -1e30f;
        for (int i = tid; i < NN; i += FPS_T) {
            const float x = xb[3 * i], y = xb[3 * i + 1], z = xb[3 * i + 2];
            mnx = fminf(mnx, x); mny = fminf(mny, y); mnz = fminf(mnz, z);
            mxx = fmaxf(mxx, x); mxy = fmaxf(mxy, y); mxz = fmaxf(mxz, z);
        }
#pragma unroll
        for (int off = 16; off; off >>= 1) {
            mnx = fminf(mnx, __shfl_xor_sync(0xffffffffu, mnx, off));
            mny = fminf(mny, __shfl_xor_sync(0xffffffffu, mny, off));
            mnz = fminf(mnz, __shfl_xor_sync(0xffffffffu, mnz, off));
            mxx = fmaxf(mxx, __shfl_xor_sync(0xffffffffu, mxx, off));
            mxy = fmaxf(mxy, __shfl_xor_sync(0xffffffffu, mxy, off));
            mxz = fmaxf(mxz, __shfl_xor_sync(0xffffffffu, mxz, off));
        }
        if (lane == 0) {
            s_wred[w][0] = mnx; s_wred[w][1] = mny; s_wred[w][2] = mnz;
            s_wred[w][3] = mxx; s_wred[w][4] = mxy; s_wred[w][5] = mxz;
        }
    }
    for (int i = tid; i < NCELL; i += FPS_T) hist[i] = 0;
    if (tid < 128) s_rh[tid] = 0;
    if (tid == 0) s_hotCnt = 0;
    __syncthreads();
    if (tid == 0) {
        float a0 = 1e30f, a1 = 1e30f, a2 = 1e30f, a3 = -1e30f, a4 = -1e30f, a5 = -1e30f;
        for (int i = 0; i < FPS_W; i++) {
            a0 = fminf(a0, s_wred[i][0]); a1 = fminf(a1, s_wred[i][1]); a2 = fminf(a2, s_wred[i][2]);
            a3 = fmaxf(a3, s_wred[i][3]); a4 = fmaxf(a4, s_wred[i][4]); a5 = fmaxf(a5, s_wred[i][5]);
        }
        s_grid[0] = a0; s_grid[1] = a1; s_grid[2] = a2;
        s_grid[3] = 16.f / fmaxf(a3 - a0, 1e-9f);
        s_grid[4] = 16.f / fmaxf(a4 - a1, 1e-9f);
        s_grid[5] = 8.f  / fmaxf(a5 - a2, 1e-9f);
        const float bx = fmaxf(fabsf(a0), fabsf(a3));
        const float by = fmaxf(fabsf(a1), fabsf(a4));
        const float bz = fmaxf(fabsf(a2), fabsf(a5));
        s_r2b = bx * bx + by * by + bz * bz + 1e-6f;
    }
    __syncthreads();

    const float gmnx = s_grid[0], gmny = s_grid[1], gmnz = s_grid[2];
    const float isx = s_grid[3], isy = s_grid[4], isz = s_grid[5];
    const float r2b = s_r2b;

    // ---- pass 1: r2 histogram -> deterministic hot threshold ----
    for (int i = tid; i < NN; i += FPS_T) {
        const float r2 = r2_rn(xb[3 * i], xb[3 * i + 1], xb[3 * i + 2]);
        const int bin = min(127, (int)(r2 * (128.f / r2b)));
        atomicAdd(&s_rh[bin], 1u);
    }
    __syncthreads();
    if (tid == 0) {
        unsigned acc = 0;
        float thr = 3e38f;
        for (int q = 127; q >= 0; q--) {
            if (acc + s_rh[q] > HOT_TGT) break;
            acc += s_rh[q];
            thr = (float)q * (r2b / 128.f);
        }
        s_thresh = thr;
    }
    __syncthreads();
    const float thresh = s_thresh;

    // ---- pass 2: Morton histogram over cold ----
    for (int i = tid; i < NN; i += FPS_T) {
        const float x = xb[3 * i], y = xb[3 * i + 1], z = xb[3 * i + 2];
        if (r2_rn(x, y, z) < thresh) {
            const int c = fps_cell(x, y, z, gmnx, gmny, gmnz, isx, isy, isz);
            atomicAdd(&hist[c], 1u);
        }
    }
    __syncthreads();

    // ---- exclusive scan of hist[2048] ----
    {
        const int t4 = tid * 4;
        unsigned v[4], s = 0;
#pragma unroll
        for (int q = 0; q < 4; q++) { v[q] = hist[t4 + q]; s += v[q]; }
        unsigned inc = s;
#pragma unroll
        for (int off = 1; off < 32; off <<= 1) {
            const unsigned n = __shfl_up_sync(0xffffffffu, inc, off);
            if (lane >= off) inc += n;
        }
        if (lane == 31) s_wsum[w] = inc;
        __syncthreads();
        if (tid < FPS_W) {
            const unsigned ws = s_wsum[tid];
            unsigned winc = ws;
#pragma unroll
            for (int off = 1; off < FPS_W; off <<= 1) {
                const unsigned n = __shfl_up_sync(0x0000ffffu, winc, off);
                if ((int)tid >= off) winc += n;
            }
            s_wbase[tid] = winc - ws;
        }
        __syncthreads();
        unsigned run = s_wbase[w] + (inc - s);
#pragma unroll
        for (int q = 0; q < 4; q++) { hist[t4 + q] = run; run += v[q]; }
    }
    __syncthreads();

    // ---- pass 3: scatter hot / cold (inv = 16383 - i) ----
    for (int i = tid; i < NN; i += FPS_T) {
        const float x = xb[3 * i], y = xb[3 * i + 1], z = xb[3 * i + 2];
        if (r2_rn(x, y, z) >= thresh) {
            const unsigned pos = atomicAdd(&s_hotCnt, 1u);
            hot4[pos] = make_float4(x, y, z, __uint_as_float(16383u - (unsigned)i));
        } else {
            const int c = fps_cell(x, y, z, gmnx, gmny, gmnz, isx, isy, isz);
            const unsigned slot = atomicAdd(&hist[c], 1u);
            cxy[slot]   = make_float2(x, y);
            inv16[slot] = (unsigned short)(16383u - (unsigned)i);
        }
    }
    __syncthreads();

    const int hc    = (int)s_hotCnt;
    const int coldN = NN - hc;
    const int nch   = (coldN + 127) >> 7;

    // pads (duplicates: identical keys/coords, harmless)
    for (int s2 = hc + tid; s2 < HOTCAP; s2 += FPS_T)
        hot4[s2] = (hc > 0) ? hot4[0]
                            : make_float4(xb[0], xb[1], xb[2], __uint_as_float(16383u));
    for (int s2 = coldN + tid; s2 < nch * 128; s2 += FPS_T) {
        cxy[s2]   = cxy[coldN - 1];
        inv16[s2] = inv16[coldN - 1];
    }
    __syncthreads();

    // ---- per-lane chunk metadata (registers) ----
    // lane m (0..7): cold chunk (w + 16m); lane 8: hot chunk (128+w)
    float bx0 = 1e30f, bx1 = 1e30f, bx2 = 1e30f;     // box min
    float bx3 = -1e30f, bx4 = -1e30f, bx5 = -1e30f;  // box max
    u64   mykey = 0ull;

    // hot -> registers (2 pts/thread) + hot AABB -> lane 8
    float hx[2], hy[2], hz[2], hd[2];
    unsigned hinv[2];
    {
        float hmn0 = 1e30f, hmn1 = 1e30f, hmn2 = 1e30f;
        float hmx0 = -1e30f, hmx1 = -1e30f, hmx2 = -1e30f;
#pragma unroll
        for (int k = 0; k < 2; k++) {
            const float4 h = hot4[tid + FPS_T * k];
            hx[k] = h.x; hy[k] = h.y; hz[k] = h.z;
            hinv[k] = __float_as_uint(h.w);
            hd[k] = 1e10f;
            hmn0 = fminf(hmn0, h.x); hmn1 = fminf(hmn1, h.y); hmn2 = fminf(hmn2, h.z);
            hmx0 = fmaxf(hmx0, h.x); hmx1 = fmaxf(hmx1, h.y); hmx2 = fmaxf(hmx2, h.z);
        }
#pragma unroll
        for (int off = 16; off; off >>= 1) {
            hmn0 = fminf(hmn0, __shfl_xor_sync(0xffffffffu, hmn0, off));
            hmn1 = fminf(hmn1, __shfl_xor_sync(0xffffffffu, hmn1, off));
            hmn2 = fminf(hmn2, __shfl_xor_sync(0xffffffffu, hmn2, off));
            hmx0 = fmaxf(hmx0, __shfl_xor_sync(0xffffffffu, hmx0, off));
            hmx1 = fmaxf(hmx1, __shfl_xor_sync(0xffffffffu, hmx1, off));
            hmx2 = fmaxf(hmx2, __shfl_xor_sync(0xffffffffu, hmx2, off));
        }
        if (lane == 8) {
            bx0 = hmn0; bx1 = hmn1; bx2 = hmn2;
            bx3 = hmx0; bx4 = hmx1; bx5 = hmx2;
            mykey = ((u64)__float_as_uint(1e10f)) << 14;  // force first scan
        }
    }

    // cold z + dist regs + saved xy, chunk AABB -> lane m
    float cz[32], cd[32];
    float sx[32], sy[32];
#pragma unroll
    for (int k = 0; k < 32; k++) { cz[k] = 0.f; cd[k] = 1e10f; sx[k] = 0.f; sy[k] = 0.f; }

#pragma unroll
    for (int m = 0; m < 8; m++) {
        const int c = w + FPS_W * m;
        if (c < nch) {
            float lmn0 = 1e30f, lmn1 = 1e30f, lmn2 = 1e30f;
            float lmx0 = -1e30f, lmx1 = -1e30f, lmx2 = -1e30f;
#pragma unroll
            for (int k = 0; k < 4; k++) {
                const int slot = c * 128 + lane + 32 * k;
                const float2 xy = cxy[slot];
                const int oi = 16383 - (int)inv16[slot];
                const float z = __ldg(xb + 3 * oi + 2);
                cz[m * 4 + k] = z;
                sx[m * 4 + k] = xy.x;
                sy[m * 4 + k] = xy.y;
                lmn0 = fminf(lmn0, xy.x); lmn1 = fminf(lmn1, xy.y); lmn2 = fminf(lmn2, z);
                lmx0 = fmaxf(lmx0, xy.x); lmx1 = fmaxf(lmx1, xy.y); lmx2 = fmaxf(lmx2, z);
            }
#pragma unroll
            for (int off = 16; off; off >>= 1) {
                lmn0 = fminf(lmn0, __shfl_xor_sync(0xffffffffu, lmn0, off));
                lmn1 = fminf(lmn1, __shfl_xor_sync(0xffffffffu, lmn1, off));
                lmn2 = fminf(lmn2, __shfl_xor_sync(0xffffffffu, lmn2, off));
                lmx0 = fmaxf(lmx0, __shfl_xor_sync(0xffffffffu, lmx0, off));
                lmx1 = fmaxf(lmx1, __shfl_xor_sync(0xffffffffu, lmx1, off));
                lmx2 = fmaxf(lmx2, __shfl_xor_sync(0xffffffffu, lmx2, off));
            }
            if (lane == m) {
                bx0 = lmn0; bx1 = lmn1; bx2 = lmn2;
                bx3 = lmx0; bx4 = lmx1; bx5 = lmx2;
                mykey = ((u64)__float_as_uint(1e10f)) << 14;  // force first scan
            }
        }
    }
    __syncthreads();

    float* outx = out_newxyz + (size_t)b * SS * 3;
    float ccx = __ldg(xb + 0), ccy = __ldg(xb + 1), ccz = __ldg(xb + 2);

    // ---- main loop ----
    for (int j = 0; j < SS; j++) {
        if (tid == 0) {
            outx[3 * j + 0] = ccx;
            outx[3 * j + 1] = ccy;
            outx[3 * j + 2] = ccz;
        }
        const float nx = -ccx, ny = -ccy, nz = -ccz;

        // --- prune: pure register math, lanes 0..8 ---
        bool act = false;
        if (lane < 9) {
            const float dxm = fmaxf(fmaxf(__fadd_rn(bx0, nx), -__fadd_rn(bx3, nx)), 0.f);
            const float dym = fmaxf(fmaxf(__fadd_rn(bx1, ny), -__fadd_rn(bx4, ny)), 0.f);
            const float dzm = fmaxf(fmaxf(__fadd_rn(bx2, nz), -__fadd_rn(bx5, nz)), 0.f);
            const float dmin2 = __fadd_rn(__fadd_rn(__fmul_rn(dxm, dxm), __fmul_rn(dym, dym)),
                                          __fmul_rn(dzm, dzm));
            const float cm = __uint_as_float((unsigned)(mykey >> 14));
            act = dmin2 < cm;   // mykey==0 for invalid chunks => never active
        }
        const unsigned mask = __ballot_sync(0xffffffffu, act);
        bool wflag = false;   // any owned chunk dirty this iteration

        // --- hot scan (bit 8) ---
        if ((mask >> 8) & 1u) {
            u64 bk = 0ull; float hbx = 0.f, hby = 0.f, hbz = 0.f;
            bool chg = false;
#pragma unroll
            for (int k = 0; k < 2; k++) {
                const float d = dist_rn(hx[k], hy[k], hz[k], nx, ny, nz);
                const float old = hd[k];
                const float nd = fminf(old, d);
                chg |= (nd < old);
                hd[k] = nd;
                const u64 key = ((u64)__float_as_uint(nd) << 14) | (u64)hinv[k];
                if (key > bk) { bk = key; hbx = hx[k]; hby = hy[k]; hbz = hz[k]; }
            }
            if (__ballot_sync(0xffffffffu, chg)) {
                const unsigned d32 = (unsigned)(bk >> 14);
                const unsigned K32 = __reduce_max_sync(0xffffffffu, d32);
                const unsigned myinv = (unsigned)(bk & 0x3FFFull);
                const unsigned I = __reduce_max_sync(0xffffffffu, (d32 == K32) ? myinv : 0u);
                const unsigned own = __ballot_sync(0xffffffffu, (d32 == K32) && (myinv == I));
                if (lane == (int)(__ffs(own) - 1)) cwin[128 + w] = make_float4(hbx, hby, hbz, 0.f);
                if (lane == 8) mykey = ((u64)K32 << 14) | (u64)I;
                wflag = true;
            }
        }

        // --- cold scans: pass 1 dists; pass 2 keys only if dirty ---
#pragma unroll
        for (int m = 0; m < 8; m++) {
            if ((mask >> m) & 1u) {   // warp-uniform
                const int c = w + FPS_W * m;
                bool chg = false;
#pragma unroll
                for (int k = 0; k < 4; k++) {
                    const float d = dist_rn(sx[m * 4 + k], sy[m * 4 + k], cz[m * 4 + k],
                                            nx, ny, nz);
                    const float old = cd[m * 4 + k];
                    const float nd = fminf(old, d);
                    chg |= (nd < old);
                    cd[m * 4 + k] = nd;
                }
                if (__ballot_sync(0xffffffffu, chg)) {
                    u64 bk = 0ull; float cbx = 0.f, cby = 0.f, cbz = 0.f;
#pragma unroll
                    for (int k = 0; k < 4; k++) {
                        const int slot = c * 128 + lane + 32 * k;
                        const u64 key = ((u64)__float_as_uint(cd[m * 4 + k]) << 14)
                                      | (u64)inv16[slot];
                        if (key > bk) {
                            bk = key;
                            cbx = sx[m * 4 + k]; cby = sy[m * 4 + k]; cbz = cz[m * 4 + k];
                        }
                    }
                    const unsigned d32 = (unsigned)(bk >> 14);
                    const unsigned K32 = __reduce_max_sync(0xffffffffu, d32);
                    const unsigned myinv = (unsigned)(bk & 0x3FFFull);
                    const unsigned I = __reduce_max_sync(0xffffffffu, (d32 == K32) ? myinv : 0u);
                    const unsigned own = __ballot_sync(0xffffffffu, (d32 == K32) && (myinv == I));
                    if (lane == (int)(__ffs(own) - 1)) cwin[c] = make_float4(cbx, cby, cbz, 0.f);
                    if (lane == m) mykey = ((u64)K32 << 14) | (u64)I;
                    wflag = true;
                }
            }
        }

        // --- incremental warp-max refresh (only if any owned chunk changed) ---
        if (wflag) {
            const unsigned d32 = (lane < 9) ? (unsigned)(mykey >> 14) : 0u;
            const unsigned K = __reduce_max_sync(0xffffffffu, d32);
            const unsigned I = __reduce_max_sync(0xffffffffu,
                (d32 == K) ? (unsigned)(mykey & 0x3FFFull) : 0u);
            const u64 wm = ((u64)K << 14) | (u64)I;
            const unsigned own = __ballot_sync(0xffffffffu,
                (lane < 9) && (mykey == wm));
            const int sl = (int)(__ffs(own) - 1);
            const int src = (sl < 8) ? (w + FPS_W * sl) : (128 + w);
            if (lane == 0) {
                s_wm[w] = wm;
                s_wwin[w] = cwin[src];
            }
        }
        __syncthreads();

        // --- block argmax over 16 warp keys (every warp, redundant) ---
        {
            const u64 k = (lane < FPS_W) ? s_wm[lane] : 0ull;
            const unsigned d32 = (unsigned)(k >> 14);
            const unsigned K = __reduce_max_sync(0xffffffffu, d32);
            const unsigned I = __reduce_max_sync(0xffffffffu,
                (d32 == K) ? (unsigned)(k & 0x3FFFull) : 0u);
            const u64 W = ((u64)K << 14) | (u64)I;
            const unsigned has = __ballot_sync(0xffffffffu, (lane < FPS_W) && (k == W));
            const int wi = (int)(__ffs(has) - 1);
            const float4 wv = s_wwin[wi];
            ccx = wv.x; ccy = wv.y; ccz = wv.z;
        }
        __syncthreads();   // WAR: cwin/s_wm/s_wwin rewritten next iteration
    }
}

// =================================================================
// Kernel 2: transpose features (B,C,N) -> (B,N,C)
// =================================================================
__global__ void transpose_kernel(const float* __restrict__ f)
{
    __shared__ float tile[32][33];
    const int b  = blockIdx.z;
    const int n0 = blockIdx.x * 32;
    const int c0 = blockIdx.y * 32;
    const int tx = threadIdx.x, ty = threadIdx.y;
    tile[ty][tx] = f[((size_t)b * CIN + (c0 + ty)) * NN + n0 + tx];
    __syncthreads();
    g_featsT[((size_t)b * NN + (n0 + ty)) * CIN + c0 + tx] = tile[tx][ty];
}

// =================================================================
// Kernel 3: ball query (one warp per group), first-32-ascending
// =================================================================
__global__ void ballq_kernel(const float* __restrict__ xyz,
                             const float* __restrict__ newxyz)
{
    const int g    = blockIdx.x * 8 + (threadIdx.x >> 5);
    const int lane = threadIdx.x & 31;
    const int b    = g >> 12;
    const float* xb = xyz + (size_t)b * NN * 3;

    const float cx = newxyz[g * 3 + 0];
    const float cy = newxyz[g * 3 + 1];
    const float cz = newxyz[g * 3 + 2];

    int* out = g_ballIdx + g * NSAMP;
    int cnt = 0;

    for (int base = 0; base < NN && cnt < NSAMP; base += 32) {
        const int i = base + lane;
        const float dx = xb[3 * i + 0] - cx;
        const float dy = xb[3 * i + 1] - cy;
        const float dz = xb[3 * i + 2] - cz;
        const float d2 = __fadd_rn(__fadd_rn(__fmul_rn(dx, dx), __fmul_rn(dy, dy)),
                                   __fmul_rn(dz, dz));
        const bool inb = d2 < 0.25f;
        const unsigned m = __ballot_sync(0xffffffffu, inb);
        const int pos = cnt + __popc(m & ((1u << lane) - 1u));
        if (inb && pos < NSAMP) out[pos] = i;
        cnt += __popc(m);
    }
    __syncwarp();
    if (cnt == 0) {
        out[lane] = 0;
    } else if (cnt < NSAMP) {
        const int first = out[0];
        if (lane >= cnt) out[lane] = first;
    }
    if (lane == 0) g_ballCnt[g] = cnt;
}

// =================================================================
// Kernel 4: fused gather + MLP + pool + agg + score, 8 GROUPS/BLOCK,
// 512 threads. Pool/agg buffers alias dead h1 (actB) storage.
// =================================================================
#define MLP_G     8
#define W1_STRV   72
#define W2_STRV   72
#define W3_STRV   136
#define NBG       256
#define NBS       264
#define W1F       (67 * W1_STRV)
#define W2F       (64 * W2_STRV)
#define W3F       (64 * W3_STRV)
#define ACTA_F    (67 * NBS)
#define ACTB_F    (64 * NBS)
#define MLP2_SMEM_FLOATS (W1F + W2F + W3F + ACTA_F + ACTB_F)

__global__ __launch_bounds__(512, 1) void group_mlp_kernel(
    const float* __restrict__ xyz,
    const float* __restrict__ newxyz,
    const float* __restrict__ w1, const float* __restrict__ b1,
    const float* __restrict__ w2, const float* __restrict__ b2,
    const float* __restrict__ w3, const float* __restrict__ b3,
    const float* __restrict__ wa, const float* __restrict__ ba,
    const float* __restrict__ wc, const float* __restrict__ bc,
    float* __restrict__ d_out)
{
    extern __shared__ float sm[];
    float* w1s     = sm;
    float* w2s     = w1s + W1F;
    float* w3s     = w2s + W2F;
    float* actA    = w3s + W3F;
    float* actB    = actA + ACTA_F;
    float* poolbuf = actB;
    float* pooled  = actB + 4096;
    float* aggv    = actB + 5120;

    __shared__ float bss[384];
    __shared__ float c3[32];
    __shared__ int   idxs[NBG];
    __shared__ int   scnt[8];

    const int blk = blockIdx.x;
    const int g0  = blk * MLP_G;
    const int b   = g0 >> 12;
    const int tid = threadIdx.x;

    if (tid < NBG) idxs[tid] = g_ballIdx[(g0 + (tid >> 5)) * NSAMP + (tid & 31)];
    if (tid >= 256 && tid < 264) scnt[tid - 256] = g_ballCnt[g0 + (tid - 256)];
    if (tid >= 264 && tid < 288) {
        const int q = (tid - 264) / 3, k = (tid - 264) % 3;
        if (q < 8) c3[q * 3 + k] = newxyz[(g0 + q) * 3 + k];
    }
    if (tid >= 288 && tid < 352)       bss[tid - 288] = b1[tid - 288];
    else if (tid >= 352 && tid < 416)  bss[64 + (tid - 352)] = b2[tid - 352];
    else if (tid >= 416 && tid < 512) {
        const int o = tid - 416;
        bss[128 + o] = b3[o];
    }
    if (tid < 32) bss[128 + 96 + tid] = b3[96 + tid];

    for (int e = tid; e < 64 * 67; e += 512) {
        const int oc = e / 67, i = e % 67;
        w1s[i * W1_STRV + oc] = w1[e];
    }
    for (int e = tid; e < 64 * 64; e += 512) {
        const int oc = e >> 6, i = e & 63;
        w2s[i * W2_STRV + oc] = w2[e];
    }
    for (int e = tid; e < 128 * 64; e += 512) {
        const int oc = e >> 6, i = e & 63;
        w3s[i * W3_STRV + oc] = w3[e];
    }
    __syncthreads();

    const float* xb = xyz + (size_t)b * NN * 3;
    for (int e = tid; e < 67 * NBG; e += 512) {
        const int nbg = e & 255;
        const int i   = e >> 8;
        const int q   = nbg >> 5;
        const int pi  = idxs[nbg];
        float v;
        if (i < 3) v = xb[pi * 3 + i] - c3[q * 3 + i];
        else       v = g_featsT[((size_t)b * NN + pi) * CIN + (i - 3)];
        actA[i * NBS + nbg] = v;
    }
    __syncthreads();

    {
        const int otile = tid & 7, ntile = tid >> 3;
        const int oc0 = otile * 8, nb0 = ntile * 4;
        float acc[8][4];
        const float4 bv0 = *(const float4*)(bss + oc0);
        const float4 bv1 = *(const float4*)(bss + oc0 + 4);
        const float bv[8] = {bv0.x, bv0.y, bv0.z, bv0.w, bv1.x, bv1.y, bv1.z, bv1.w};
#pragma unroll
        for (int jj = 0; jj < 8; jj++)
#pragma unroll
            for (int n = 0; n < 4; n++) acc[jj][n] = bv[jj];
        for (int i = 0; i < 67; i++) {
            const float4 wA = *(const float4*)(w1s + i * W1_STRV + oc0);
            const float4 wB = *(const float4*)(w1s + i * W1_STRV + oc0 + 4);
            const float4 xv = *(const float4*)(actA + i * NBS + nb0);
            const float wr[8] = {wA.x, wA.y, wA.z, wA.w, wB.x, wB.y, wB.z, wB.w};
            const float xr[4] = {xv.x, xv.y, xv.z, xv.w};
#pragma unroll
            for (int jj = 0; jj < 8; jj++)
#pragma unroll
                for (int n = 0; n < 4; n++) acc[jj][n] += wr[jj] * xr[n];
        }
#pragma unroll
        for (int jj = 0; jj < 8; jj++) {
            float4 o;
            o.x = fmaxf(acc[jj][0], 0.f); o.y = fmaxf(acc[jj][1], 0.f);
            o.z = fmaxf(acc[jj][2], 0.f); o.w = fmaxf(acc[jj][3], 0.f);
            *(float4*)(actB + (oc0 + jj) * NBS + nb0) = o;
        }
    }
    __syncthreads();

    {
        const int otile = tid & 7, ntile = tid >> 3;
        const int oc0 = otile * 8, nb0 = ntile * 4;
        float acc[8][4];
        const float4 bv0 = *(const float4*)(bss + 64 + oc0);
        const float4 bv1 = *(const float4*)(bss + 64 + oc0 + 4);
        const float bv[8] = {bv0.x, bv0.y, bv0.z, bv0.w, bv1.x, bv1.y, bv1.z, bv1.w};
#pragma unroll
        for (int jj = 0; jj < 8; jj++)
#pragma unroll
            for (int n = 0; n < 4; n++) acc[jj][n] = bv[jj];
        for (int i = 0; i < 64; i++) {
            const float4 wA = *(const float4*)(w2s + i * W2_STRV + oc0);
            const float4 wB = *(const float4*)(w2s + i * W2_STRV + oc0 + 4);
            const float4 xv = *(const float4*)(actB + i * NBS + nb0);
            const float wr[8] = {wA.x, wA.y, wA.z, wA.w, wB.x, wB.y, wB.z, wB.w};
            const float xr[4] = {xv.x, xv.y, xv.z, xv.w};
#pragma unroll
            for (int jj = 0; jj < 8; jj++)
#pragma unroll
                for (int n = 0; n < 4; n++) acc[jj][n] += wr[jj] * xr[n];
        }
        __syncthreads();
#pragma unroll
        for (int jj = 0; jj < 8; jj++) {
            float4 o;
            o.x = fmaxf(acc[jj][0], 0.f); o.y = fmaxf(acc[jj][1], 0.f);
            o.z = fmaxf(acc[jj][2], 0.f); o.w = fmaxf(acc[jj][3], 0.f);
            *(float4*)(actA + (oc0 + jj) * NBS + nb0) = o;
        }
    }
    __syncthreads();

    {
        const int otile = tid & 15, ntile = tid >> 4;
        const int oc0 = otile * 8, nb0 = ntile * 8;
        float acc[8][8];
        const float4 bv0 = *(const float4*)(bss + 128 + oc0);
        const float4 bv1 = *(const float4*)(bss + 128 + oc0 + 4);
        const float bv[8] = {bv0.x, bv0.y, bv0.z, bv0.w, bv1.x, bv1.y, bv1.z, bv1.w};
#pragma unroll
        for (int jj = 0; jj < 8; jj++)
#pragma unroll
            for (int n = 0; n < 8; n++) acc[jj][n] = bv[jj];
        for (int i = 0; i < 64; i++) {
            const float4 wA = *(const float4*)(w3s + i * W3_STRV + oc0);
            const float4 wB = *(const float4*)(w3s + i * W3_STRV + oc0 + 4);
            const float4 x0 = *(const float4*)(actA + i * NBS + nb0);
            const float4 x1 = *(const float4*)(actA + i * NBS + nb0 + 4);
            const float wr[8] = {wA.x, wA.y, wA.z, wA.w, wB.x, wB.y, wB.z, wB.w};
            const float xr[8] = {x0.x, x0.y, x0.z, x0.w, x1.x, x1.y, x1.z, x1.w};
#pragma unroll
            for (int jj = 0; jj < 8; jj++)
#pragma unroll
                for (int n = 0; n < 8; n++) acc[jj][n] += wr[jj] * xr[n];
        }
        const int grp = nb0 >> 5;
        const int ntl = (nb0 & 31) >> 3;
#pragma unroll
        for (int jj = 0; jj < 8; jj++) {
            float m = acc[jj][0];
#pragma unroll
            for (int n = 1; n < 8; n++) m = fmaxf(m, acc[jj][n]);
            m = fmaxf(m, 0.f);
            poolbuf[(oc0 + jj) * 32 + grp * 4 + ntl] = m;
        }
    }
    __syncthreads();

#pragma unroll
    for (int r = 0; r < 2; r++) {
        const int idx = tid + 512 * r;
        const int oc = idx & 127, q = idx >> 7;
        const float4 pv = *(const float4*)(poolbuf + oc * 32 + q * 4);
        const float m = fmaxf(fmaxf(pv.x, pv.y), fmaxf(pv.z, pv.w));
        pooled[q * 128 + oc] = (scnt[q] > 0) ? m : 0.f;
    }
    __syncthreads();

#pragma unroll
    for (int r = 0; r < 2; r++) {
        const int idx = tid + 512 * r;
        const int o = idx & 127, q = idx >> 7;
        float acc = ba[o];
        const float4* w4 = (const float4*)(wa + o * 128);
        const float* pv = pooled + q * 128;
#pragma unroll 8
        for (int i = 0; i < 32; i++) {
            const float4 wv = __ldg(w4 + i);
            acc += pv[4 * i + 0] * wv.x;
            acc += pv[4 * i + 1] * wv.y;
            acc += pv[4 * i + 2] * wv.z;
            acc += pv[4 * i + 3] * wv.w;
        }
        const float a = fmaxf(acc, 0.f);
        aggv[q * 128 + o] = a;
        const int gg = g0 + q;
        d_out[OUT_FEAT_OFF + ((size_t)(b * 128 + o)) * SS + (gg & 4095)] = a;
    }
    __syncthreads();

    {
        const int wq = tid >> 5, lane = tid & 31;
        if (wq < MLP_G) {
            float p = 0.f;
#pragma unroll
            for (int k = 0; k < 4; k++) {
                const int i = k * 32 + lane;
                p += aggv[wq * 128 + i] * wc[i];
            }
#pragma unroll
            for (int off = 16; off; off >>= 1)
                p += __shfl_down_sync(0xffffffffu, p, off);
            if (lane == 0) {
                const int gg = g0 + wq;
                d_out[OUT_SCORE_OFF + b * SS + (gg & 4095)] = p + bc[0];
            }
        }
    }
}

// =================================================================
// launch
// =================================================================
extern "C" void kernel_launch(void* const* d_in, const int* in_sizes, int n_in,
                              void* d_out, int out_size)
{
    const float* xyz      = (const float*)d_in[0];
    const float* features = (const float*)d_in[1];
    const float* w1 = (const float*)d_in[2];
    const float* b1 = (const float*)d_in[3];
    const float* w2 = (const float*)d_in[4];
    const float* b2 = (const float*)d_in[5];
    const float* w3 = (const float*)d_in[6];
    const float* b3 = (const float*)d_in[7];
    const float* wa = (const float*)d_in[8];
    const float* ba = (const float*)d_in[9];
    const float* wc = (const float*)d_in[10];
    const float* bc = (const float*)d_in[11];
    float* out = (float*)d_out;

    static bool attr_set = false;
    if (!attr_set) {
        cudaFuncSetAttribute(fps_kernel, cudaFuncAttributeMaxDynamicSharedMemorySize,
                             FPS_SMEM_BYTES);
        cudaFuncSetAttribute(group_mlp_kernel, cudaFuncAttributeMaxDynamicSharedMemorySize,
                             MLP2_SMEM_FLOATS * (int)sizeof(float));
        attr_set = true;
    }

    // 1) transpose features to (B,N,C)
    transpose_kernel<<<dim3(NN / 32, CIN / 32, BB), dim3(32, 32)>>>(features);

    // 2) FPS -> writes new_xyz into d_out[0:24576)
    fps_kernel<<<BB, FPS_T, FPS_SMEM_BYTES>>>(xyz, out + OUT_XYZ_OFF);

    // 3) ball query
    ballq_kernel<<<(BB * SS) / 8, 256>>>(xyz, out + OUT_XYZ_OFF);

    // 4) fused gather + MLP + pool + agg + score (8 groups/block)
    group_mlp_kernel<<<(BB * SS) / MLP_G, 512, MLP2_SMEM_FLOATS * sizeof(float)>>>(
        xyz, out + OUT_XYZ_OFF,
        w1, b1, w2, b2, w3, b3, wa, ba, wc, bc, out);
}